// round 1
// baseline (speedup 1.0000x reference)
#include <cuda_runtime.h>
#include <math.h>

// ---------------------------------------------------------------------------
// Model_Recursive_LSTM_v2 — fp32 baseline
// B=256, L=64 (only 0..47 used), IN=1024, E=180
// ---------------------------------------------------------------------------

#define E_DIM 180
#define G_DIM 720          // 4*E
#define M_CE  12288        // 256 * 48 effective rows
#define S_CL  1536         // 256 * 6 leaf sequences
#define S_MID 768          // 256 * 3
#define S_RT  256

// ---- scratch layout (floats) ----
#define OFF_EMB0  0UL                    // 12288*600
#define OFF_EMB1  7372800UL              // 12288*350
#define OFF_EMB2  11673600UL             // 12288*200
#define OFF_EMBD  14131200UL             // 12288*180
#define OFF_XG    16343040UL             // 12288*720 (cl x-proj)
#define OFF_XGM   25190400UL             // 1536*720  (mid x-proj)
#define OFF_XGR   26296320UL             // 768*720   (root x-proj)
#define OFF_HW    26849280UL             // 1536*720  (h@Whh^T, reused)
#define OFF_HA    27955200UL             // 1536*180  (cl h)
#define OFF_CA    28231680UL             // 1536*180  (cl c)
#define OFF_CAT   28508160UL             // 1536*360
#define OFF_T200  29061120UL             // 1536*200
#define OFF_LEAF  29368320UL             // 1536*180
#define OFF_HM    29644800UL             // 768*180
#define OFF_CM    29783040UL             // 768*180
#define OFF_MIDO  29921280UL             // 768*180
#define OFF_HR    30059520UL             // 256*180
#define OFF_CR    30105600UL             // 256*180
#define OFF_PROG  30151680UL             // 256*180
#define OFF_R0    30197760UL             // 256*200
#define OFF_R1    30248960UL             // 256*180
#define SCRATCH_F 30295040UL

__device__ float g_scratch[SCRATCH_F];

// ---------------------------------------------------------------------------
// Tiled SGEMM: C[M,N] = act( A[M,K] @ W[N,K]^T + bias )
// remap!=0: logical A-row m maps to physical row (m/48)*64 + (m%48)
// ---------------------------------------------------------------------------
#define BM 128
#define BN 128
#define BK 8

__global__ __launch_bounds__(256) void sgemm_kernel(
    const float* __restrict__ A, const float* __restrict__ W,
    const float* __restrict__ bias, float* __restrict__ C,
    int M, int N, int K, int act, int remap)
{
    __shared__ float As[BK][BM];
    __shared__ float Bs[BK][BN];

    const int tid = threadIdx.x;
    const int tx = tid & 15;          // 0..15  (column group)
    const int ty = tid >> 4;          // 0..15  (row group)
    const int bm = blockIdx.y * BM;
    const int bn = blockIdx.x * BN;

    float acc[8][8];
#pragma unroll
    for (int i = 0; i < 8; i++)
#pragma unroll
        for (int j = 0; j < 8; j++) acc[i][j] = 0.f;

    for (int k0 = 0; k0 < K; k0 += BK) {
        // load A tile (128 x 8)
#pragma unroll
        for (int l = 0; l < 4; l++) {
            int idx = tid + l * 256;          // 0..1023
            int m = idx >> 3, k = idx & 7;
            int gm = bm + m, gk = k0 + k;
            float v = 0.f;
            if (gm < M && gk < K) {
                long ar = remap ? ((long)(gm / 48) * 64 + (gm % 48)) : (long)gm;
                v = A[ar * K + gk];
            }
            As[k][m] = v;
        }
        // load W tile (128 x 8)
#pragma unroll
        for (int l = 0; l < 4; l++) {
            int idx = tid + l * 256;
            int n = idx >> 3, k = idx & 7;
            int gn = bn + n, gk = k0 + k;
            float v = 0.f;
            if (gn < N && gk < K) v = W[(long)gn * K + gk];
            Bs[k][n] = v;
        }
        __syncthreads();

#pragma unroll
        for (int kk = 0; kk < BK; kk++) {
            float ra[8], rb[8];
#pragma unroll
            for (int i = 0; i < 8; i++) ra[i] = As[kk][ty * 8 + i];
#pragma unroll
            for (int j = 0; j < 8; j++) rb[j] = Bs[kk][tx * 8 + j];
#pragma unroll
            for (int i = 0; i < 8; i++)
#pragma unroll
                for (int j = 0; j < 8; j++) acc[i][j] += ra[i] * rb[j];
        }
        __syncthreads();
    }

#pragma unroll
    for (int i = 0; i < 8; i++) {
        int gm = bm + ty * 8 + i;
        if (gm >= M) continue;
#pragma unroll
        for (int j = 0; j < 8; j++) {
            int gn = bn + tx * 8 + j;
            if (gn >= N) continue;
            float v = acc[i][j];
            if (bias) v += bias[gn];
            if (act) v = v > 0.f ? v : (expf(v) - 1.f);   // ELU
            C[(long)gm * N + gn] = v;
        }
    }
}

// ---------------------------------------------------------------------------
// LSTM pointwise step: gate order i,f,g,o (torch).
// xg row for sequence s at time t: (s/divA)*mulA + (s%divA)*mulB + t
// first!=0: h_prev = c_prev = 0 and hW ignored.
// ---------------------------------------------------------------------------
__device__ __forceinline__ float sigf(float x) { return 1.f / (1.f + expf(-x)); }

__global__ void lstm_step_kernel(
    const float* __restrict__ xg, const float* __restrict__ hW,
    const float* __restrict__ bih, const float* __restrict__ bhh,
    float* __restrict__ h, float* __restrict__ c,
    int S, int t, int divA, int mulA, int mulB, int first)
{
    int idx = blockIdx.x * blockDim.x + threadIdx.x;
    if (idx >= S * E_DIM) return;
    int s = idx / E_DIM, e = idx % E_DIM;
    int xrow = (s / divA) * mulA + (s % divA) * mulB + t;
    const float* xr = xg + (long)xrow * G_DIM;

    float gi = xr[e]             + bih[e]             + bhh[e];
    float gf = xr[E_DIM + e]     + bih[E_DIM + e]     + bhh[E_DIM + e];
    float gg = xr[2 * E_DIM + e] + bih[2 * E_DIM + e] + bhh[2 * E_DIM + e];
    float go = xr[3 * E_DIM + e] + bih[3 * E_DIM + e] + bhh[3 * E_DIM + e];

    float cprev = 0.f;
    if (!first) {
        const float* hr = hW + (long)s * G_DIM;
        gi += hr[e]; gf += hr[E_DIM + e]; gg += hr[2 * E_DIM + e]; go += hr[3 * E_DIM + e];
        cprev = c[idx];
    }
    float cn = sigf(gf) * cprev + sigf(gi) * tanhf(gg);
    c[idx] = cn;
    h[idx] = sigf(go) * tanhf(cn);
}

// ---------------------------------------------------------------------------
// Assemble concat rows: cat[r][0:180]=first, cat[r][180:360]=second
// ---------------------------------------------------------------------------
__global__ void concat_kernel(
    const float* __restrict__ first, int firstB,
    const float* __restrict__ second, int secondB,
    float* __restrict__ cat, int rows)
{
    int idx = blockIdx.x * blockDim.x + threadIdx.x;
    if (idx >= rows * 2 * E_DIM) return;
    int r = idx / (2 * E_DIM), e = idx % (2 * E_DIM);
    float v;
    if (e < E_DIM) v = firstB  ? first[e]            : first[(long)r * E_DIM + e];
    else { int e2 = e - E_DIM; v = secondB ? second[e2] : second[(long)r * E_DIM + e2]; }
    cat[idx] = v;
}

// ---------------------------------------------------------------------------
// Final prediction: out[b] = dot(x[b], w) + b0   (one warp per row)
// ---------------------------------------------------------------------------
__global__ void pred_kernel(const float* __restrict__ x, const float* __restrict__ w,
                            const float* __restrict__ b, float* __restrict__ out, int rows)
{
    int gwarp = (blockIdx.x * blockDim.x + threadIdx.x) >> 5;
    int lane = threadIdx.x & 31;
    if (gwarp >= rows) return;
    float s = 0.f;
    for (int e = lane; e < E_DIM; e += 32) s += x[(long)gwarp * E_DIM + e] * w[e];
#pragma unroll
    for (int o = 16; o; o >>= 1) s += __shfl_down_sync(0xffffffffu, s, o);
    if (lane == 0) out[gwarp] = s + b[0];
}

// ---------------------------------------------------------------------------
// host side
// ---------------------------------------------------------------------------
static inline void gemm(const float* A, const float* W, const float* bias, float* C,
                        int M, int N, int K, int act, int remap)
{
    dim3 grid((N + BN - 1) / BN, (M + BM - 1) / BM);
    sgemm_kernel<<<grid, 256>>>(A, W, bias, C, M, N, K, act, remap);
}

extern "C" void kernel_launch(void* const* d_in, const int* in_sizes, int n_in,
                              void* d_out, int out_size)
{
    const float* ast    = (const float*)d_in[0];
    const float* ce_w0  = (const float*)d_in[1];  const float* ce_b0 = (const float*)d_in[2];
    const float* ce_w1  = (const float*)d_in[3];  const float* ce_b1 = (const float*)d_in[4];
    const float* ce_w2  = (const float*)d_in[5];  const float* ce_b2 = (const float*)d_in[6];
    const float* ce_w3  = (const float*)d_in[7];  const float* ce_b3 = (const float*)d_in[8];
    const float* cc_w0  = (const float*)d_in[9];  const float* cc_b0 = (const float*)d_in[10];
    const float* cc_w1  = (const float*)d_in[11]; const float* cc_b1 = (const float*)d_in[12];
    const float* rg_w0  = (const float*)d_in[13]; const float* rg_b0 = (const float*)d_in[14];
    const float* rg_w1  = (const float*)d_in[15]; const float* rg_b1 = (const float*)d_in[16];
    const float* pred_w = (const float*)d_in[17]; const float* pred_b = (const float*)d_in[18];
    const float* cl_Wih = (const float*)d_in[19]; const float* cl_Whh = (const float*)d_in[20];
    const float* cl_bih = (const float*)d_in[21]; const float* cl_bhh = (const float*)d_in[22];
    const float* nl_Wih = (const float*)d_in[23]; const float* nl_Whh = (const float*)d_in[24];
    const float* nl_bih = (const float*)d_in[25]; const float* nl_bhh = (const float*)d_in[26];
    const float* no_comps = (const float*)d_in[27];
    const float* no_nodes = (const float*)d_in[28];
    float* out = (float*)d_out;

    float* S0 = nullptr;
    cudaGetSymbolAddress((void**)&S0, g_scratch);

    float* emb0 = S0 + OFF_EMB0;  float* emb1 = S0 + OFF_EMB1;
    float* emb2 = S0 + OFF_EMB2;  float* embd = S0 + OFF_EMBD;
    float* xg   = S0 + OFF_XG;    float* xgm  = S0 + OFF_XGM;  float* xgr = S0 + OFF_XGR;
    float* hW   = S0 + OFF_HW;
    float* hA   = S0 + OFF_HA;    float* cA   = S0 + OFF_CA;
    float* cat  = S0 + OFF_CAT;   float* t200 = S0 + OFF_T200;
    float* leaf = S0 + OFF_LEAF;
    float* hM   = S0 + OFF_HM;    float* cM   = S0 + OFF_CM;   float* mido = S0 + OFF_MIDO;
    float* hR   = S0 + OFF_HR;    float* cR   = S0 + OFF_CR;
    float* prog = S0 + OFF_PROG;  float* r0   = S0 + OFF_R0;   float* r1  = S0 + OFF_R1;

    // ---- Phase A: comp-embedding MLP on the 48 used positions ----
    gemm(ast,  ce_w0, ce_b0, emb0, M_CE, 600, 1024, 1, 1);   // remap 48-of-64
    gemm(emb0, ce_w1, ce_b1, emb1, M_CE, 350, 600, 1, 0);
    gemm(emb1, ce_w2, ce_b2, emb2, M_CE, 200, 350, 1, 0);
    gemm(emb2, ce_w3, ce_b3, embd, M_CE, E_DIM, 200, 1, 0);

    // ---- Phase B: cl LSTM over 6 leaves x 8 steps (batched S=1536) ----
    gemm(embd, cl_Wih, nullptr, xg, M_CE, G_DIM, E_DIM, 0, 0);   // x-proj hoisted
    {
        int thr = S_CL * E_DIM;
        lstm_step_kernel<<<(thr + 255) / 256, 256>>>(xg, hW, cl_bih, cl_bhh, hA, cA,
                                                     S_CL, 0, 6, 48, 8, 1);
        for (int t = 1; t < 8; t++) {
            gemm(hA, cl_Whh, nullptr, hW, S_CL, G_DIM, E_DIM, 0, 0);
            lstm_step_kernel<<<(thr + 255) / 256, 256>>>(xg, hW, cl_bih, cl_bhh, hA, cA,
                                                         S_CL, t, 6, 48, 8, 0);
        }
    }

    // ---- Phase C: leaf concat block (nodes=no_nodes bcast, comps=h) ----
    {
        int thr = S_CL * 2 * E_DIM;
        concat_kernel<<<(thr + 255) / 256, 256>>>(no_nodes, 1, hA, 0, cat, S_CL);
        gemm(cat,  cc_w0, cc_b0, t200, S_CL, 200, 2 * E_DIM, 1, 0);
        gemm(t200, cc_w1, cc_b1, leaf, S_CL, E_DIM, 200, 1, 0);
    }

    // ---- Phase D: mid nl LSTM (S=768, T=2 over leaf pairs) ----
    gemm(leaf, nl_Wih, nullptr, xgm, S_CL, G_DIM, E_DIM, 0, 0);
    {
        int thr = S_MID * E_DIM;
        lstm_step_kernel<<<(thr + 255) / 256, 256>>>(xgm, hW, nl_bih, nl_bhh, hM, cM,
                                                     S_MID, 0, 3, 6, 2, 1);
        gemm(hM, nl_Whh, nullptr, hW, S_MID, G_DIM, E_DIM, 0, 0);
        lstm_step_kernel<<<(thr + 255) / 256, 256>>>(xgm, hW, nl_bih, nl_bhh, hM, cM,
                                                     S_MID, 1, 3, 6, 2, 0);
    }

    // ---- Phase E: mid concat block (nodes=h, comps=no_comps bcast) ----
    {
        int thr = S_MID * 2 * E_DIM;
        concat_kernel<<<(thr + 255) / 256, 256>>>(hM, 0, no_comps, 1, cat, S_MID);
        gemm(cat,  cc_w0, cc_b0, t200, S_MID, 200, 2 * E_DIM, 1, 0);
        gemm(t200, cc_w1, cc_b1, mido, S_MID, E_DIM, 200, 1, 0);
    }

    // ---- Phase F: root nl LSTM (S=256, T=3 over mids) ----
    gemm(mido, nl_Wih, nullptr, xgr, S_MID, G_DIM, E_DIM, 0, 0);
    {
        int thr = S_RT * E_DIM;
        lstm_step_kernel<<<(thr + 255) / 256, 256>>>(xgr, hW, nl_bih, nl_bhh, hR, cR,
                                                     S_RT, 0, 1, 3, 0, 1);
        for (int t = 1; t < 3; t++) {
            gemm(hR, nl_Whh, nullptr, hW, S_RT, G_DIM, E_DIM, 0, 0);
            lstm_step_kernel<<<(thr + 255) / 256, 256>>>(xgr, hW, nl_bih, nl_bhh, hR, cR,
                                                         S_RT, t, 1, 3, 0, 0);
        }
    }

    // ---- Phase G: root concat block ----
    {
        int thr = S_RT * 2 * E_DIM;
        concat_kernel<<<(thr + 255) / 256, 256>>>(hR, 0, no_comps, 1, cat, S_RT);
        gemm(cat,  cc_w0, cc_b0, t200, S_RT, 200, 2 * E_DIM, 1, 0);
        gemm(t200, cc_w1, cc_b1, prog, S_RT, E_DIM, 200, 1, 0);
    }

    // ---- Phase H: regression head ----
    gemm(prog, rg_w0, rg_b0, r0, S_RT, 200, E_DIM, 1, 0);
    gemm(r0,   rg_w1, rg_b1, r1, S_RT, E_DIM, 200, 1, 0);
    pred_kernel<<<(S_RT * 32 + 255) / 256, 256>>>(r1, pred_w, pred_b, out, S_RT);
}

// round 3
// speedup vs baseline: 1.4388x; 1.4388x over previous
#include <cuda_runtime.h>
#include <math.h>
#include <stdint.h>

// ---------------------------------------------------------------------------
// Model_Recursive_LSTM_v2 — 3xTF32 tensor-core GEMM version
// B=256, L=64 (only 0..47 used), IN=1024, E=180
// ---------------------------------------------------------------------------

#define E_DIM 180
#define G_DIM 720          // 4*E
#define M_CE  12288        // 256 * 48 effective rows
#define S_CL  1536         // 256 * 6 leaf sequences
#define S_MID 768          // 256 * 3
#define S_RT  256

// ---- scratch layout (floats) ----
#define OFF_EMB0  0UL                    // 12288*600
#define OFF_EMB1  7372800UL              // 12288*350
#define OFF_EMB2  11673600UL             // 12288*200
#define OFF_EMBD  14131200UL             // 12288*180
#define OFF_XG    16343040UL             // 12288*720 (cl x-proj)
#define OFF_XGM   25190400UL             // 1536*720  (mid x-proj)
#define OFF_XGR   26296320UL             // 768*720   (root x-proj)
#define OFF_HW    26849280UL             // 1536*720  (h@Whh^T, reused)
#define OFF_HA    27955200UL             // 1536*180  (cl h)
#define OFF_CA    28231680UL             // 1536*180  (cl c)
#define OFF_CAT   28508160UL             // 1536*360
#define OFF_T200  29061120UL             // 1536*200
#define OFF_LEAF  29368320UL             // 1536*180
#define OFF_HM    29644800UL             // 768*180
#define OFF_CM    29783040UL             // 768*180
#define OFF_MIDO  29921280UL             // 768*180
#define OFF_HR    30059520UL             // 256*180
#define OFF_CR    30105600UL             // 256*180
#define OFF_PROG  30151680UL             // 256*180
#define OFF_R0    30197760UL             // 256*200
#define OFF_R1    30248960UL             // 256*180
#define SCRATCH_F 30295040UL

__device__ float g_scratch[SCRATCH_F];

// ---------------------------------------------------------------------------
// 3xTF32 tensor-core GEMM: C[M,N] = act( A[M,K] @ W[N,K]^T + bias )
// Each operand split v = hi + lo (both tf32); acc += hi*hi + hi*lo + lo*hi.
// remap!=0: logical A-row m maps to physical row (m/48)*64 + (m%48)
// Block tile 128x128, BK=16. 8 warps, each 64(M)x32(N) via m16n8k8 mma.
// ---------------------------------------------------------------------------
#define BM 128
#define BN 128
#define BKT 16
#define SPAD 132   // smem row stride (words), conflict-free fragment reads

__device__ __forceinline__ uint32_t f2tf32(float v) {
    uint32_t r;
    asm("cvt.rna.tf32.f32 %0, %1;" : "=r"(r) : "f"(v));
    return r;
}

__device__ __forceinline__ void mma_tf32(float* d, const uint32_t* a, const uint32_t* b) {
    asm volatile(
        "mma.sync.aligned.m16n8k8.row.col.f32.tf32.tf32.f32 "
        "{%0,%1,%2,%3}, {%4,%5,%6,%7}, {%8,%9}, {%0,%1,%2,%3};"
        : "+f"(d[0]), "+f"(d[1]), "+f"(d[2]), "+f"(d[3])
        : "r"(a[0]), "r"(a[1]), "r"(a[2]), "r"(a[3]),
          "r"(b[0]), "r"(b[1]));
}

__global__ __launch_bounds__(256) void mma_gemm_kernel(
    const float* __restrict__ A, const float* __restrict__ W,
    const float* __restrict__ bias, float* __restrict__ C,
    int M, int N, int K, int act, int remap)
{
    __shared__ uint32_t AsH[BKT][SPAD];   // [k][m] hi
    __shared__ uint32_t AsL[BKT][SPAD];   // [k][m] lo
    __shared__ uint32_t BsH[BKT][SPAD];   // [k][n] hi
    __shared__ uint32_t BsL[BKT][SPAD];   // [k][n] lo

    const int tid  = threadIdx.x;
    const int warp = tid >> 5;
    const int lane = tid & 31;
    const int wm = warp & 1;        // 2 warps along M
    const int wn = warp >> 1;       // 4 warps along N
    const int bm = blockIdx.y * BM;
    const int bn = blockIdx.x * BN;

    const int grp = lane >> 2;      // 0..7
    const int tig = lane & 3;       // 0..3

    float acc[4][4][4];             // [mtile][ntile][creg]
#pragma unroll
    for (int i = 0; i < 4; i++)
#pragma unroll
        for (int j = 0; j < 4; j++)
#pragma unroll
            for (int r = 0; r < 4; r++) acc[i][j][r] = 0.f;

    // global-load assignment: thread loads 8 consecutive k of one row
    const int arow = tid >> 1;
    const int akof = (tid & 1) * 8;
    long abase = -1;
    {
        int gm = bm + arow;
        if (gm < M) {
            long r = remap ? ((long)(gm / 48) * 64 + (gm % 48)) : (long)gm;
            abase = r * (long)K;
        }
    }
    long bbase = (bn + arow < N) ? (long)(bn + arow) * K : -1;

    for (int k0 = 0; k0 < K; k0 += BKT) {
#pragma unroll
        for (int j = 0; j < 8; j++) {
            int gk = k0 + akof + j;
            float va = (abase >= 0 && gk < K) ? A[abase + gk] : 0.f;
            float vb = (bbase >= 0 && gk < K) ? W[bbase + gk] : 0.f;
            uint32_t ah = f2tf32(va);
            uint32_t bh = f2tf32(vb);
            AsH[akof + j][arow] = ah;
            AsL[akof + j][arow] = f2tf32(va - __uint_as_float(ah));
            BsH[akof + j][arow] = bh;
            BsL[akof + j][arow] = f2tf32(vb - __uint_as_float(bh));
        }
        __syncthreads();

        // ---- compute: 2 k-slices of 8 ----
#pragma unroll
        for (int ks = 0; ks < 2; ks++) {
            const int kb = ks * 8;
            uint32_t ah[4][4], al[4][4];
            uint32_t bh[4][2], bl[4][2];
#pragma unroll
            for (int mt = 0; mt < 4; mt++) {
                int mr = wm * 64 + mt * 16 + grp;
                ah[mt][0] = AsH[kb + tig][mr];
                ah[mt][1] = AsH[kb + tig][mr + 8];
                ah[mt][2] = AsH[kb + tig + 4][mr];
                ah[mt][3] = AsH[kb + tig + 4][mr + 8];
                al[mt][0] = AsL[kb + tig][mr];
                al[mt][1] = AsL[kb + tig][mr + 8];
                al[mt][2] = AsL[kb + tig + 4][mr];
                al[mt][3] = AsL[kb + tig + 4][mr + 8];
            }
#pragma unroll
            for (int nt = 0; nt < 4; nt++) {
                int nc = wn * 32 + nt * 8 + grp;
                bh[nt][0] = BsH[kb + tig][nc];
                bh[nt][1] = BsH[kb + tig + 4][nc];
                bl[nt][0] = BsL[kb + tig][nc];
                bl[nt][1] = BsL[kb + tig + 4][nc];
            }
#pragma unroll
            for (int mt = 0; mt < 4; mt++)
#pragma unroll
                for (int nt = 0; nt < 4; nt++) {
                    mma_tf32(acc[mt][nt], ah[mt], bl[nt]);  // hi*lo
                    mma_tf32(acc[mt][nt], al[mt], bh[nt]);  // lo*hi
                    mma_tf32(acc[mt][nt], ah[mt], bh[nt]);  // hi*hi
                }
        }
        __syncthreads();
    }

    // ---- epilogue: bias + ELU + store ----
#pragma unroll
    for (int mt = 0; mt < 4; mt++) {
        int r0 = bm + wm * 64 + mt * 16 + grp;
        int r1 = r0 + 8;
#pragma unroll
        for (int nt = 0; nt < 4; nt++) {
            int cc = bn + wn * 32 + nt * 8 + tig * 2;
#pragma unroll
            for (int h = 0; h < 2; h++) {
                int rr = h ? r1 : r0;
                if (rr >= M) continue;
#pragma unroll
                for (int q = 0; q < 2; q++) {
                    int gn = cc + q;
                    if (gn >= N) continue;
                    float v = acc[mt][nt][h * 2 + q];
                    if (bias) v += bias[gn];
                    if (act) v = v > 0.f ? v : (expf(v) - 1.f);
                    C[(long)rr * N + gn] = v;
                }
            }
        }
    }
}

// ---------------------------------------------------------------------------
// LSTM pointwise step: gate order i,f,g,o (torch).
// xg row for sequence s at time t: (s/divA)*mulA + (s%divA)*mulB + t
// first!=0: h_prev = c_prev = 0 and hW ignored.
// ---------------------------------------------------------------------------
__device__ __forceinline__ float sigf(float x) { return 1.f / (1.f + expf(-x)); }

__global__ void lstm_step_kernel(
    const float* __restrict__ xg, const float* __restrict__ hW,
    const float* __restrict__ bih, const float* __restrict__ bhh,
    float* __restrict__ h, float* __restrict__ c,
    int S, int t, int divA, int mulA, int mulB, int first)
{
    int idx = blockIdx.x * blockDim.x + threadIdx.x;
    if (idx >= S * E_DIM) return;
    int s = idx / E_DIM, e = idx % E_DIM;
    int xrow = (s / divA) * mulA + (s % divA) * mulB + t;
    const float* xr = xg + (long)xrow * G_DIM;

    float gi = xr[e]             + bih[e]             + bhh[e];
    float gf = xr[E_DIM + e]     + bih[E_DIM + e]     + bhh[E_DIM + e];
    float gg = xr[2 * E_DIM + e] + bih[2 * E_DIM + e] + bhh[2 * E_DIM + e];
    float go = xr[3 * E_DIM + e] + bih[3 * E_DIM + e] + bhh[3 * E_DIM + e];

    float cprev = 0.f;
    if (!first) {
        const float* hr = hW + (long)s * G_DIM;
        gi += hr[e]; gf += hr[E_DIM + e]; gg += hr[2 * E_DIM + e]; go += hr[3 * E_DIM + e];
        cprev = c[idx];
    }
    float cn = sigf(gf) * cprev + sigf(gi) * tanhf(gg);
    c[idx] = cn;
    h[idx] = sigf(go) * tanhf(cn);
}

// ---------------------------------------------------------------------------
// Assemble concat rows: cat[r][0:180]=first, cat[r][180:360]=second
// ---------------------------------------------------------------------------
__global__ void concat_kernel(
    const float* __restrict__ first, int firstB,
    const float* __restrict__ second, int secondB,
    float* __restrict__ cat, int rows)
{
    int idx = blockIdx.x * blockDim.x + threadIdx.x;
    if (idx >= rows * 2 * E_DIM) return;
    int r = idx / (2 * E_DIM), e = idx % (2 * E_DIM);
    float v;
    if (e < E_DIM) v = firstB  ? first[e]            : first[(long)r * E_DIM + e];
    else { int e2 = e - E_DIM; v = secondB ? second[e2] : second[(long)r * E_DIM + e2]; }
    cat[idx] = v;
}

// ---------------------------------------------------------------------------
// Final prediction: out[b] = dot(x[b], w) + b0   (one warp per row)
// ---------------------------------------------------------------------------
__global__ void pred_kernel(const float* __restrict__ x, const float* __restrict__ w,
                            const float* __restrict__ b, float* __restrict__ out, int rows)
{
    int gwarp = (blockIdx.x * blockDim.x + threadIdx.x) >> 5;
    int lane = threadIdx.x & 31;
    if (gwarp >= rows) return;
    float s = 0.f;
    for (int e = lane; e < E_DIM; e += 32) s += x[(long)gwarp * E_DIM + e] * w[e];
#pragma unroll
    for (int o = 16; o; o >>= 1) s += __shfl_down_sync(0xffffffffu, s, o);
    if (lane == 0) out[gwarp] = s + b[0];
}

// ---------------------------------------------------------------------------
// host side
// ---------------------------------------------------------------------------
static inline void gemm(const float* A, const float* W, const float* bias, float* C,
                        int M, int N, int K, int act, int remap)
{
    dim3 grid((N + BN - 1) / BN, (M + BM - 1) / BM);
    mma_gemm_kernel<<<grid, 256>>>(A, W, bias, C, M, N, K, act, remap);
}

extern "C" void kernel_launch(void* const* d_in, const int* in_sizes, int n_in,
                              void* d_out, int out_size)
{
    const float* ast    = (const float*)d_in[0];
    const float* ce_w0  = (const float*)d_in[1];  const float* ce_b0 = (const float*)d_in[2];
    const float* ce_w1  = (const float*)d_in[3];  const float* ce_b1 = (const float*)d_in[4];
    const float* ce_w2  = (const float*)d_in[5];  const float* ce_b2 = (const float*)d_in[6];
    const float* ce_w3  = (const float*)d_in[7];  const float* ce_b3 = (const float*)d_in[8];
    const float* cc_w0  = (const float*)d_in[9];  const float* cc_b0 = (const float*)d_in[10];
    const float* cc_w1  = (const float*)d_in[11]; const float* cc_b1 = (const float*)d_in[12];
    const float* rg_w0  = (const float*)d_in[13]; const float* rg_b0 = (const float*)d_in[14];
    const float* rg_w1  = (const float*)d_in[15]; const float* rg_b1 = (const float*)d_in[16];
    const float* pred_w = (const float*)d_in[17]; const float* pred_b = (const float*)d_in[18];
    const float* cl_Wih = (const float*)d_in[19]; const float* cl_Whh = (const float*)d_in[20];
    const float* cl_bih = (const float*)d_in[21]; const float* cl_bhh = (const float*)d_in[22];
    const float* nl_Wih = (const float*)d_in[23]; const float* nl_Whh = (const float*)d_in[24];
    const float* nl_bih = (const float*)d_in[25]; const float* nl_bhh = (const float*)d_in[26];
    const float* no_comps = (const float*)d_in[27];
    const float* no_nodes = (const float*)d_in[28];
    float* out = (float*)d_out;

    float* S0 = nullptr;
    cudaGetSymbolAddress((void**)&S0, g_scratch);

    float* emb0 = S0 + OFF_EMB0;  float* emb1 = S0 + OFF_EMB1;
    float* emb2 = S0 + OFF_EMB2;  float* embd = S0 + OFF_EMBD;
    float* xg   = S0 + OFF_XG;    float* xgm  = S0 + OFF_XGM;  float* xgr = S0 + OFF_XGR;
    float* hW   = S0 + OFF_HW;
    float* hA   = S0 + OFF_HA;    float* cA   = S0 + OFF_CA;
    float* cat  = S0 + OFF_CAT;   float* t200 = S0 + OFF_T200;
    float* leaf = S0 + OFF_LEAF;
    float* hM   = S0 + OFF_HM;    float* cM   = S0 + OFF_CM;   float* mido = S0 + OFF_MIDO;
    float* hR   = S0 + OFF_HR;    float* cR   = S0 + OFF_CR;
    float* prog = S0 + OFF_PROG;  float* r0   = S0 + OFF_R0;   float* r1  = S0 + OFF_R1;

    // ---- Phase A: comp-embedding MLP on the 48 used positions ----
    gemm(ast,  ce_w0, ce_b0, emb0, M_CE, 600, 1024, 1, 1);   // remap 48-of-64
    gemm(emb0, ce_w1, ce_b1, emb1, M_CE, 350, 600, 1, 0);
    gemm(emb1, ce_w2, ce_b2, emb2, M_CE, 200, 350, 1, 0);
    gemm(emb2, ce_w3, ce_b3, embd, M_CE, E_DIM, 200, 1, 0);

    // ---- Phase B: cl LSTM over 6 leaves x 8 steps (batched S=1536) ----
    gemm(embd, cl_Wih, nullptr, xg, M_CE, G_DIM, E_DIM, 0, 0);   // x-proj hoisted
    {
        int thr = S_CL * E_DIM;
        lstm_step_kernel<<<(thr + 255) / 256, 256>>>(xg, hW, cl_bih, cl_bhh, hA, cA,
                                                     S_CL, 0, 6, 48, 8, 1);
        for (int t = 1; t < 8; t++) {
            gemm(hA, cl_Whh, nullptr, hW, S_CL, G_DIM, E_DIM, 0, 0);
            lstm_step_kernel<<<(thr + 255) / 256, 256>>>(xg, hW, cl_bih, cl_bhh, hA, cA,
                                                         S_CL, t, 6, 48, 8, 0);
        }
    }

    // ---- Phase C: leaf concat block (nodes=no_nodes bcast, comps=h) ----
    {
        int thr = S_CL * 2 * E_DIM;
        concat_kernel<<<(thr + 255) / 256, 256>>>(no_nodes, 1, hA, 0, cat, S_CL);
        gemm(cat,  cc_w0, cc_b0, t200, S_CL, 200, 2 * E_DIM, 1, 0);
        gemm(t200, cc_w1, cc_b1, leaf, S_CL, E_DIM, 200, 1, 0);
    }

    // ---- Phase D: mid nl LSTM (S=768, T=2 over leaf pairs) ----
    gemm(leaf, nl_Wih, nullptr, xgm, S_CL, G_DIM, E_DIM, 0, 0);
    {
        int thr = S_MID * E_DIM;
        lstm_step_kernel<<<(thr + 255) / 256, 256>>>(xgm, hW, nl_bih, nl_bhh, hM, cM,
                                                     S_MID, 0, 3, 6, 2, 1);
        gemm(hM, nl_Whh, nullptr, hW, S_MID, G_DIM, E_DIM, 0, 0);
        lstm_step_kernel<<<(thr + 255) / 256, 256>>>(xgm, hW, nl_bih, nl_bhh, hM, cM,
                                                     S_MID, 1, 3, 6, 2, 0);
    }

    // ---- Phase E: mid concat block (nodes=h, comps=no_comps bcast) ----
    {
        int thr = S_MID * 2 * E_DIM;
        concat_kernel<<<(thr + 255) / 256, 256>>>(hM, 0, no_comps, 1, cat, S_MID);
        gemm(cat,  cc_w0, cc_b0, t200, S_MID, 200, 2 * E_DIM, 1, 0);
        gemm(t200, cc_w1, cc_b1, mido, S_MID, E_DIM, 200, 1, 0);
    }

    // ---- Phase F: root nl LSTM (S=256, T=3 over mids) ----
    gemm(mido, nl_Wih, nullptr, xgr, S_MID, G_DIM, E_DIM, 0, 0);
    {
        int thr = S_RT * E_DIM;
        lstm_step_kernel<<<(thr + 255) / 256, 256>>>(xgr, hW, nl_bih, nl_bhh, hR, cR,
                                                     S_RT, 0, 1, 3, 0, 1);
        for (int t = 1; t < 3; t++) {
            gemm(hR, nl_Whh, nullptr, hW, S_RT, G_DIM, E_DIM, 0, 0);
            lstm_step_kernel<<<(thr + 255) / 256, 256>>>(xgr, hW, nl_bih, nl_bhh, hR, cR,
                                                         S_RT, t, 1, 3, 0, 0);
        }
    }

    // ---- Phase G: root concat block ----
    {
        int thr = S_RT * 2 * E_DIM;
        concat_kernel<<<(thr + 255) / 256, 256>>>(hR, 0, no_comps, 1, cat, S_RT);
        gemm(cat,  cc_w0, cc_b0, t200, S_RT, 200, 2 * E_DIM, 1, 0);
        gemm(t200, cc_w1, cc_b1, prog, S_RT, E_DIM, 200, 1, 0);
    }

    // ---- Phase H: regression head ----
    gemm(prog, rg_w0, rg_b0, r0, S_RT, 200, E_DIM, 1, 0);
    gemm(r0,   rg_w1, rg_b1, r1, S_RT, E_DIM, 200, 1, 0);
    pred_kernel<<<(S_RT * 32 + 255) / 256, 256>>>(r1, pred_w, pred_b, out, S_RT);
}

// round 4
// speedup vs baseline: 1.4404x; 1.0011x over previous
#include <cuda_runtime.h>
#include <math.h>
#include <stdint.h>

// ---------------------------------------------------------------------------
// Model_Recursive_LSTM_v2 — 3xTF32 tensor-core GEMM, software-pipelined
// B=256, L=64 (only 0..47 used), IN=1024, E=180
// ---------------------------------------------------------------------------

#define E_DIM 180
#define G_DIM 720          // 4*E
#define M_CE  12288        // 256 * 48 effective rows
#define S_CL  1536         // 256 * 6 leaf sequences
#define S_MID 768          // 256 * 3
#define S_RT  256

// ---- scratch layout (floats) ----
#define OFF_EMB0  0UL                    // 12288*600
#define OFF_EMB1  7372800UL              // 12288*350
#define OFF_EMB2  11673600UL             // 12288*200
#define OFF_EMBD  14131200UL             // 12288*180
#define OFF_XG    16343040UL             // 12288*720 (cl x-proj)
#define OFF_XGM   25190400UL             // 1536*720  (mid x-proj)
#define OFF_XGR   26296320UL             // 768*720   (root x-proj)
#define OFF_HW    26849280UL             // 1536*720  (h@Whh^T, reused)
#define OFF_HA    27955200UL             // 1536*180  (cl h)
#define OFF_CA    28231680UL             // 1536*180  (cl c)
#define OFF_CAT   28508160UL             // 1536*360
#define OFF_T200  29061120UL             // 1536*200
#define OFF_LEAF  29368320UL             // 1536*180
#define OFF_HM    29644800UL             // 768*180
#define OFF_CM    29783040UL             // 768*180
#define OFF_MIDO  29921280UL             // 768*180
#define OFF_HR    30059520UL             // 256*180
#define OFF_CR    30105600UL             // 256*180
#define OFF_PROG  30151680UL             // 256*180
#define OFF_R0    30197760UL             // 256*200
#define OFF_R1    30248960UL             // 256*180
#define SCRATCH_F 30295040UL

__device__ float g_scratch[SCRATCH_F];

// ---------------------------------------------------------------------------
// 3xTF32 pipelined GEMM: C[M,N] = act( A[M,K] @ W[N,K]^T + bias )
// Each operand split v = hi + lo (tf32); acc += hi*hi + hi*lo + lo*hi.
// Double-buffered smem, register-staged global loads (1 sync / K-slab).
// remap!=0: logical A-row m maps to physical row (m/48)*64 + (m%48)
// ---------------------------------------------------------------------------
#define BM 128
#define BN 128
#define BKT 16
#define SPAD 132                 // smem row stride (words)
#define TILEW (BKT * SPAD)       // 2112 words per array
#define STAGEW (4 * TILEW)       // AsH,AsL,BsH,BsL per stage
#define SMEM_BYTES (2 * STAGEW * 4)   // 67584 B

__device__ __forceinline__ uint32_t f2tf32(float v) {
    uint32_t r;
    asm("cvt.rna.tf32.f32 %0, %1;" : "=r"(r) : "f"(v));
    return r;
}

__device__ __forceinline__ void mma_tf32(float* d, const uint32_t* a, const uint32_t* b) {
    asm volatile(
        "mma.sync.aligned.m16n8k8.row.col.f32.tf32.tf32.f32 "
        "{%0,%1,%2,%3}, {%4,%5,%6,%7}, {%8,%9}, {%0,%1,%2,%3};"
        : "+f"(d[0]), "+f"(d[1]), "+f"(d[2]), "+f"(d[3])
        : "r"(a[0]), "r"(a[1]), "r"(a[2]), "r"(a[3]),
          "r"(b[0]), "r"(b[1]));
}

extern __shared__ uint32_t dynsmem[];

__global__ __launch_bounds__(256) void mma_gemm_kernel(
    const float* __restrict__ A, const float* __restrict__ W,
    const float* __restrict__ bias, float* __restrict__ C,
    int M, int N, int K, int act, int remap)
{
    const int tid  = threadIdx.x;
    const int warp = tid >> 5;
    const int lane = tid & 31;
    const int wm = warp & 1;        // 2 warps along M
    const int wn = warp >> 1;       // 4 warps along N
    const int bm = blockIdx.y * BM;
    const int bn = blockIdx.x * BN;

    const int grp = lane >> 2;      // 0..7
    const int tig = lane & 3;       // 0..3

    float acc[4][4][4];
#pragma unroll
    for (int i = 0; i < 4; i++)
#pragma unroll
        for (int j = 0; j < 4; j++)
#pragma unroll
            for (int r = 0; r < 4; r++) acc[i][j][r] = 0.f;

    // global-load assignment: thread loads 8 consecutive k of one row
    const int arow = tid >> 1;
    const int akof = (tid & 1) * 8;
    long abase = -1;
    {
        int gm = bm + arow;
        if (gm < M) {
            long r = remap ? ((long)(gm / 48) * 64 + (gm % 48)) : (long)gm;
            abase = r * (long)K;
        }
    }
    long bbase = (bn + arow < N) ? (long)(bn + arow) * K : -1;

    float ra[8], rb[8];

    // ---- prologue: load + convert + store slab 0 ----
#pragma unroll
    for (int j = 0; j < 8; j++) {
        int gk = akof + j;
        ra[j] = (abase >= 0 && gk < K) ? A[abase + gk] : 0.f;
        rb[j] = (bbase >= 0 && gk < K) ? W[bbase + gk] : 0.f;
    }
    {
        uint32_t* sAH = dynsmem;
        uint32_t* sAL = dynsmem + TILEW;
        uint32_t* sBH = dynsmem + 2 * TILEW;
        uint32_t* sBL = dynsmem + 3 * TILEW;
#pragma unroll
        for (int j = 0; j < 8; j++) {
            uint32_t ah = f2tf32(ra[j]);
            uint32_t bh = f2tf32(rb[j]);
            int off = (akof + j) * SPAD + arow;
            sAH[off] = ah;
            sAL[off] = f2tf32(ra[j] - __uint_as_float(ah));
            sBH[off] = bh;
            sBL[off] = f2tf32(rb[j] - __uint_as_float(bh));
        }
    }
    __syncthreads();

    int cur = 0;
    for (int k0 = 0; k0 < K; k0 += BKT) {
        const int nxt = k0 + BKT;
        const bool has = nxt < K;

        // issue next slab's global loads (latency overlapped with MMAs below)
        if (has) {
#pragma unroll
            for (int j = 0; j < 8; j++) {
                int gk = nxt + akof + j;
                ra[j] = (abase >= 0 && gk < K) ? A[abase + gk] : 0.f;
                rb[j] = (bbase >= 0 && gk < K) ? W[bbase + gk] : 0.f;
            }
        }

        // ---- compute current slab ----
        {
            const uint32_t* sAH = dynsmem + cur * STAGEW;
            const uint32_t* sAL = sAH + TILEW;
            const uint32_t* sBH = sAH + 2 * TILEW;
            const uint32_t* sBL = sAH + 3 * TILEW;
#pragma unroll
            for (int ks = 0; ks < 2; ks++) {
                const int kb = ks * 8;
                uint32_t ah[4][4], al[4][4];
                uint32_t bh[4][2], bl[4][2];
#pragma unroll
                for (int mt = 0; mt < 4; mt++) {
                    int mr = wm * 64 + mt * 16 + grp;
                    int o0 = (kb + tig) * SPAD;
                    int o1 = (kb + tig + 4) * SPAD;
                    ah[mt][0] = sAH[o0 + mr];
                    ah[mt][1] = sAH[o0 + mr + 8];
                    ah[mt][2] = sAH[o1 + mr];
                    ah[mt][3] = sAH[o1 + mr + 8];
                    al[mt][0] = sAL[o0 + mr];
                    al[mt][1] = sAL[o0 + mr + 8];
                    al[mt][2] = sAL[o1 + mr];
                    al[mt][3] = sAL[o1 + mr + 8];
                }
#pragma unroll
                for (int nt = 0; nt < 4; nt++) {
                    int nc = wn * 32 + nt * 8 + grp;
                    int o0 = (kb + tig) * SPAD;
                    int o1 = (kb + tig + 4) * SPAD;
                    bh[nt][0] = sBH[o0 + nc];
                    bh[nt][1] = sBH[o1 + nc];
                    bl[nt][0] = sBL[o0 + nc];
                    bl[nt][1] = sBL[o1 + nc];
                }
#pragma unroll
                for (int mt = 0; mt < 4; mt++)
#pragma unroll
                    for (int nt = 0; nt < 4; nt++) {
                        mma_tf32(acc[mt][nt], ah[mt], bl[nt]);  // hi*lo
                        mma_tf32(acc[mt][nt], al[mt], bh[nt]);  // lo*hi
                        mma_tf32(acc[mt][nt], ah[mt], bh[nt]);  // hi*hi
                    }
            }
        }

        // ---- convert + store next slab into the other buffer ----
        if (has) {
            uint32_t* sAH = dynsmem + (cur ^ 1) * STAGEW;
            uint32_t* sAL = sAH + TILEW;
            uint32_t* sBH = sAH + 2 * TILEW;
            uint32_t* sBL = sAH + 3 * TILEW;
#pragma unroll
            for (int j = 0; j < 8; j++) {
                uint32_t ah = f2tf32(ra[j]);
                uint32_t bh = f2tf32(rb[j]);
                int off = (akof + j) * SPAD + arow;
                sAH[off] = ah;
                sAL[off] = f2tf32(ra[j] - __uint_as_float(ah));
                sBH[off] = bh;
                sBL[off] = f2tf32(rb[j] - __uint_as_float(bh));
            }
        }
        __syncthreads();
        cur ^= 1;
    }

    // ---- epilogue: bias + ELU + store ----
#pragma unroll
    for (int mt = 0; mt < 4; mt++) {
        int r0 = bm + wm * 64 + mt * 16 + grp;
        int r1 = r0 + 8;
#pragma unroll
        for (int nt = 0; nt < 4; nt++) {
            int cc = bn + wn * 32 + nt * 8 + tig * 2;
#pragma unroll
            for (int h = 0; h < 2; h++) {
                int rr = h ? r1 : r0;
                if (rr >= M) continue;
#pragma unroll
                for (int q = 0; q < 2; q++) {
                    int gn = cc + q;
                    if (gn >= N) continue;
                    float v = acc[mt][nt][h * 2 + q];
                    if (bias) v += bias[gn];
                    if (act) v = v > 0.f ? v : (expf(v) - 1.f);
                    C[(long)rr * N + gn] = v;
                }
            }
        }
    }
}

// ---------------------------------------------------------------------------
// LSTM pointwise step: gate order i,f,g,o (torch).
// xg row for sequence s at time t: (s/divA)*mulA + (s%divA)*mulB + t
// first!=0: h_prev = c_prev = 0 and hW ignored.
// ---------------------------------------------------------------------------
__device__ __forceinline__ float sigf(float x) { return 1.f / (1.f + expf(-x)); }

__global__ void lstm_step_kernel(
    const float* __restrict__ xg, const float* __restrict__ hW,
    const float* __restrict__ bih, const float* __restrict__ bhh,
    float* __restrict__ h, float* __restrict__ c,
    int S, int t, int divA, int mulA, int mulB, int first)
{
    int idx = blockIdx.x * blockDim.x + threadIdx.x;
    if (idx >= S * E_DIM) return;
    int s = idx / E_DIM, e = idx % E_DIM;
    int xrow = (s / divA) * mulA + (s % divA) * mulB + t;
    const float* xr = xg + (long)xrow * G_DIM;

    float gi = xr[e]             + bih[e]             + bhh[e];
    float gf = xr[E_DIM + e]     + bih[E_DIM + e]     + bhh[E_DIM + e];
    float gg = xr[2 * E_DIM + e] + bih[2 * E_DIM + e] + bhh[2 * E_DIM + e];
    float go = xr[3 * E_DIM + e] + bih[3 * E_DIM + e] + bhh[3 * E_DIM + e];

    float cprev = 0.f;
    if (!first) {
        const float* hr = hW + (long)s * G_DIM;
        gi += hr[e]; gf += hr[E_DIM + e]; gg += hr[2 * E_DIM + e]; go += hr[3 * E_DIM + e];
        cprev = c[idx];
    }
    float cn = sigf(gf) * cprev + sigf(gi) * tanhf(gg);
    c[idx] = cn;
    h[idx] = sigf(go) * tanhf(cn);
}

// ---------------------------------------------------------------------------
// Assemble concat rows: cat[r][0:180]=first, cat[r][180:360]=second
// ---------------------------------------------------------------------------
__global__ void concat_kernel(
    const float* __restrict__ first, int firstB,
    const float* __restrict__ second, int secondB,
    float* __restrict__ cat, int rows)
{
    int idx = blockIdx.x * blockDim.x + threadIdx.x;
    if (idx >= rows * 2 * E_DIM) return;
    int r = idx / (2 * E_DIM), e = idx % (2 * E_DIM);
    float v;
    if (e < E_DIM) v = firstB  ? first[e]            : first[(long)r * E_DIM + e];
    else { int e2 = e - E_DIM; v = secondB ? second[e2] : second[(long)r * E_DIM + e2]; }
    cat[idx] = v;
}

// ---------------------------------------------------------------------------
// Final prediction: out[b] = dot(x[b], w) + b0   (one warp per row)
// ---------------------------------------------------------------------------
__global__ void pred_kernel(const float* __restrict__ x, const float* __restrict__ w,
                            const float* __restrict__ b, float* __restrict__ out, int rows)
{
    int gwarp = (blockIdx.x * blockDim.x + threadIdx.x) >> 5;
    int lane = threadIdx.x & 31;
    if (gwarp >= rows) return;
    float s = 0.f;
    for (int e = lane; e < E_DIM; e += 32) s += x[(long)gwarp * E_DIM + e] * w[e];
#pragma unroll
    for (int o = 16; o; o >>= 1) s += __shfl_down_sync(0xffffffffu, s, o);
    if (lane == 0) out[gwarp] = s + b[0];
}

// ---------------------------------------------------------------------------
// host side
// ---------------------------------------------------------------------------
static inline void gemm(const float* A, const float* W, const float* bias, float* C,
                        int M, int N, int K, int act, int remap)
{
    dim3 grid((N + BN - 1) / BN, (M + BM - 1) / BM);
    mma_gemm_kernel<<<grid, 256, SMEM_BYTES>>>(A, W, bias, C, M, N, K, act, remap);
}

extern "C" void kernel_launch(void* const* d_in, const int* in_sizes, int n_in,
                              void* d_out, int out_size)
{
    cudaFuncSetAttribute(mma_gemm_kernel,
                         cudaFuncAttributeMaxDynamicSharedMemorySize, SMEM_BYTES);

    const float* ast    = (const float*)d_in[0];
    const float* ce_w0  = (const float*)d_in[1];  const float* ce_b0 = (const float*)d_in[2];
    const float* ce_w1  = (const float*)d_in[3];  const float* ce_b1 = (const float*)d_in[4];
    const float* ce_w2  = (const float*)d_in[5];  const float* ce_b2 = (const float*)d_in[6];
    const float* ce_w3  = (const float*)d_in[7];  const float* ce_b3 = (const float*)d_in[8];
    const float* cc_w0  = (const float*)d_in[9];  const float* cc_b0 = (const float*)d_in[10];
    const float* cc_w1  = (const float*)d_in[11]; const float* cc_b1 = (const float*)d_in[12];
    const float* rg_w0  = (const float*)d_in[13]; const float* rg_b0 = (const float*)d_in[14];
    const float* rg_w1  = (const float*)d_in[15]; const float* rg_b1 = (const float*)d_in[16];
    const float* pred_w = (const float*)d_in[17]; const float* pred_b = (const float*)d_in[18];
    const float* cl_Wih = (const float*)d_in[19]; const float* cl_Whh = (const float*)d_in[20];
    const float* cl_bih = (const float*)d_in[21]; const float* cl_bhh = (const float*)d_in[22];
    const float* nl_Wih = (const float*)d_in[23]; const float* nl_Whh = (const float*)d_in[24];
    const float* nl_bih = (const float*)d_in[25]; const float* nl_bhh = (const float*)d_in[26];
    const float* no_comps = (const float*)d_in[27];
    const float* no_nodes = (const float*)d_in[28];
    float* out = (float*)d_out;

    float* S0 = nullptr;
    cudaGetSymbolAddress((void**)&S0, g_scratch);

    float* emb0 = S0 + OFF_EMB0;  float* emb1 = S0 + OFF_EMB1;
    float* emb2 = S0 + OFF_EMB2;  float* embd = S0 + OFF_EMBD;
    float* xg   = S0 + OFF_XG;    float* xgm  = S0 + OFF_XGM;  float* xgr = S0 + OFF_XGR;
    float* hW   = S0 + OFF_HW;
    float* hA   = S0 + OFF_HA;    float* cA   = S0 + OFF_CA;
    float* cat  = S0 + OFF_CAT;   float* t200 = S0 + OFF_T200;
    float* leaf = S0 + OFF_LEAF;
    float* hM   = S0 + OFF_HM;    float* cM   = S0 + OFF_CM;   float* mido = S0 + OFF_MIDO;
    float* hR   = S0 + OFF_HR;    float* cR   = S0 + OFF_CR;
    float* prog = S0 + OFF_PROG;  float* r0   = S0 + OFF_R0;   float* r1  = S0 + OFF_R1;

    // ---- Phase A: comp-embedding MLP on the 48 used positions ----
    gemm(ast,  ce_w0, ce_b0, emb0, M_CE, 600, 1024, 1, 1);   // remap 48-of-64
    gemm(emb0, ce_w1, ce_b1, emb1, M_CE, 350, 600, 1, 0);
    gemm(emb1, ce_w2, ce_b2, emb2, M_CE, 200, 350, 1, 0);
    gemm(emb2, ce_w3, ce_b3, embd, M_CE, E_DIM, 200, 1, 0);

    // ---- Phase B: cl LSTM over 6 leaves x 8 steps (batched S=1536) ----
    gemm(embd, cl_Wih, nullptr, xg, M_CE, G_DIM, E_DIM, 0, 0);   // x-proj hoisted
    {
        int thr = S_CL * E_DIM;
        lstm_step_kernel<<<(thr + 255) / 256, 256>>>(xg, hW, cl_bih, cl_bhh, hA, cA,
                                                     S_CL, 0, 6, 48, 8, 1);
        for (int t = 1; t < 8; t++) {
            gemm(hA, cl_Whh, nullptr, hW, S_CL, G_DIM, E_DIM, 0, 0);
            lstm_step_kernel<<<(thr + 255) / 256, 256>>>(xg, hW, cl_bih, cl_bhh, hA, cA,
                                                         S_CL, t, 6, 48, 8, 0);
        }
    }

    // ---- Phase C: leaf concat block (nodes=no_nodes bcast, comps=h) ----
    {
        int thr = S_CL * 2 * E_DIM;
        concat_kernel<<<(thr + 255) / 256, 256>>>(no_nodes, 1, hA, 0, cat, S_CL);
        gemm(cat,  cc_w0, cc_b0, t200, S_CL, 200, 2 * E_DIM, 1, 0);
        gemm(t200, cc_w1, cc_b1, leaf, S_CL, E_DIM, 200, 1, 0);
    }

    // ---- Phase D: mid nl LSTM (S=768, T=2 over leaf pairs) ----
    gemm(leaf, nl_Wih, nullptr, xgm, S_CL, G_DIM, E_DIM, 0, 0);
    {
        int thr = S_MID * E_DIM;
        lstm_step_kernel<<<(thr + 255) / 256, 256>>>(xgm, hW, nl_bih, nl_bhh, hM, cM,
                                                     S_MID, 0, 3, 6, 2, 1);
        gemm(hM, nl_Whh, nullptr, hW, S_MID, G_DIM, E_DIM, 0, 0);
        lstm_step_kernel<<<(thr + 255) / 256, 256>>>(xgm, hW, nl_bih, nl_bhh, hM, cM,
                                                     S_MID, 1, 3, 6, 2, 0);
    }

    // ---- Phase E: mid concat block (nodes=h, comps=no_comps bcast) ----
    {
        int thr = S_MID * 2 * E_DIM;
        concat_kernel<<<(thr + 255) / 256, 256>>>(hM, 0, no_comps, 1, cat, S_MID);
        gemm(cat,  cc_w0, cc_b0, t200, S_MID, 200, 2 * E_DIM, 1, 0);
        gemm(t200, cc_w1, cc_b1, mido, S_MID, E_DIM, 200, 1, 0);
    }

    // ---- Phase F: root nl LSTM (S=256, T=3 over mids) ----
    gemm(mido, nl_Wih, nullptr, xgr, S_MID, G_DIM, E_DIM, 0, 0);
    {
        int thr = S_RT * E_DIM;
        lstm_step_kernel<<<(thr + 255) / 256, 256>>>(xgr, hW, nl_bih, nl_bhh, hR, cR,
                                                     S_RT, 0, 1, 3, 0, 1);
        for (int t = 1; t < 3; t++) {
            gemm(hR, nl_Whh, nullptr, hW, S_RT, G_DIM, E_DIM, 0, 0);
            lstm_step_kernel<<<(thr + 255) / 256, 256>>>(xgr, hW, nl_bih, nl_bhh, hR, cR,
                                                         S_RT, t, 1, 3, 0, 0);
        }
    }

    // ---- Phase G: root concat block ----
    {
        int thr = S_RT * 2 * E_DIM;
        concat_kernel<<<(thr + 255) / 256, 256>>>(hR, 0, no_comps, 1, cat, S_RT);
        gemm(cat,  cc_w0, cc_b0, t200, S_RT, 200, 2 * E_DIM, 1, 0);
        gemm(t200, cc_w1, cc_b1, prog, S_RT, E_DIM, 200, 1, 0);
    }

    // ---- Phase H: regression head ----
    gemm(prog, rg_w0, rg_b0, r0, S_RT, 200, E_DIM, 1, 0);
    gemm(r0,   rg_w1, rg_b1, r1, S_RT, E_DIM, 200, 1, 0);
    pred_kernel<<<(S_RT * 32 + 255) / 256, 256>>>(r1, pred_w, pred_b, out, S_RT);
}

// round 5
// speedup vs baseline: 1.8010x; 1.2503x over previous
#include <cuda_runtime.h>
#include <math.h>
#include <stdint.h>

// ---------------------------------------------------------------------------
// Model_Recursive_LSTM_v2 — 3xTF32 tensor-core GEMM, 2 tile sizes + occupancy
// B=256, L=64 (only 0..47 used), IN=1024, E=180
// ---------------------------------------------------------------------------

#define E_DIM 180
#define G_DIM 720          // 4*E
#define M_CE  12288        // 256 * 48 effective rows
#define S_CL  1536         // 256 * 6 leaf sequences
#define S_MID 768          // 256 * 3
#define S_RT  256

// ---- scratch layout (floats) ----
#define OFF_EMB0  0UL                    // 12288*600
#define OFF_EMB1  7372800UL              // 12288*350
#define OFF_EMB2  11673600UL             // 12288*200
#define OFF_EMBD  14131200UL             // 12288*180
#define OFF_XG    16343040UL             // 12288*720 (cl x-proj)
#define OFF_XGM   25190400UL             // 1536*720  (mid x-proj)
#define OFF_XGR   26296320UL             // 768*720   (root x-proj)
#define OFF_HW    26849280UL             // 1536*720  (h@Whh^T, reused)
#define OFF_HA    27955200UL             // 1536*180  (cl h)
#define OFF_CA    28231680UL             // 1536*180  (cl c)
#define OFF_CAT   28508160UL             // 1536*360
#define OFF_T200  29061120UL             // 1536*200
#define OFF_LEAF  29368320UL             // 1536*180
#define OFF_HM    29644800UL             // 768*180
#define OFF_CM    29783040UL             // 768*180
#define OFF_MIDO  29921280UL             // 768*180
#define OFF_HR    30059520UL             // 256*180
#define OFF_CR    30105600UL             // 256*180
#define OFF_PROG  30151680UL             // 256*180
#define OFF_R0    30197760UL             // 256*200
#define OFF_R1    30248960UL             // 256*180
#define SCRATCH_F 30295040UL

__device__ float g_scratch[SCRATCH_F];

__device__ __forceinline__ uint32_t f2tf32(float v) {
    uint32_t r;
    asm("cvt.rna.tf32.f32 %0, %1;" : "=r"(r) : "f"(v));
    return r;
}

__device__ __forceinline__ void mma_tf32(float* d, const uint32_t* a, const uint32_t* b) {
    asm volatile(
        "mma.sync.aligned.m16n8k8.row.col.f32.tf32.tf32.f32 "
        "{%0,%1,%2,%3}, {%4,%5,%6,%7}, {%8,%9}, {%0,%1,%2,%3};"
        : "+f"(d[0]), "+f"(d[1]), "+f"(d[2]), "+f"(d[3])
        : "r"(a[0]), "r"(a[1]), "r"(a[2]), "r"(a[3]),
          "r"(b[0]), "r"(b[1]));
}

extern __shared__ uint32_t dynsmem[];

// ---------------------------------------------------------------------------
// Templated 3xTF32 pipelined GEMM: C[M,N] = act( A[M,K] @ W[N,K]^T + bias )
// BMT==BNT, THREADS = 2*BMT. Warps tile WMT x WNT; each warp MT*16 x NT*8.
// Double-buffered smem; register-staged global loads.
// remap!=0: logical A-row m maps to physical row (m/48)*64 + (m%48)
// ---------------------------------------------------------------------------
template <int BMT, int WMT, int WNT, int MINB>
__global__ __launch_bounds__(2 * BMT, MINB) void mma_gemm_t(
    const float* __restrict__ A, const float* __restrict__ W,
    const float* __restrict__ bias, float* __restrict__ C,
    int M, int N, int K, int act, int remap)
{
    constexpr int BNT = BMT;
    constexpr int MT = BMT / (WMT * 16);
    constexpr int NT = BNT / (WNT * 8);
    constexpr int SPADT = BMT + 4;
    constexpr int TILEWT = 16 * SPADT;
    constexpr int STAGEWT = 4 * TILEWT;

    const int tid  = threadIdx.x;
    const int warp = tid >> 5;
    const int lane = tid & 31;
    const int wm = warp % WMT;
    const int wn = warp / WMT;
    const int bm = blockIdx.y * BMT;
    const int bn = blockIdx.x * BNT;

    const int grp = lane >> 2;      // 0..7
    const int tig = lane & 3;       // 0..3

    float acc[MT][NT][4];
#pragma unroll
    for (int i = 0; i < MT; i++)
#pragma unroll
        for (int j = 0; j < NT; j++)
#pragma unroll
            for (int r = 0; r < 4; r++) acc[i][j][r] = 0.f;

    // global-load assignment: thread loads 8 consecutive k of one row
    const int arow = tid >> 1;
    const int akof = (tid & 1) * 8;
    long abase = -1;
    {
        int gm = bm + arow;
        if (gm < M) {
            long r = remap ? ((long)(gm / 48) * 64 + (gm % 48)) : (long)gm;
            abase = r * (long)K;
        }
    }
    long bbase = (bn + arow < N) ? (long)(bn + arow) * K : -1;

    float ra[8], rb[8];

    // ---- prologue: load + convert + store slab 0 ----
#pragma unroll
    for (int j = 0; j < 8; j++) {
        int gk = akof + j;
        ra[j] = (abase >= 0 && gk < K) ? A[abase + gk] : 0.f;
        rb[j] = (bbase >= 0 && gk < K) ? W[bbase + gk] : 0.f;
    }
    {
        uint32_t* sAH = dynsmem;
        uint32_t* sAL = dynsmem + TILEWT;
        uint32_t* sBH = dynsmem + 2 * TILEWT;
        uint32_t* sBL = dynsmem + 3 * TILEWT;
#pragma unroll
        for (int j = 0; j < 8; j++) {
            uint32_t ah = f2tf32(ra[j]);
            uint32_t bh = f2tf32(rb[j]);
            int off = (akof + j) * SPADT + arow;
            sAH[off] = ah;
            sAL[off] = f2tf32(ra[j] - __uint_as_float(ah));
            sBH[off] = bh;
            sBL[off] = f2tf32(rb[j] - __uint_as_float(bh));
        }
    }
    __syncthreads();

    int cur = 0;
    for (int k0 = 0; k0 < K; k0 += 16) {
        const int nxt = k0 + 16;
        const bool has = nxt < K;

        if (has) {
#pragma unroll
            for (int j = 0; j < 8; j++) {
                int gk = nxt + akof + j;
                ra[j] = (abase >= 0 && gk < K) ? A[abase + gk] : 0.f;
                rb[j] = (bbase >= 0 && gk < K) ? W[bbase + gk] : 0.f;
            }
        }

        // ---- compute current slab ----
        {
            const uint32_t* sAH = dynsmem + cur * STAGEWT;
            const uint32_t* sAL = sAH + TILEWT;
            const uint32_t* sBH = sAH + 2 * TILEWT;
            const uint32_t* sBL = sAH + 3 * TILEWT;
#pragma unroll
            for (int ks = 0; ks < 2; ks++) {
                const int kb = ks * 8;
                uint32_t ah[MT][4], al[MT][4];
                uint32_t bh[NT][2], bl[NT][2];
                const int o0 = (kb + tig) * SPADT;
                const int o1 = (kb + tig + 4) * SPADT;
#pragma unroll
                for (int mt = 0; mt < MT; mt++) {
                    int mr = wm * MT * 16 + mt * 16 + grp;
                    ah[mt][0] = sAH[o0 + mr];
                    ah[mt][1] = sAH[o0 + mr + 8];
                    ah[mt][2] = sAH[o1 + mr];
                    ah[mt][3] = sAH[o1 + mr + 8];
                    al[mt][0] = sAL[o0 + mr];
                    al[mt][1] = sAL[o0 + mr + 8];
                    al[mt][2] = sAL[o1 + mr];
                    al[mt][3] = sAL[o1 + mr + 8];
                }
#pragma unroll
                for (int nt = 0; nt < NT; nt++) {
                    int nc = wn * NT * 8 + nt * 8 + grp;
                    bh[nt][0] = sBH[o0 + nc];
                    bh[nt][1] = sBH[o1 + nc];
                    bl[nt][0] = sBL[o0 + nc];
                    bl[nt][1] = sBL[o1 + nc];
                }
#pragma unroll
                for (int mt = 0; mt < MT; mt++)
#pragma unroll
                    for (int nt = 0; nt < NT; nt++) {
                        mma_tf32(acc[mt][nt], ah[mt], bl[nt]);  // hi*lo
                        mma_tf32(acc[mt][nt], al[mt], bh[nt]);  // lo*hi
                        mma_tf32(acc[mt][nt], ah[mt], bh[nt]);  // hi*hi
                    }
            }
        }

        // ---- convert + store next slab into the other buffer ----
        if (has) {
            uint32_t* sAH = dynsmem + (cur ^ 1) * STAGEWT;
            uint32_t* sAL = sAH + TILEWT;
            uint32_t* sBH = sAH + 2 * TILEWT;
            uint32_t* sBL = sAH + 3 * TILEWT;
#pragma unroll
            for (int j = 0; j < 8; j++) {
                uint32_t ah = f2tf32(ra[j]);
                uint32_t bh = f2tf32(rb[j]);
                int off = (akof + j) * SPADT + arow;
                sAH[off] = ah;
                sAL[off] = f2tf32(ra[j] - __uint_as_float(ah));
                sBH[off] = bh;
                sBL[off] = f2tf32(rb[j] - __uint_as_float(bh));
            }
        }
        __syncthreads();
        cur ^= 1;
    }

    // ---- epilogue: bias + ELU + store ----
#pragma unroll
    for (int mt = 0; mt < MT; mt++) {
        int r0 = bm + wm * MT * 16 + mt * 16 + grp;
        int r1 = r0 + 8;
#pragma unroll
        for (int nt = 0; nt < NT; nt++) {
            int cc = bn + wn * NT * 8 + nt * 8 + tig * 2;
#pragma unroll
            for (int h = 0; h < 2; h++) {
                int rr = h ? r1 : r0;
                if (rr >= M) continue;
#pragma unroll
                for (int q = 0; q < 2; q++) {
                    int gn = cc + q;
                    if (gn >= N) continue;
                    float v = acc[mt][nt][h * 2 + q];
                    if (bias) v += bias[gn];
                    if (act) v = v > 0.f ? v : (expf(v) - 1.f);
                    C[(long)rr * N + gn] = v;
                }
            }
        }
    }
}

// instantiations
// large: 128x128 tile, 8 warps (2x4), each 64x32; min 2 CTAs/SM (regs<=128)
// small: 64x64 tile, 4 warps (2x2), each 32x32; min 4 CTAs/SM
#define SMEM_L (2 * 4 * 16 * (128 + 4) * 4)   // 67584
#define SMEM_S (2 * 4 * 16 * (64 + 4) * 4)    // 34816

// ---------------------------------------------------------------------------
// LSTM pointwise step: gate order i,f,g,o (torch).
// ---------------------------------------------------------------------------
__device__ __forceinline__ float sigf(float x) { return 1.f / (1.f + expf(-x)); }

__global__ void lstm_step_kernel(
    const float* __restrict__ xg, const float* __restrict__ hW,
    const float* __restrict__ bih, const float* __restrict__ bhh,
    float* __restrict__ h, float* __restrict__ c,
    int S, int t, int divA, int mulA, int mulB, int first)
{
    int idx = blockIdx.x * blockDim.x + threadIdx.x;
    if (idx >= S * E_DIM) return;
    int s = idx / E_DIM, e = idx % E_DIM;
    int xrow = (s / divA) * mulA + (s % divA) * mulB + t;
    const float* xr = xg + (long)xrow * G_DIM;

    float gi = xr[e]             + bih[e]             + bhh[e];
    float gf = xr[E_DIM + e]     + bih[E_DIM + e]     + bhh[E_DIM + e];
    float gg = xr[2 * E_DIM + e] + bih[2 * E_DIM + e] + bhh[2 * E_DIM + e];
    float go = xr[3 * E_DIM + e] + bih[3 * E_DIM + e] + bhh[3 * E_DIM + e];

    float cprev = 0.f;
    if (!first) {
        const float* hr = hW + (long)s * G_DIM;
        gi += hr[e]; gf += hr[E_DIM + e]; gg += hr[2 * E_DIM + e]; go += hr[3 * E_DIM + e];
        cprev = c[idx];
    }
    float cn = sigf(gf) * cprev + sigf(gi) * tanhf(gg);
    c[idx] = cn;
    h[idx] = sigf(go) * tanhf(cn);
}

// ---------------------------------------------------------------------------
__global__ void concat_kernel(
    const float* __restrict__ first, int firstB,
    const float* __restrict__ second, int secondB,
    float* __restrict__ cat, int rows)
{
    int idx = blockIdx.x * blockDim.x + threadIdx.x;
    if (idx >= rows * 2 * E_DIM) return;
    int r = idx / (2 * E_DIM), e = idx % (2 * E_DIM);
    float v;
    if (e < E_DIM) v = firstB  ? first[e]            : first[(long)r * E_DIM + e];
    else { int e2 = e - E_DIM; v = secondB ? second[e2] : second[(long)r * E_DIM + e2]; }
    cat[idx] = v;
}

// ---------------------------------------------------------------------------
__global__ void pred_kernel(const float* __restrict__ x, const float* __restrict__ w,
                            const float* __restrict__ b, float* __restrict__ out, int rows)
{
    int gwarp = (blockIdx.x * blockDim.x + threadIdx.x) >> 5;
    int lane = threadIdx.x & 31;
    if (gwarp >= rows) return;
    float s = 0.f;
    for (int e = lane; e < E_DIM; e += 32) s += x[(long)gwarp * E_DIM + e] * w[e];
#pragma unroll
    for (int o = 16; o; o >>= 1) s += __shfl_down_sync(0xffffffffu, s, o);
    if (lane == 0) out[gwarp] = s + b[0];
}

// ---------------------------------------------------------------------------
// host side
// ---------------------------------------------------------------------------
static inline void gemm(const float* A, const float* W, const float* bias, float* C,
                        int M, int N, int K, int act, int remap)
{
    int gL = ((N + 127) / 128) * ((M + 127) / 128);
    if (gL >= 96) {
        dim3 grid((N + 127) / 128, (M + 127) / 128);
        mma_gemm_t<128, 2, 4, 2><<<grid, 256, SMEM_L>>>(A, W, bias, C, M, N, K, act, remap);
    } else {
        dim3 grid((N + 63) / 64, (M + 63) / 64);
        mma_gemm_t<64, 2, 2, 4><<<grid, 128, SMEM_S>>>(A, W, bias, C, M, N, K, act, remap);
    }
}

extern "C" void kernel_launch(void* const* d_in, const int* in_sizes, int n_in,
                              void* d_out, int out_size)
{
    cudaFuncSetAttribute((const void*)mma_gemm_t<128, 2, 4, 2>,
                         cudaFuncAttributeMaxDynamicSharedMemorySize, SMEM_L);
    cudaFuncSetAttribute((const void*)mma_gemm_t<64, 2, 2, 4>,
                         cudaFuncAttributeMaxDynamicSharedMemorySize, SMEM_S);

    const float* ast    = (const float*)d_in[0];
    const float* ce_w0  = (const float*)d_in[1];  const float* ce_b0 = (const float*)d_in[2];
    const float* ce_w1  = (const float*)d_in[3];  const float* ce_b1 = (const float*)d_in[4];
    const float* ce_w2  = (const float*)d_in[5];  const float* ce_b2 = (const float*)d_in[6];
    const float* ce_w3  = (const float*)d_in[7];  const float* ce_b3 = (const float*)d_in[8];
    const float* cc_w0  = (const float*)d_in[9];  const float* cc_b0 = (const float*)d_in[10];
    const float* cc_w1  = (const float*)d_in[11]; const float* cc_b1 = (const float*)d_in[12];
    const float* rg_w0  = (const float*)d_in[13]; const float* rg_b0 = (const float*)d_in[14];
    const float* rg_w1  = (const float*)d_in[15]; const float* rg_b1 = (const float*)d_in[16];
    const float* pred_w = (const float*)d_in[17]; const float* pred_b = (const float*)d_in[18];
    const float* cl_Wih = (const float*)d_in[19]; const float* cl_Whh = (const float*)d_in[20];
    const float* cl_bih = (const float*)d_in[21]; const float* cl_bhh = (const float*)d_in[22];
    const float* nl_Wih = (const float*)d_in[23]; const float* nl_Whh = (const float*)d_in[24];
    const float* nl_bih = (const float*)d_in[25]; const float* nl_bhh = (const float*)d_in[26];
    const float* no_comps = (const float*)d_in[27];
    const float* no_nodes = (const float*)d_in[28];
    float* out = (float*)d_out;

    float* S0 = nullptr;
    cudaGetSymbolAddress((void**)&S0, g_scratch);

    float* emb0 = S0 + OFF_EMB0;  float* emb1 = S0 + OFF_EMB1;
    float* emb2 = S0 + OFF_EMB2;  float* embd = S0 + OFF_EMBD;
    float* xg   = S0 + OFF_XG;    float* xgm  = S0 + OFF_XGM;  float* xgr = S0 + OFF_XGR;
    float* hW   = S0 + OFF_HW;
    float* hA   = S0 + OFF_HA;    float* cA   = S0 + OFF_CA;
    float* cat  = S0 + OFF_CAT;   float* t200 = S0 + OFF_T200;
    float* leaf = S0 + OFF_LEAF;
    float* hM   = S0 + OFF_HM;    float* cM   = S0 + OFF_CM;   float* mido = S0 + OFF_MIDO;
    float* hR   = S0 + OFF_HR;    float* cR   = S0 + OFF_CR;
    float* prog = S0 + OFF_PROG;  float* r0   = S0 + OFF_R0;   float* r1  = S0 + OFF_R1;

    // ---- Phase A: comp-embedding MLP on the 48 used positions ----
    gemm(ast,  ce_w0, ce_b0, emb0, M_CE, 600, 1024, 1, 1);   // remap 48-of-64
    gemm(emb0, ce_w1, ce_b1, emb1, M_CE, 350, 600, 1, 0);
    gemm(emb1, ce_w2, ce_b2, emb2, M_CE, 200, 350, 1, 0);
    gemm(emb2, ce_w3, ce_b3, embd, M_CE, E_DIM, 200, 1, 0);

    // ---- Phase B: cl LSTM over 6 leaves x 8 steps (batched S=1536) ----
    gemm(embd, cl_Wih, nullptr, xg, M_CE, G_DIM, E_DIM, 0, 0);   // x-proj hoisted
    {
        int thr = S_CL * E_DIM;
        lstm_step_kernel<<<(thr + 255) / 256, 256>>>(xg, hW, cl_bih, cl_bhh, hA, cA,
                                                     S_CL, 0, 6, 48, 8, 1);
        for (int t = 1; t < 8; t++) {
            gemm(hA, cl_Whh, nullptr, hW, S_CL, G_DIM, E_DIM, 0, 0);
            lstm_step_kernel<<<(thr + 255) / 256, 256>>>(xg, hW, cl_bih, cl_bhh, hA, cA,
                                                         S_CL, t, 6, 48, 8, 0);
        }
    }

    // ---- Phase C: leaf concat block (nodes=no_nodes bcast, comps=h) ----
    {
        int thr = S_CL * 2 * E_DIM;
        concat_kernel<<<(thr + 255) / 256, 256>>>(no_nodes, 1, hA, 0, cat, S_CL);
        gemm(cat,  cc_w0, cc_b0, t200, S_CL, 200, 2 * E_DIM, 1, 0);
        gemm(t200, cc_w1, cc_b1, leaf, S_CL, E_DIM, 200, 1, 0);
    }

    // ---- Phase D: mid nl LSTM (S=768, T=2 over leaf pairs) ----
    gemm(leaf, nl_Wih, nullptr, xgm, S_CL, G_DIM, E_DIM, 0, 0);
    {
        int thr = S_MID * E_DIM;
        lstm_step_kernel<<<(thr + 255) / 256, 256>>>(xgm, hW, nl_bih, nl_bhh, hM, cM,
                                                     S_MID, 0, 3, 6, 2, 1);
        gemm(hM, nl_Whh, nullptr, hW, S_MID, G_DIM, E_DIM, 0, 0);
        lstm_step_kernel<<<(thr + 255) / 256, 256>>>(xgm, hW, nl_bih, nl_bhh, hM, cM,
                                                     S_MID, 1, 3, 6, 2, 0);
    }

    // ---- Phase E: mid concat block (nodes=h, comps=no_comps bcast) ----
    {
        int thr = S_MID * 2 * E_DIM;
        concat_kernel<<<(thr + 255) / 256, 256>>>(hM, 0, no_comps, 1, cat, S_MID);
        gemm(cat,  cc_w0, cc_b0, t200, S_MID, 200, 2 * E_DIM, 1, 0);
        gemm(t200, cc_w1, cc_b1, mido, S_MID, E_DIM, 200, 1, 0);
    }

    // ---- Phase F: root nl LSTM (S=256, T=3 over mids) ----
    gemm(mido, nl_Wih, nullptr, xgr, S_MID, G_DIM, E_DIM, 0, 0);
    {
        int thr = S_RT * E_DIM;
        lstm_step_kernel<<<(thr + 255) / 256, 256>>>(xgr, hW, nl_bih, nl_bhh, hR, cR,
                                                     S_RT, 0, 1, 3, 0, 1);
        for (int t = 1; t < 3; t++) {
            gemm(hR, nl_Whh, nullptr, hW, S_RT, G_DIM, E_DIM, 0, 0);
            lstm_step_kernel<<<(thr + 255) / 256, 256>>>(xgr, hW, nl_bih, nl_bhh, hR, cR,
                                                         S_RT, t, 1, 3, 0, 0);
        }
    }

    // ---- Phase G: root concat block ----
    {
        int thr = S_RT * 2 * E_DIM;
        concat_kernel<<<(thr + 255) / 256, 256>>>(hR, 0, no_comps, 1, cat, S_RT);
        gemm(cat,  cc_w0, cc_b0, t200, S_RT, 200, 2 * E_DIM, 1, 0);
        gemm(t200, cc_w1, cc_b1, prog, S_RT, E_DIM, 200, 1, 0);
    }

    // ---- Phase H: regression head ----
    gemm(prog, rg_w0, rg_b0, r0, S_RT, 200, E_DIM, 1, 0);
    gemm(r0,   rg_w1, rg_b1, r1, S_RT, E_DIM, 200, 1, 0);
    pred_kernel<<<(S_RT * 32 + 255) / 256, 256>>>(r1, pred_w, pred_b, out, S_RT);
}

// round 6
// speedup vs baseline: 1.8825x; 1.0453x over previous
#include <cuda_runtime.h>
#include <math.h>
#include <stdint.h>

// ---------------------------------------------------------------------------
// Model_Recursive_LSTM_v2 — 3xTF32 tensor-core GEMM, uint4-packed fragments
// B=256, L=64 (only 0..47 used), IN=1024, E=180
// ---------------------------------------------------------------------------

#define E_DIM 180
#define G_DIM 720          // 4*E
#define M_CE  12288        // 256 * 48 effective rows
#define S_CL  1536         // 256 * 6 leaf sequences
#define S_MID 768          // 256 * 3
#define S_RT  256

// ---- scratch layout (floats) ----
#define OFF_EMB0  0UL                    // 12288*600
#define OFF_EMB1  7372800UL              // 12288*350
#define OFF_EMB2  11673600UL             // 12288*200
#define OFF_EMBD  14131200UL             // 12288*180
#define OFF_XG    16343040UL             // 12288*720 (cl x-proj)
#define OFF_XGM   25190400UL             // 1536*720  (mid x-proj)
#define OFF_XGR   26296320UL             // 768*720   (root x-proj)
#define OFF_HW    26849280UL             // 1536*720  (h@Whh^T, reused)
#define OFF_HA    27955200UL             // 1536*180  (cl h)
#define OFF_CA    28231680UL             // 1536*180  (cl c)
#define OFF_CAT   28508160UL             // 1536*360
#define OFF_T200  29061120UL             // 1536*200
#define OFF_LEAF  29368320UL             // 1536*180
#define OFF_HM    29644800UL             // 768*180
#define OFF_CM    29783040UL             // 768*180
#define OFF_MIDO  29921280UL             // 768*180
#define OFF_HR    30059520UL             // 256*180
#define OFF_CR    30105600UL             // 256*180
#define OFF_PROG  30151680UL             // 256*180
#define OFF_R0    30197760UL             // 256*200
#define OFF_R1    30248960UL             // 256*180
#define SCRATCH_F 30295040UL

__device__ float g_scratch[SCRATCH_F];

__device__ __forceinline__ uint32_t f2tf32(float v) {
    uint32_t r;
    asm("cvt.rna.tf32.f32 %0, %1;" : "=r"(r) : "f"(v));
    return r;
}

__device__ __forceinline__ void mma_tf32(float* d, const uint32_t* a, const uint32_t* b) {
    asm volatile(
        "mma.sync.aligned.m16n8k8.row.col.f32.tf32.tf32.f32 "
        "{%0,%1,%2,%3}, {%4,%5,%6,%7}, {%8,%9}, {%0,%1,%2,%3};"
        : "+f"(d[0]), "+f"(d[1]), "+f"(d[2]), "+f"(d[3])
        : "r"(a[0]), "r"(a[1]), "r"(a[2]), "r"(a[3]),
          "r"(b[0]), "r"(b[1]));
}

extern __shared__ uint32_t dynsmem[];

// ---------------------------------------------------------------------------
// Templated 3xTF32 pipelined GEMM: C[M,N] = act( A[M,K] @ W[N,K]^T + bias )
// Smem layout: per row (m or n), 8 uint4 covering 16 k values:
//   uint4 j (ks=j>>2, t=j&3) = { hi[ks*8+t], lo[ks*8+t], hi[ks*8+t+4], lo[ks*8+t+4] }
// Row stride = 12 uint4 (48 words == 16 mod 32 banks -> paired rows disjoint).
// Fragment loads are single LDS.128 per (row, k-slice).
// remap!=0: logical A-row m maps to physical row (m/48)*64 + (m%48)
// ---------------------------------------------------------------------------
template <int BMT, int WMT, int WNT, int MINB>
__global__ __launch_bounds__(2 * BMT, MINB) void mma_gemm_t(
    const float* __restrict__ A, const float* __restrict__ W,
    const float* __restrict__ bias, float* __restrict__ C,
    int M, int N, int K, int act, int remap)
{
    constexpr int BNT = BMT;
    constexpr int MT = BMT / (WMT * 16);
    constexpr int NT = BNT / (WNT * 8);
    constexpr int RS = 12;                 // uint4 per row (8 data + 4 pad)
    constexpr int ARR_U4 = BMT * RS;       // one operand array
    constexpr int STAGE_U4 = 2 * ARR_U4;   // A + B

    uint4* smem4 = reinterpret_cast<uint4*>(dynsmem);

    const int tid  = threadIdx.x;
    const int warp = tid >> 5;
    const int lane = tid & 31;
    const int wm = warp % WMT;
    const int wn = warp / WMT;
    const int bm = blockIdx.y * BMT;
    const int bn = blockIdx.x * BNT;

    const int grp = lane >> 2;      // 0..7
    const int tig = lane & 3;       // 0..3

    float acc[MT][NT][4];
#pragma unroll
    for (int i = 0; i < MT; i++)
#pragma unroll
        for (int j = 0; j < NT; j++)
#pragma unroll
            for (int r = 0; r < 4; r++) acc[i][j][r] = 0.f;

    // global-load assignment: thread loads 8 consecutive k of one row
    const int arow = tid >> 1;
    const int akof = (tid & 1) * 8;        // ks*8
    const int j0   = (tid & 1) * 4;        // uint4 base index in row
    long abase = -1;
    {
        int gm = bm + arow;
        if (gm < M) {
            long r = remap ? ((long)(gm / 48) * 64 + (gm % 48)) : (long)gm;
            abase = r * (long)K;
        }
    }
    long bbase = (bn + arow < N) ? (long)(bn + arow) * K : -1;

    float ra[8], rb[8];

    // ---- prologue: load + convert + store slab 0 ----
    if (16 <= K) {
#pragma unroll
        for (int j = 0; j < 8; j++) {
            int gk = akof + j;
            ra[j] = (abase >= 0) ? A[abase + gk] : 0.f;
            rb[j] = (bbase >= 0) ? W[bbase + gk] : 0.f;
        }
    } else {
#pragma unroll
        for (int j = 0; j < 8; j++) {
            int gk = akof + j;
            ra[j] = (abase >= 0 && gk < K) ? A[abase + gk] : 0.f;
            rb[j] = (bbase >= 0 && gk < K) ? W[bbase + gk] : 0.f;
        }
    }
    {
        uint4* sA = smem4;
        uint4* sB = smem4 + ARR_U4;
#pragma unroll
        for (int t = 0; t < 4; t++) {
            uint32_t h0 = f2tf32(ra[t]);
            uint32_t l0 = f2tf32(ra[t] - __uint_as_float(h0));
            uint32_t h1 = f2tf32(ra[t + 4]);
            uint32_t l1 = f2tf32(ra[t + 4] - __uint_as_float(h1));
            sA[arow * RS + j0 + t] = make_uint4(h0, l0, h1, l1);
            h0 = f2tf32(rb[t]);
            l0 = f2tf32(rb[t] - __uint_as_float(h0));
            h1 = f2tf32(rb[t + 4]);
            l1 = f2tf32(rb[t + 4] - __uint_as_float(h1));
            sB[arow * RS + j0 + t] = make_uint4(h0, l0, h1, l1);
        }
    }
    __syncthreads();

    int cur = 0;
    for (int k0 = 0; k0 < K; k0 += 16) {
        const int nxt = k0 + 16;
        const bool has = nxt < K;

        if (has) {
            if (nxt + 16 <= K) {
#pragma unroll
                for (int j = 0; j < 8; j++) {
                    int gk = nxt + akof + j;
                    ra[j] = (abase >= 0) ? A[abase + gk] : 0.f;
                    rb[j] = (bbase >= 0) ? W[bbase + gk] : 0.f;
                }
            } else {
#pragma unroll
                for (int j = 0; j < 8; j++) {
                    int gk = nxt + akof + j;
                    ra[j] = (abase >= 0 && gk < K) ? A[abase + gk] : 0.f;
                    rb[j] = (bbase >= 0 && gk < K) ? W[bbase + gk] : 0.f;
                }
            }
        }

        // ---- compute current slab ----
        {
            const uint4* sA = smem4 + cur * STAGE_U4;
            const uint4* sB = sA + ARR_U4;
#pragma unroll
            for (int ks = 0; ks < 2; ks++) {
                const int cbase = ks * 4 + tig;
                uint32_t ah[MT][4], al[MT][4];
                uint32_t bh[NT][2], bl[NT][2];
#pragma unroll
                for (int mt = 0; mt < MT; mt++) {
                    int mr = wm * MT * 16 + mt * 16 + grp;
                    uint4 p0 = sA[mr * RS + cbase];
                    uint4 p1 = sA[(mr + 8) * RS + cbase];
                    ah[mt][0] = p0.x; ah[mt][1] = p1.x; ah[mt][2] = p0.z; ah[mt][3] = p1.z;
                    al[mt][0] = p0.y; al[mt][1] = p1.y; al[mt][2] = p0.w; al[mt][3] = p1.w;
                }
#pragma unroll
                for (int nt = 0; nt < NT; nt++) {
                    int nc = wn * NT * 8 + nt * 8 + grp;
                    uint4 q = sB[nc * RS + cbase];
                    bh[nt][0] = q.x; bh[nt][1] = q.z;
                    bl[nt][0] = q.y; bl[nt][1] = q.w;
                }
#pragma unroll
                for (int mt = 0; mt < MT; mt++)
#pragma unroll
                    for (int nt = 0; nt < NT; nt++) {
                        mma_tf32(acc[mt][nt], ah[mt], bl[nt]);  // hi*lo
                        mma_tf32(acc[mt][nt], al[mt], bh[nt]);  // lo*hi
                        mma_tf32(acc[mt][nt], ah[mt], bh[nt]);  // hi*hi
                    }
            }
        }

        // ---- convert + store next slab into the other buffer ----
        if (has) {
            uint4* sA = smem4 + (cur ^ 1) * STAGE_U4;
            uint4* sB = sA + ARR_U4;
#pragma unroll
            for (int t = 0; t < 4; t++) {
                uint32_t h0 = f2tf32(ra[t]);
                uint32_t l0 = f2tf32(ra[t] - __uint_as_float(h0));
                uint32_t h1 = f2tf32(ra[t + 4]);
                uint32_t l1 = f2tf32(ra[t + 4] - __uint_as_float(h1));
                sA[arow * RS + j0 + t] = make_uint4(h0, l0, h1, l1);
                h0 = f2tf32(rb[t]);
                l0 = f2tf32(rb[t] - __uint_as_float(h0));
                h1 = f2tf32(rb[t + 4]);
                l1 = f2tf32(rb[t + 4] - __uint_as_float(h1));
                sB[arow * RS + j0 + t] = make_uint4(h0, l0, h1, l1);
            }
        }
        __syncthreads();
        cur ^= 1;
    }

    // ---- epilogue: bias + ELU + store ----
#pragma unroll
    for (int mt = 0; mt < MT; mt++) {
        int r0 = bm + wm * MT * 16 + mt * 16 + grp;
        int r1 = r0 + 8;
#pragma unroll
        for (int nt = 0; nt < NT; nt++) {
            int cc = bn + wn * NT * 8 + nt * 8 + tig * 2;
#pragma unroll
            for (int h = 0; h < 2; h++) {
                int rr = h ? r1 : r0;
                if (rr >= M) continue;
#pragma unroll
                for (int q = 0; q < 2; q++) {
                    int gn = cc + q;
                    if (gn >= N) continue;
                    float v = acc[mt][nt][h * 2 + q];
                    if (bias) v += bias[gn];
                    if (act) v = v > 0.f ? v : (expf(v) - 1.f);
                    C[(long)rr * N + gn] = v;
                }
            }
        }
    }
}

// smem sizes: 2 stages * 2 arrays * BMT rows * 12 uint4 * 16 B
#define SMEM_L (2 * 2 * 128 * 12 * 16)   // 98304
#define SMEM_S (2 * 2 * 64 * 12 * 16)    // 49152

// ---------------------------------------------------------------------------
// LSTM pointwise step: gate order i,f,g,o (torch).
// ---------------------------------------------------------------------------
__device__ __forceinline__ float sigf(float x) { return 1.f / (1.f + expf(-x)); }

__global__ void lstm_step_kernel(
    const float* __restrict__ xg, const float* __restrict__ hW,
    const float* __restrict__ bih, const float* __restrict__ bhh,
    float* __restrict__ h, float* __restrict__ c,
    int S, int t, int divA, int mulA, int mulB, int first)
{
    int idx = blockIdx.x * blockDim.x + threadIdx.x;
    if (idx >= S * E_DIM) return;
    int s = idx / E_DIM, e = idx % E_DIM;
    int xrow = (s / divA) * mulA + (s % divA) * mulB + t;
    const float* xr = xg + (long)xrow * G_DIM;

    float gi = xr[e]             + bih[e]             + bhh[e];
    float gf = xr[E_DIM + e]     + bih[E_DIM + e]     + bhh[E_DIM + e];
    float gg = xr[2 * E_DIM + e] + bih[2 * E_DIM + e] + bhh[2 * E_DIM + e];
    float go = xr[3 * E_DIM + e] + bih[3 * E_DIM + e] + bhh[3 * E_DIM + e];

    float cprev = 0.f;
    if (!first) {
        const float* hr = hW + (long)s * G_DIM;
        gi += hr[e]; gf += hr[E_DIM + e]; gg += hr[2 * E_DIM + e]; go += hr[3 * E_DIM + e];
        cprev = c[idx];
    }
    float cn = sigf(gf) * cprev + sigf(gi) * tanhf(gg);
    c[idx] = cn;
    h[idx] = sigf(go) * tanhf(cn);
}

// ---------------------------------------------------------------------------
__global__ void concat_kernel(
    const float* __restrict__ first, int firstB,
    const float* __restrict__ second, int secondB,
    float* __restrict__ cat, int rows)
{
    int idx = blockIdx.x * blockDim.x + threadIdx.x;
    if (idx >= rows * 2 * E_DIM) return;
    int r = idx / (2 * E_DIM), e = idx % (2 * E_DIM);
    float v;
    if (e < E_DIM) v = firstB  ? first[e]            : first[(long)r * E_DIM + e];
    else { int e2 = e - E_DIM; v = secondB ? second[e2] : second[(long)r * E_DIM + e2]; }
    cat[idx] = v;
}

// ---------------------------------------------------------------------------
__global__ void pred_kernel(const float* __restrict__ x, const float* __restrict__ w,
                            const float* __restrict__ b, float* __restrict__ out, int rows)
{
    int gwarp = (blockIdx.x * blockDim.x + threadIdx.x) >> 5;
    int lane = threadIdx.x & 31;
    if (gwarp >= rows) return;
    float s = 0.f;
    for (int e = lane; e < E_DIM; e += 32) s += x[(long)gwarp * E_DIM + e] * w[e];
#pragma unroll
    for (int o = 16; o; o >>= 1) s += __shfl_down_sync(0xffffffffu, s, o);
    if (lane == 0) out[gwarp] = s + b[0];
}

// ---------------------------------------------------------------------------
// host side
// ---------------------------------------------------------------------------
static inline void gemm(const float* A, const float* W, const float* bias, float* C,
                        int M, int N, int K, int act, int remap)
{
    int gL = ((N + 127) / 128) * ((M + 127) / 128);
    if (gL >= 96) {
        dim3 grid((N + 127) / 128, (M + 127) / 128);
        mma_gemm_t<128, 2, 4, 2><<<grid, 256, SMEM_L>>>(A, W, bias, C, M, N, K, act, remap);
    } else {
        dim3 grid((N + 63) / 64, (M + 63) / 64);
        mma_gemm_t<64, 2, 2, 4><<<grid, 128, SMEM_S>>>(A, W, bias, C, M, N, K, act, remap);
    }
}

extern "C" void kernel_launch(void* const* d_in, const int* in_sizes, int n_in,
                              void* d_out, int out_size)
{
    cudaFuncSetAttribute((const void*)mma_gemm_t<128, 2, 4, 2>,
                         cudaFuncAttributeMaxDynamicSharedMemorySize, SMEM_L);
    cudaFuncSetAttribute((const void*)mma_gemm_t<64, 2, 2, 4>,
                         cudaFuncAttributeMaxDynamicSharedMemorySize, SMEM_S);

    const float* ast    = (const float*)d_in[0];
    const float* ce_w0  = (const float*)d_in[1];  const float* ce_b0 = (const float*)d_in[2];
    const float* ce_w1  = (const float*)d_in[3];  const float* ce_b1 = (const float*)d_in[4];
    const float* ce_w2  = (const float*)d_in[5];  const float* ce_b2 = (const float*)d_in[6];
    const float* ce_w3  = (const float*)d_in[7];  const float* ce_b3 = (const float*)d_in[8];
    const float* cc_w0  = (const float*)d_in[9];  const float* cc_b0 = (const float*)d_in[10];
    const float* cc_w1  = (const float*)d_in[11]; const float* cc_b1 = (const float*)d_in[12];
    const float* rg_w0  = (const float*)d_in[13]; const float* rg_b0 = (const float*)d_in[14];
    const float* rg_w1  = (const float*)d_in[15]; const float* rg_b1 = (const float*)d_in[16];
    const float* pred_w = (const float*)d_in[17]; const float* pred_b = (const float*)d_in[18];
    const float* cl_Wih = (const float*)d_in[19]; const float* cl_Whh = (const float*)d_in[20];
    const float* cl_bih = (const float*)d_in[21]; const float* cl_bhh = (const float*)d_in[22];
    const float* nl_Wih = (const float*)d_in[23]; const float* nl_Whh = (const float*)d_in[24];
    const float* nl_bih = (const float*)d_in[25]; const float* nl_bhh = (const float*)d_in[26];
    const float* no_comps = (const float*)d_in[27];
    const float* no_nodes = (const float*)d_in[28];
    float* out = (float*)d_out;

    float* S0 = nullptr;
    cudaGetSymbolAddress((void**)&S0, g_scratch);

    float* emb0 = S0 + OFF_EMB0;  float* emb1 = S0 + OFF_EMB1;
    float* emb2 = S0 + OFF_EMB2;  float* embd = S0 + OFF_EMBD;
    float* xg   = S0 + OFF_XG;    float* xgm  = S0 + OFF_XGM;  float* xgr = S0 + OFF_XGR;
    float* hW   = S0 + OFF_HW;
    float* hA   = S0 + OFF_HA;    float* cA   = S0 + OFF_CA;
    float* cat  = S0 + OFF_CAT;   float* t200 = S0 + OFF_T200;
    float* leaf = S0 + OFF_LEAF;
    float* hM   = S0 + OFF_HM;    float* cM   = S0 + OFF_CM;   float* mido = S0 + OFF_MIDO;
    float* hR   = S0 + OFF_HR;    float* cR   = S0 + OFF_CR;
    float* prog = S0 + OFF_PROG;  float* r0   = S0 + OFF_R0;   float* r1  = S0 + OFF_R1;

    // ---- Phase A: comp-embedding MLP on the 48 used positions ----
    gemm(ast,  ce_w0, ce_b0, emb0, M_CE, 600, 1024, 1, 1);   // remap 48-of-64
    gemm(emb0, ce_w1, ce_b1, emb1, M_CE, 350, 600, 1, 0);
    gemm(emb1, ce_w2, ce_b2, emb2, M_CE, 200, 350, 1, 0);
    gemm(emb2, ce_w3, ce_b3, embd, M_CE, E_DIM, 200, 1, 0);

    // ---- Phase B: cl LSTM over 6 leaves x 8 steps (batched S=1536) ----
    gemm(embd, cl_Wih, nullptr, xg, M_CE, G_DIM, E_DIM, 0, 0);   // x-proj hoisted
    {
        int thr = S_CL * E_DIM;
        lstm_step_kernel<<<(thr + 255) / 256, 256>>>(xg, hW, cl_bih, cl_bhh, hA, cA,
                                                     S_CL, 0, 6, 48, 8, 1);
        for (int t = 1; t < 8; t++) {
            gemm(hA, cl_Whh, nullptr, hW, S_CL, G_DIM, E_DIM, 0, 0);
            lstm_step_kernel<<<(thr + 255) / 256, 256>>>(xg, hW, cl_bih, cl_bhh, hA, cA,
                                                         S_CL, t, 6, 48, 8, 0);
        }
    }

    // ---- Phase C: leaf concat block (nodes=no_nodes bcast, comps=h) ----
    {
        int thr = S_CL * 2 * E_DIM;
        concat_kernel<<<(thr + 255) / 256, 256>>>(no_nodes, 1, hA, 0, cat, S_CL);
        gemm(cat,  cc_w0, cc_b0, t200, S_CL, 200, 2 * E_DIM, 1, 0);
        gemm(t200, cc_w1, cc_b1, leaf, S_CL, E_DIM, 200, 1, 0);
    }

    // ---- Phase D: mid nl LSTM (S=768, T=2 over leaf pairs) ----
    gemm(leaf, nl_Wih, nullptr, xgm, S_CL, G_DIM, E_DIM, 0, 0);
    {
        int thr = S_MID * E_DIM;
        lstm_step_kernel<<<(thr + 255) / 256, 256>>>(xgm, hW, nl_bih, nl_bhh, hM, cM,
                                                     S_MID, 0, 3, 6, 2, 1);
        gemm(hM, nl_Whh, nullptr, hW, S_MID, G_DIM, E_DIM, 0, 0);
        lstm_step_kernel<<<(thr + 255) / 256, 256>>>(xgm, hW, nl_bih, nl_bhh, hM, cM,
                                                     S_MID, 1, 3, 6, 2, 0);
    }

    // ---- Phase E: mid concat block (nodes=h, comps=no_comps bcast) ----
    {
        int thr = S_MID * 2 * E_DIM;
        concat_kernel<<<(thr + 255) / 256, 256>>>(hM, 0, no_comps, 1, cat, S_MID);
        gemm(cat,  cc_w0, cc_b0, t200, S_MID, 200, 2 * E_DIM, 1, 0);
        gemm(t200, cc_w1, cc_b1, mido, S_MID, E_DIM, 200, 1, 0);
    }

    // ---- Phase F: root nl LSTM (S=256, T=3 over mids) ----
    gemm(mido, nl_Wih, nullptr, xgr, S_MID, G_DIM, E_DIM, 0, 0);
    {
        int thr = S_RT * E_DIM;
        lstm_step_kernel<<<(thr + 255) / 256, 256>>>(xgr, hW, nl_bih, nl_bhh, hR, cR,
                                                     S_RT, 0, 1, 3, 0, 1);
        for (int t = 1; t < 3; t++) {
            gemm(hR, nl_Whh, nullptr, hW, S_RT, G_DIM, E_DIM, 0, 0);
            lstm_step_kernel<<<(thr + 255) / 256, 256>>>(xgr, hW, nl_bih, nl_bhh, hR, cR,
                                                         S_RT, t, 1, 3, 0, 0);
        }
    }

    // ---- Phase G: root concat block ----
    {
        int thr = S_RT * 2 * E_DIM;
        concat_kernel<<<(thr + 255) / 256, 256>>>(hR, 0, no_comps, 1, cat, S_RT);
        gemm(cat,  cc_w0, cc_b0, t200, S_RT, 200, 2 * E_DIM, 1, 0);
        gemm(t200, cc_w1, cc_b1, prog, S_RT, E_DIM, 200, 1, 0);
    }

    // ---- Phase H: regression head ----
    gemm(prog, rg_w0, rg_b0, r0, S_RT, 200, E_DIM, 1, 0);
    gemm(r0,   rg_w1, rg_b1, r1, S_RT, E_DIM, 200, 1, 0);
    pred_kernel<<<(S_RT * 32 + 255) / 256, 256>>>(r1, pred_w, pred_b, out, S_RT);
}

// round 7
// speedup vs baseline: 1.8828x; 1.0002x over previous
#include <cuda_runtime.h>
#include <math.h>
#include <stdint.h>

// ---------------------------------------------------------------------------
// Model_Recursive_LSTM_v2 — 3xTF32 tensor-core GEMM with pre-packed (hi,lo)
// operands. B=256, L=64 (only 0..47 used), IN=1024, E=180
//
// Packed layout: per row, k in groups of 8, stored as uint2 (hi,lo) pairs in
// order [e0,e4,e1,e5,e2,e6,e3,e7]; K padded to multiple of 16 with zeros.
// This matches the smem fragment layout exactly -> GEMM mainloop is pure
// LDG.128 -> STS.128, no conversion math.
// ---------------------------------------------------------------------------

#define E_DIM 180
#define G_DIM 720
#define M_CE  12288
#define S_CL  1536
#define S_MID 768
#define S_RT  256

// ---- scratch layout (float units; all offsets multiple of 4) ----
#define OFF_ASTP  0UL            // 12288x1024 u2
#define OFF_E0P   25165824UL     // 12288x608 u2
#define OFF_E1P   40108032UL     // 12288x352 u2
#define OFF_E2P   48758784UL     // 12288x208 u2
#define OFF_EDP   53870592UL     // 12288x192 u2
#define OFF_XG    58589184UL     // 12288x720 f32
#define OFF_HW    67436544UL     // 1536x720 f32
#define OFF_HAP   68542464UL     // 1536x192 u2
#define OFF_CA    69132288UL     // 1536x180 f32
#define OFF_CATP  69408768UL     // 1536x368 u2
#define OFF_T2P   70539264UL     // 1536x208 u2
#define OFF_LFP   71178240UL     // 1536x192 u2
#define OFF_XGM   71768064UL     // 1536x720 f32
#define OFF_HMP   72873984UL     // 768x192 u2
#define OFF_CM    73168896UL     // 768x180 f32
#define OFF_MDP   73307136UL     // 768x192 u2
#define OFF_XGR   73602048UL     // 768x720 f32
#define OFF_HRP   74155008UL     // 256x192 u2
#define OFF_CR    74253312UL     // 256x180 f32
#define OFF_PGP   74299392UL     // 256x192 u2
#define OFF_R0P   74397696UL     // 256x208 u2
#define OFF_R1    74504192UL     // 256x180 f32
#define OFF_W0P   74550272UL     // 600x1024 u2
#define OFF_W1P   75779072UL     // 350x608 u2
#define OFF_W2P   76204672UL     // 200x352 u2
#define OFF_W3P   76345472UL     // 180x208 u2
#define OFF_CW0P  76420352UL     // 200x368 u2
#define OFF_CW1P  76567552UL     // 180x208 u2
#define OFF_RW0P  76642432UL     // 200x192 u2
#define OFF_RW1P  76719232UL     // 180x208 u2
#define OFF_CLIP  76794112UL     // 720x192 u2
#define OFF_CLHP  77070592UL     // 720x192 u2
#define OFF_NLIP  77347072UL     // 720x192 u2
#define OFF_NLHP  77623552UL     // 720x192 u2
#define OFF_NCP   77900032UL     // 1x192 u2
#define OFF_NNP   77900416UL     // 1x192 u2
#define SCRATCH_F 77900800UL

__device__ float4 g_scratch4[SCRATCH_F / 4];

__device__ __forceinline__ uint32_t f2tf32(float v) {
    uint32_t r;
    asm("cvt.rna.tf32.f32 %0, %1;" : "=r"(r) : "f"(v));
    return r;
}

__device__ __forceinline__ int pslot(int g) { return g < 4 ? 2 * g : 2 * (g - 4) + 1; }
// packed u2 index within a row of width Kp
__device__ __forceinline__ long pidx(long row, int k, int Kp) {
    return row * Kp + (k >> 3) * 8 + pslot(k & 7);
}

__device__ __forceinline__ void mma_tf32(float* d, const uint32_t* a, const uint32_t* b) {
    asm volatile(
        "mma.sync.aligned.m16n8k8.row.col.f32.tf32.tf32.f32 "
        "{%0,%1,%2,%3}, {%4,%5,%6,%7}, {%8,%9}, {%0,%1,%2,%3};"
        : "+f"(d[0]), "+f"(d[1]), "+f"(d[2]), "+f"(d[3])
        : "r"(a[0]), "r"(a[1]), "r"(a[2]), "r"(a[3]),
          "r"(b[0]), "r"(b[1]));
}

extern __shared__ uint32_t dynsmem[];

// ---------------------------------------------------------------------------
// Packed-operand 3xTF32 GEMM: C[M,N] = act( A @ W^T + bias )
// A: packed u2 [M x Kp], W: packed u2 [N x Kp] (rows >= N guarded to zero).
// Npck > 0: write packed u2 C [M x Npck] (cols N..Npck zero).
// Npck == 0: write fp32 C [M x N].
// M must be a multiple of BMT (true for all call sites).
// ---------------------------------------------------------------------------
template <int BMT, int WMT, int WNT, int MINB>
__global__ __launch_bounds__(2 * BMT, MINB) void mma_gemm_p(
    const uint4* __restrict__ Ap, const uint4* __restrict__ Wp,
    const float* __restrict__ bias, void* __restrict__ Cout,
    int M, int N, int Kp, int act, int Npck)
{
    constexpr int BNT = BMT;
    constexpr int MT = BMT / (WMT * 16);
    constexpr int NT = BNT / (WNT * 8);
    constexpr int RS = 12;                 // uint4 per row (8 data + 4 pad)
    constexpr int ARR_U4 = BMT * RS;
    constexpr int STAGE_U4 = 2 * ARR_U4;

    uint4* smem4 = reinterpret_cast<uint4*>(dynsmem);

    const int tid  = threadIdx.x;
    const int warp = tid >> 5;
    const int lane = tid & 31;
    const int wm = warp % WMT;
    const int wn = warp / WMT;
    const int bm = blockIdx.y * BMT;
    const int bn = blockIdx.x * BNT;

    const int grp = lane >> 2;
    const int tig = lane & 3;

    float acc[MT][NT][4];
#pragma unroll
    for (int i = 0; i < MT; i++)
#pragma unroll
        for (int j = 0; j < NT; j++)
#pragma unroll
            for (int r = 0; r < 4; r++) acc[i][j][r] = 0.f;

    // per-thread global load: 4 consecutive uint4 (8 packed elements = 16 k)
    const int arow = tid >> 1;
    const int j0   = (tid & 1) * 4;
    const long rowU4 = (long)(Kp >> 1);          // uint4 per packed row
    const long aBase = (long)(bm + arow) * rowU4;
    const bool bValid = (bn + arow) < N;
    const long bBase = bValid ? (long)(bn + arow) * rowU4 : 0;
    const uint4 zero4 = make_uint4(0, 0, 0, 0);

    uint4 ra[4], rb[4];

    // prologue: slab 0
#pragma unroll
    for (int t = 0; t < 4; t++) {
        ra[t] = Ap[aBase + j0 + t];
        rb[t] = bValid ? Wp[bBase + j0 + t] : zero4;
    }
    {
        uint4* sA = smem4;
        uint4* sB = smem4 + ARR_U4;
#pragma unroll
        for (int t = 0; t < 4; t++) {
            sA[arow * RS + j0 + t] = ra[t];
            sB[arow * RS + j0 + t] = rb[t];
        }
    }
    __syncthreads();

    int cur = 0;
    for (int k0 = 0; k0 < Kp; k0 += 16) {
        const int nxt = k0 + 16;
        const bool has = nxt < Kp;

        if (has) {
            const long kb = (long)(nxt >> 1);
#pragma unroll
            for (int t = 0; t < 4; t++) {
                ra[t] = Ap[aBase + kb + j0 + t];
                rb[t] = bValid ? Wp[bBase + kb + j0 + t] : zero4;
            }
        }

        // compute current slab
        {
            const uint4* sA = smem4 + cur * STAGE_U4;
            const uint4* sB = sA + ARR_U4;
#pragma unroll
            for (int ks = 0; ks < 2; ks++) {
                const int cbase = ks * 4 + tig;
                uint32_t ah[MT][4], al[MT][4];
                uint32_t bh[NT][2], bl[NT][2];
#pragma unroll
                for (int mt = 0; mt < MT; mt++) {
                    int mr = wm * MT * 16 + mt * 16 + grp;
                    uint4 p0 = sA[mr * RS + cbase];
                    uint4 p1 = sA[(mr + 8) * RS + cbase];
                    ah[mt][0] = p0.x; ah[mt][1] = p1.x; ah[mt][2] = p0.z; ah[mt][3] = p1.z;
                    al[mt][0] = p0.y; al[mt][1] = p1.y; al[mt][2] = p0.w; al[mt][3] = p1.w;
                }
#pragma unroll
                for (int nt = 0; nt < NT; nt++) {
                    int nc = wn * NT * 8 + nt * 8 + grp;
                    uint4 q = sB[nc * RS + cbase];
                    bh[nt][0] = q.x; bh[nt][1] = q.z;
                    bl[nt][0] = q.y; bl[nt][1] = q.w;
                }
#pragma unroll
                for (int mt = 0; mt < MT; mt++)
#pragma unroll
                    for (int nt = 0; nt < NT; nt++) {
                        mma_tf32(acc[mt][nt], ah[mt], bl[nt]);
                        mma_tf32(acc[mt][nt], al[mt], bh[nt]);
                        mma_tf32(acc[mt][nt], ah[mt], bh[nt]);
                    }
            }
        }

        if (has) {
            uint4* sA = smem4 + (cur ^ 1) * STAGE_U4;
            uint4* sB = sA + ARR_U4;
#pragma unroll
            for (int t = 0; t < 4; t++) {
                sA[arow * RS + j0 + t] = ra[t];
                sB[arow * RS + j0 + t] = rb[t];
            }
        }
        __syncthreads();
        cur ^= 1;
    }

    // epilogue
    float* Cf = (float*)Cout;
    uint2* Cp = (uint2*)Cout;
#pragma unroll
    for (int mt = 0; mt < MT; mt++) {
        int r0 = bm + wm * MT * 16 + mt * 16 + grp;
        int r1 = r0 + 8;
#pragma unroll
        for (int nt = 0; nt < NT; nt++) {
            int cc = bn + wn * NT * 8 + nt * 8 + tig * 2;
#pragma unroll
            for (int h = 0; h < 2; h++) {
                int rr = h ? r1 : r0;
#pragma unroll
                for (int q = 0; q < 2; q++) {
                    int gn = cc + q;
                    if (Npck > 0) {
                        if (gn >= Npck) continue;
                        float v = 0.f;
                        if (gn < N) {
                            v = acc[mt][nt][h * 2 + q];
                            if (bias) v += bias[gn];
                            if (act) v = v > 0.f ? v : (expf(v) - 1.f);
                        }
                        uint32_t hi = f2tf32(v);
                        uint32_t lo = f2tf32(v - __uint_as_float(hi));
                        Cp[pidx((long)rr, gn, Npck)] = make_uint2(hi, lo);
                    } else {
                        if (gn >= N) continue;
                        float v = acc[mt][nt][h * 2 + q];
                        if (bias) v += bias[gn];
                        if (act) v = v > 0.f ? v : (expf(v) - 1.f);
                        Cf[(long)rr * N + gn] = v;
                    }
                }
            }
        }
    }
}

#define SMEM_L (2 * 2 * 128 * 12 * 16)   // 98304
#define SMEM_S (2 * 2 * 64 * 12 * 16)    // 36864... (64*12*16*4 = 49152/... ) actually 2*2*64*12*16 = 49152

// ---------------------------------------------------------------------------
// Pack kernels: fp32 -> (hi,lo) permuted+padded layout
// ---------------------------------------------------------------------------
#define NPACK 14
struct PackTable {
    const float* src[NPACK];
    float* dst[NPACK];
    int rows[NPACK];
    int K[NPACK];
    int Kp[NPACK];
};

__global__ void pack_many_kernel(PackTable pt) {
    int which = blockIdx.y;
    int rows = pt.rows[which], K = pt.K[which], Kp = pt.Kp[which];
    long n = (long)rows * Kp;
    long idx = (long)blockIdx.x * blockDim.x + threadIdx.x;
    if (idx >= n) return;
    int r = (int)(idx / Kp);
    int k = (int)(idx % Kp);
    float v = (k < K) ? pt.src[which][(long)r * K + k] : 0.f;
    uint32_t hi = f2tf32(v);
    uint32_t lo = f2tf32(v - __uint_as_float(hi));
    ((uint2*)pt.dst[which])[pidx((long)r, k, Kp)] = make_uint2(hi, lo);
}

// ast pack with 48-of-64 row gather; K=1024 (no pad)
__global__ void pack_ast_kernel(const float* __restrict__ src, uint2* __restrict__ dst) {
    long idx = (long)blockIdx.x * blockDim.x + threadIdx.x;
    if (idx >= (long)M_CE * 1024) return;
    int m = (int)(idx / 1024);
    int k = (int)(idx % 1024);
    long phys = (long)(m / 48) * 64 + (m % 48);
    float v = src[phys * 1024 + k];
    uint32_t hi = f2tf32(v);
    uint32_t lo = f2tf32(v - __uint_as_float(hi));
    dst[pidx((long)m, k, 1024)] = make_uint2(hi, lo);
}

// ---------------------------------------------------------------------------
// LSTM pointwise step; writes h in packed layout (width 192)
// ---------------------------------------------------------------------------
__device__ __forceinline__ float sigf(float x) { return 1.f / (1.f + expf(-x)); }

__global__ void lstm_step_kernel(
    const float* __restrict__ xg, const float* __restrict__ hW,
    const float* __restrict__ bih, const float* __restrict__ bhh,
    uint2* __restrict__ hP, float* __restrict__ c,
    int S, int t, int divA, int mulA, int mulB, int first)
{
    int idx = blockIdx.x * blockDim.x + threadIdx.x;
    if (idx >= S * 192) return;
    int s = idx / 192, e = idx % 192;
    if (e >= E_DIM) {
        hP[pidx((long)s, e, 192)] = make_uint2(0, 0);
        return;
    }
    int xrow = (s / divA) * mulA + (s % divA) * mulB + t;
    const float* xr = xg + (long)xrow * G_DIM;

    float gi = xr[e]             + bih[e]             + bhh[e];
    float gf = xr[E_DIM + e]     + bih[E_DIM + e]     + bhh[E_DIM + e];
    float gg = xr[2 * E_DIM + e] + bih[2 * E_DIM + e] + bhh[2 * E_DIM + e];
    float go = xr[3 * E_DIM + e] + bih[3 * E_DIM + e] + bhh[3 * E_DIM + e];

    float cprev = 0.f;
    if (!first) {
        const float* hr = hW + (long)s * G_DIM;
        gi += hr[e]; gf += hr[E_DIM + e]; gg += hr[2 * E_DIM + e]; go += hr[3 * E_DIM + e];
        cprev = c[s * E_DIM + e];
    }
    float cn = sigf(gf) * cprev + sigf(gi) * tanhf(gg);
    c[s * E_DIM + e] = cn;
    float hv = sigf(go) * tanhf(cn);
    uint32_t hi = f2tf32(hv);
    uint32_t lo = f2tf32(hv - __uint_as_float(hi));
    hP[pidx((long)s, e, 192)] = make_uint2(hi, lo);
}

// ---------------------------------------------------------------------------
// Concat (packed -> packed, width 368). firstB/secondB: broadcast row 0.
// ---------------------------------------------------------------------------
__global__ void concat_kernel(
    const uint2* __restrict__ first, int firstB,
    const uint2* __restrict__ second, int secondB,
    uint2* __restrict__ cat, int rows)
{
    int idx = blockIdx.x * blockDim.x + threadIdx.x;
    if (idx >= rows * 368) return;
    int r = idx / 368, j = idx % 368;
    uint2 v = make_uint2(0, 0);
    if (j < E_DIM) {
        long sr = firstB ? 0 : (long)r;
        v = first[pidx(sr, j, 192)];
    } else if (j < 2 * E_DIM) {
        int i = j - E_DIM;
        long sr = secondB ? 0 : (long)r;
        v = second[pidx(sr, i, 192)];
    }
    cat[pidx((long)r, j, 368)] = v;
}

// ---------------------------------------------------------------------------
__global__ void pred_kernel(const float* __restrict__ x, const float* __restrict__ w,
                            const float* __restrict__ b, float* __restrict__ out, int rows)
{
    int gwarp = (blockIdx.x * blockDim.x + threadIdx.x) >> 5;
    int lane = threadIdx.x & 31;
    if (gwarp >= rows) return;
    float s = 0.f;
    for (int e = lane; e < E_DIM; e += 32) s += x[(long)gwarp * E_DIM + e] * w[e];
#pragma unroll
    for (int o = 16; o; o >>= 1) s += __shfl_down_sync(0xffffffffu, s, o);
    if (lane == 0) out[gwarp] = s + b[0];
}

// ---------------------------------------------------------------------------
// host side
// ---------------------------------------------------------------------------
static inline void gemm(const float* Ap, const float* Wp, const float* bias, void* C,
                        int M, int N, int Kp, int act, int Npck)
{
    int NN = (Npck > N) ? Npck : N;
    int gL = ((NN + 127) / 128) * ((M + 127) / 128);
    if (gL >= 96) {
        dim3 grid((NN + 127) / 128, (M + 127) / 128);
        mma_gemm_p<128, 2, 4, 2><<<grid, 256, SMEM_L>>>(
            (const uint4*)Ap, (const uint4*)Wp, bias, C, M, N, Kp, act, Npck);
    } else {
        dim3 grid((NN + 63) / 64, (M + 63) / 64);
        mma_gemm_p<64, 2, 2, 4><<<grid, SMEM_S ? 128 : 128, 2 * 2 * 64 * 12 * 16>>>(
            (const uint4*)Ap, (const uint4*)Wp, bias, C, M, N, Kp, act, Npck);
    }
}

extern "C" void kernel_launch(void* const* d_in, const int* in_sizes, int n_in,
                              void* d_out, int out_size)
{
    cudaFuncSetAttribute((const void*)mma_gemm_p<128, 2, 4, 2>,
                         cudaFuncAttributeMaxDynamicSharedMemorySize, SMEM_L);
    cudaFuncSetAttribute((const void*)mma_gemm_p<64, 2, 2, 4>,
                         cudaFuncAttributeMaxDynamicSharedMemorySize, 2 * 2 * 64 * 12 * 16);

    const float* ast    = (const float*)d_in[0];
    const float* ce_w0  = (const float*)d_in[1];  const float* ce_b0 = (const float*)d_in[2];
    const float* ce_w1  = (const float*)d_in[3];  const float* ce_b1 = (const float*)d_in[4];
    const float* ce_w2  = (const float*)d_in[5];  const float* ce_b2 = (const float*)d_in[6];
    const float* ce_w3  = (const float*)d_in[7];  const float* ce_b3 = (const float*)d_in[8];
    const float* cc_w0  = (const float*)d_in[9];  const float* cc_b0 = (const float*)d_in[10];
    const float* cc_w1  = (const float*)d_in[11]; const float* cc_b1 = (const float*)d_in[12];
    const float* rg_w0  = (const float*)d_in[13]; const float* rg_b0 = (const float*)d_in[14];
    const float* rg_w1  = (const float*)d_in[15]; const float* rg_b1 = (const float*)d_in[16];
    const float* pred_w = (const float*)d_in[17]; const float* pred_b = (const float*)d_in[18];
    const float* cl_Wih = (const float*)d_in[19]; const float* cl_Whh = (const float*)d_in[20];
    const float* cl_bih = (const float*)d_in[21]; const float* cl_bhh = (const float*)d_in[22];
    const float* nl_Wih = (const float*)d_in[23]; const float* nl_Whh = (const float*)d_in[24];
    const float* nl_bih = (const float*)d_in[25]; const float* nl_bhh = (const float*)d_in[26];
    const float* no_comps = (const float*)d_in[27];
    const float* no_nodes = (const float*)d_in[28];
    float* out = (float*)d_out;

    float* S0 = nullptr;
    cudaGetSymbolAddress((void**)&S0, g_scratch4);

    float* astP = S0 + OFF_ASTP;
    float* e0P = S0 + OFF_E0P;   float* e1P = S0 + OFF_E1P;
    float* e2P = S0 + OFF_E2P;   float* edP = S0 + OFF_EDP;
    float* xg  = S0 + OFF_XG;    float* hW  = S0 + OFF_HW;
    float* hAP = S0 + OFF_HAP;   float* cA  = S0 + OFF_CA;
    float* catP = S0 + OFF_CATP; float* t2P = S0 + OFF_T2P;
    float* lfP = S0 + OFF_LFP;   float* xgm = S0 + OFF_XGM;
    float* hMP = S0 + OFF_HMP;   float* cM  = S0 + OFF_CM;
    float* mdP = S0 + OFF_MDP;   float* xgr = S0 + OFF_XGR;
    float* hRP = S0 + OFF_HRP;   float* cR  = S0 + OFF_CR;
    float* pgP = S0 + OFF_PGP;   float* r0P = S0 + OFF_R0P;
    float* r1  = S0 + OFF_R1;
    float* w0P = S0 + OFF_W0P;   float* w1P = S0 + OFF_W1P;
    float* w2P = S0 + OFF_W2P;   float* w3P = S0 + OFF_W3P;
    float* cw0P = S0 + OFF_CW0P; float* cw1P = S0 + OFF_CW1P;
    float* rw0P = S0 + OFF_RW0P; float* rw1P = S0 + OFF_RW1P;
    float* clIP = S0 + OFF_CLIP; float* clHP = S0 + OFF_CLHP;
    float* nlIP = S0 + OFF_NLIP; float* nlHP = S0 + OFF_NLHP;
    float* ncP = S0 + OFF_NCP;   float* nnP = S0 + OFF_NNP;

    // ---- pack weights + constants (one launch) ----
    PackTable pt;
    const float* srcs[NPACK] = { ce_w0, ce_w1, ce_w2, ce_w3, cc_w0, cc_w1, rg_w0, rg_w1,
                                 cl_Wih, cl_Whh, nl_Wih, nl_Whh, no_comps, no_nodes };
    float* dsts[NPACK] = { w0P, w1P, w2P, w3P, cw0P, cw1P, rw0P, rw1P,
                           clIP, clHP, nlIP, nlHP, ncP, nnP };
    int rws[NPACK] = { 600, 350, 200, 180, 200, 180, 200, 180, 720, 720, 720, 720, 1, 1 };
    int ks[NPACK]  = { 1024, 600, 350, 200, 360, 200, 180, 200, 180, 180, 180, 180, 180, 180 };
    int kps[NPACK] = { 1024, 608, 352, 208, 368, 208, 192, 208, 192, 192, 192, 192, 192, 192 };
    for (int i = 0; i < NPACK; i++) {
        pt.src[i] = srcs[i]; pt.dst[i] = dsts[i];
        pt.rows[i] = rws[i]; pt.K[i] = ks[i]; pt.Kp[i] = kps[i];
    }
    {
        long maxn = 600L * 1024;
        dim3 g((unsigned)((maxn + 255) / 256), NPACK);
        pack_many_kernel<<<g, 256>>>(pt);
    }
    pack_ast_kernel<<<(int)(((long)M_CE * 1024 + 255) / 256), 256>>>(ast, (uint2*)astP);

    // ---- Phase A: comp-embedding MLP ----
    gemm(astP, w0P, ce_b0, e0P, M_CE, 600, 1024, 1, 608);
    gemm(e0P,  w1P, ce_b1, e1P, M_CE, 350, 608, 1, 352);
    gemm(e1P,  w2P, ce_b2, e2P, M_CE, 200, 352, 1, 208);
    gemm(e2P,  w3P, ce_b3, edP, M_CE, 180, 208, 1, 192);

    // ---- Phase B: cl LSTM (S=1536, T=8) ----
    gemm(edP, clIP, nullptr, xg, M_CE, G_DIM, 192, 0, 0);
    {
        int thr = S_CL * 192;
        lstm_step_kernel<<<(thr + 255) / 256, 256>>>(xg, hW, cl_bih, cl_bhh,
                                                     (uint2*)hAP, cA, S_CL, 0, 6, 48, 8, 1);
        for (int t = 1; t < 8; t++) {
            gemm(hAP, clHP, nullptr, hW, S_CL, G_DIM, 192, 0, 0);
            lstm_step_kernel<<<(thr + 255) / 256, 256>>>(xg, hW, cl_bih, cl_bhh,
                                                         (uint2*)hAP, cA, S_CL, t, 6, 48, 8, 0);
        }
    }

    // ---- Phase C: leaf concat block ----
    {
        int thr = S_CL * 368;
        concat_kernel<<<(thr + 255) / 256, 256>>>((uint2*)nnP, 1, (uint2*)hAP, 0,
                                                  (uint2*)catP, S_CL);
        gemm(catP, cw0P, cc_b0, t2P, S_CL, 200, 368, 1, 208);
        gemm(t2P,  cw1P, cc_b1, lfP, S_CL, 180, 208, 1, 192);
    }

    // ---- Phase D: mid nl LSTM (S=768, T=2) ----
    gemm(lfP, nlIP, nullptr, xgm, S_CL, G_DIM, 192, 0, 0);
    {
        int thr = S_MID * 192;
        lstm_step_kernel<<<(thr + 255) / 256, 256>>>(xgm, hW, nl_bih, nl_bhh,
                                                     (uint2*)hMP, cM, S_MID, 0, 3, 6, 2, 1);
        gemm(hMP, nlHP, nullptr, hW, S_MID, G_DIM, 192, 0, 0);
        lstm_step_kernel<<<(thr + 255) / 256, 256>>>(xgm, hW, nl_bih, nl_bhh,
                                                     (uint2*)hMP, cM, S_MID, 1, 3, 6, 2, 0);
    }

    // ---- Phase E: mid concat block ----
    {
        int thr = S_MID * 368;
        concat_kernel<<<(thr + 255) / 256, 256>>>((uint2*)hMP, 0, (uint2*)ncP, 1,
                                                  (uint2*)catP, S_MID);
        gemm(catP, cw0P, cc_b0, t2P, S_MID, 200, 368, 1, 208);
        gemm(t2P,  cw1P, cc_b1, mdP, S_MID, 180, 208, 1, 192);
    }

    // ---- Phase F: root nl LSTM (S=256, T=3) ----
    gemm(mdP, nlIP, nullptr, xgr, S_MID, G_DIM, 192, 0, 0);
    {
        int thr = S_RT * 192;
        lstm_step_kernel<<<(thr + 255) / 256, 256>>>(xgr, hW, nl_bih, nl_bhh,
                                                     (uint2*)hRP, cR, S_RT, 0, 1, 3, 0, 1);
        for (int t = 1; t < 3; t++) {
            gemm(hRP, nlHP, nullptr, hW, S_RT, G_DIM, 192, 0, 0);
            lstm_step_kernel<<<(thr + 255) / 256, 256>>>(xgr, hW, nl_bih, nl_bhh,
                                                         (uint2*)hRP, cR, S_RT, t, 1, 3, 0, 0);
        }
    }

    // ---- Phase G: root concat block ----
    {
        int thr = S_RT * 368;
        concat_kernel<<<(thr + 255) / 256, 256>>>((uint2*)hRP, 0, (uint2*)ncP, 1,
                                                  (uint2*)catP, S_RT);
        gemm(catP, cw0P, cc_b0, t2P, S_RT, 200, 368, 1, 208);
        gemm(t2P,  cw1P, cc_b1, pgP, S_RT, 180, 208, 1, 192);
    }

    // ---- Phase H: regression head ----
    gemm(pgP, rw0P, rg_b0, r0P, S_RT, 200, 192, 1, 208);
    gemm(r0P, rw1P, rg_b1, r1, S_RT, 180, 208, 1, 0);
    pred_kernel<<<(S_RT * 32 + 255) / 256, 256>>>(r1, pred_w, pred_b, out, S_RT);
}

// round 9
// speedup vs baseline: 2.8371x; 1.5069x over previous
#include <cuda_runtime.h>
#include <math.h>
#include <stdint.h>

// ---------------------------------------------------------------------------
// Model_Recursive_LSTM_v2 — 3xBF16 (Ootomo split) tensor-core GEMM
// B=256, L=64 (only 0..47 used), IN=1024, E=180
// GEMM: mma.m16n8k16.bf16, operands split v = hi + lo (bf16 each);
// acc += hi*hi + hi*lo + lo*hi  (fp32 accumulate). Per-K cost is half of
// the 3xTF32 k8 path in MMAs, smem bytes, and LDS instructions.
// ---------------------------------------------------------------------------

#define E_DIM 180
#define G_DIM 720          // 4*E
#define M_CE  12288        // 256 * 48 effective rows
#define S_CL  1536
#define S_MID 768
#define S_RT  256

// ---- scratch layout (floats) ----
#define OFF_EMB0  0UL                    // 12288*600
#define OFF_EMB1  7372800UL              // 12288*350
#define OFF_EMB2  11673600UL             // 12288*200
#define OFF_EMBD  14131200UL             // 12288*180
#define OFF_XG    16343040UL             // 12288*720
#define OFF_XGM   25190400UL             // 1536*720
#define OFF_XGR   26296320UL             // 768*720
#define OFF_HW    26849280UL             // 1536*720
#define OFF_HA    27955200UL             // 1536*180
#define OFF_CA    28231680UL             // 1536*180
#define OFF_CAT   28508160UL             // 1536*360
#define OFF_T200  29061120UL             // 1536*200
#define OFF_LEAF  29368320UL             // 1536*180
#define OFF_HM    29644800UL             // 768*180
#define OFF_CM    29783040UL             // 768*180
#define OFF_MIDO  29921280UL             // 768*180
#define OFF_HR    30059520UL             // 256*180
#define OFF_CR    30105600UL             // 256*180
#define OFF_PROG  30151680UL             // 256*180
#define OFF_R0    30197760UL             // 256*200
#define OFF_R1    30248960UL             // 256*180
#define SCRATCH_F 30295040UL

__device__ float g_scratch[SCRATCH_F];

// hi/lo bf16 split of two consecutive values -> {hi_pair, lo_pair}
// low 16 bits of each pair = even element (v0), high = odd (v1).
__device__ __forceinline__ uint2 bfsplit2(float v0, float v1) {
    uint32_t hp;
    asm("cvt.rn.bf16x2.f32 %0, %1, %2;" : "=r"(hp) : "f"(v1), "f"(v0));
    float h0 = __uint_as_float(hp << 16);
    float h1 = __uint_as_float(hp & 0xffff0000u);
    uint32_t lp;
    asm("cvt.rn.bf16x2.f32 %0, %1, %2;" : "=r"(lp) : "f"(v1 - h1), "f"(v0 - h0));
    return make_uint2(hp, lp);
}

__device__ __forceinline__ void mma_bf16(float* d, const uint32_t* a, const uint32_t* b) {
    asm volatile(
        "mma.sync.aligned.m16n8k16.row.col.f32.bf16.bf16.f32 "
        "{%0,%1,%2,%3}, {%4,%5,%6,%7}, {%8,%9}, {%0,%1,%2,%3};"
        : "+f"(d[0]), "+f"(d[1]), "+f"(d[2]), "+f"(d[3])
        : "r"(a[0]), "r"(a[1]), "r"(a[2]), "r"(a[3]),
          "r"(b[0]), "r"(b[1]));
}

extern __shared__ uint32_t dynsmem[];

// ---------------------------------------------------------------------------
// 3xBF16 pipelined GEMM: C[M,N] = act( A[M,K] @ W[N,K]^T + bias )
// Smem per row: 4 uint4 covering one k16 slice:
//   slot t (t=0..3) = { hi(k=2t,2t+1), lo(2t,2t+1), hi(2t+8,2t+9), lo(2t+8,2t+9) }
// Row stride RS=4 uint4 (64B) -> conflict-free fragment LDS.128.
// Fragment regs for m16n8k16 come from single LDS.128 per (row, tig).
// remap!=0: logical A-row m maps to physical row (m/48)*64 + (m%48)
// M must be a multiple of BMT (true for all call sites).
// ---------------------------------------------------------------------------
template <int BMT, int WMT, int WNT, int MINB>
__global__ __launch_bounds__(2 * BMT, MINB) void mma_gemm_bf(
    const float* __restrict__ A, const float* __restrict__ W,
    const float* __restrict__ bias, float* __restrict__ C,
    int M, int N, int K, int act, int remap)
{
    constexpr int MT = BMT / (WMT * 16);
    constexpr int NT = BMT / (WNT * 8);
    constexpr int RS = 4;                  // uint4 per row (one k16 slice)
    constexpr int ARR_U4 = BMT * RS;
    constexpr int STAGE_U4 = 2 * ARR_U4;   // A + B

    uint4* smem4 = reinterpret_cast<uint4*>(dynsmem);

    const int tid  = threadIdx.x;
    const int warp = tid >> 5;
    const int lane = tid & 31;
    const int wm = warp % WMT;
    const int wn = warp / WMT;
    const int bm = blockIdx.y * BMT;
    const int bn = blockIdx.x * BMT;

    const int grp = lane >> 2;
    const int tig = lane & 3;

    float acc[MT][NT][4];
#pragma unroll
    for (int i = 0; i < MT; i++)
#pragma unroll
        for (int j = 0; j < NT; j++)
#pragma unroll
            for (int r = 0; r < 4; r++) acc[i][j][r] = 0.f;

    // loader: 2 threads per row; thread half h covers k offsets
    // {4h..4h+3, 4h+8..4h+11} within the 16-k slab (slots 2h, 2h+1).
    const int arow = tid >> 1;
    const int h    = tid & 1;
    long abase = -1;
    {
        int gm = bm + arow;
        if (gm < M) {
            long r = remap ? ((long)(gm / 48) * 64 + (gm % 48)) : (long)gm;
            abase = r * (long)K;
        }
    }
    const long bbase = (bn + arow < N) ? (long)(bn + arow) * K : -1;

    int kk[8];
#pragma unroll
    for (int j = 0; j < 8; j++) kk[j] = 4 * h + (j < 4 ? j : j + 4);

    float ra[8], rb[8];

    // ---- prologue: slab 0 ----
#pragma unroll
    for (int j = 0; j < 8; j++) {
        int gk = kk[j];
        ra[j] = (abase >= 0 && gk < K) ? A[abase + gk] : 0.f;
        rb[j] = (bbase >= 0 && gk < K) ? W[bbase + gk] : 0.f;
    }
    {
        uint4* sA = smem4;
        uint4* sB = smem4 + ARR_U4;
#pragma unroll
        for (int j = 0; j < 2; j++) {
            uint2 pl = bfsplit2(ra[2 * j],     ra[2 * j + 1]);
            uint2 ph = bfsplit2(ra[4 + 2 * j], ra[5 + 2 * j]);
            sA[arow * RS + 2 * h + j] = make_uint4(pl.x, pl.y, ph.x, ph.y);
            pl = bfsplit2(rb[2 * j],     rb[2 * j + 1]);
            ph = bfsplit2(rb[4 + 2 * j], rb[5 + 2 * j]);
            sB[arow * RS + 2 * h + j] = make_uint4(pl.x, pl.y, ph.x, ph.y);
        }
    }
    __syncthreads();

    int cur = 0;
    for (int k0 = 0; k0 < K; k0 += 16) {
        const int nxt = k0 + 16;
        const bool has = nxt < K;

        if (has) {
            if (nxt + 16 <= K) {
#pragma unroll
                for (int j = 0; j < 8; j++) {
                    int gk = nxt + kk[j];
                    ra[j] = (abase >= 0) ? A[abase + gk] : 0.f;
                    rb[j] = (bbase >= 0) ? W[bbase + gk] : 0.f;
                }
            } else {
#pragma unroll
                for (int j = 0; j < 8; j++) {
                    int gk = nxt + kk[j];
                    ra[j] = (abase >= 0 && gk < K) ? A[abase + gk] : 0.f;
                    rb[j] = (bbase >= 0 && gk < K) ? W[bbase + gk] : 0.f;
                }
            }
        }

        // ---- compute current slab (one k16 slice) ----
        {
            const uint4* sA = smem4 + cur * STAGE_U4;
            const uint4* sB = sA + ARR_U4;
            uint32_t ah[MT][4], al[MT][4];
            uint32_t bh[NT][2], bl[NT][2];
#pragma unroll
            for (int mt = 0; mt < MT; mt++) {
                int mr = wm * MT * 16 + mt * 16 + grp;
                uint4 p0 = sA[mr * RS + tig];
                uint4 p1 = sA[(mr + 8) * RS + tig];
                ah[mt][0] = p0.x; ah[mt][1] = p1.x; ah[mt][2] = p0.z; ah[mt][3] = p1.z;
                al[mt][0] = p0.y; al[mt][1] = p1.y; al[mt][2] = p0.w; al[mt][3] = p1.w;
            }
#pragma unroll
            for (int nt = 0; nt < NT; nt++) {
                int nc = wn * NT * 8 + nt * 8 + grp;
                uint4 q = sB[nc * RS + tig];
                bh[nt][0] = q.x; bh[nt][1] = q.z;
                bl[nt][0] = q.y; bl[nt][1] = q.w;
            }
#pragma unroll
            for (int mt = 0; mt < MT; mt++)
#pragma unroll
                for (int nt = 0; nt < NT; nt++) {
                    mma_bf16(acc[mt][nt], ah[mt], bl[nt]);   // hi*lo
                    mma_bf16(acc[mt][nt], al[mt], bh[nt]);   // lo*hi
                    mma_bf16(acc[mt][nt], ah[mt], bh[nt]);   // hi*hi
                }
        }

        // ---- store next slab into the other buffer ----
        if (has) {
            uint4* sA = smem4 + (cur ^ 1) * STAGE_U4;
            uint4* sB = sA + ARR_U4;
#pragma unroll
            for (int j = 0; j < 2; j++) {
                uint2 pl = bfsplit2(ra[2 * j],     ra[2 * j + 1]);
                uint2 ph = bfsplit2(ra[4 + 2 * j], ra[5 + 2 * j]);
                sA[arow * RS + 2 * h + j] = make_uint4(pl.x, pl.y, ph.x, ph.y);
                pl = bfsplit2(rb[2 * j],     rb[2 * j + 1]);
                ph = bfsplit2(rb[4 + 2 * j], rb[5 + 2 * j]);
                sB[arow * RS + 2 * h + j] = make_uint4(pl.x, pl.y, ph.x, ph.y);
            }
        }
        __syncthreads();
        cur ^= 1;
    }

    // ---- epilogue: bias + ELU + store ----
#pragma unroll
    for (int mt = 0; mt < MT; mt++) {
        int r0 = bm + wm * MT * 16 + mt * 16 + grp;
        int r1 = r0 + 8;
#pragma unroll
        for (int nt = 0; nt < NT; nt++) {
            int cc = bn + wn * NT * 8 + nt * 8 + tig * 2;
#pragma unroll
            for (int hh = 0; hh < 2; hh++) {
                int rr = hh ? r1 : r0;
                if (rr >= M) continue;
#pragma unroll
                for (int q = 0; q < 2; q++) {
                    int gn = cc + q;
                    if (gn >= N) continue;
                    float v = acc[mt][nt][hh * 2 + q];
                    if (bias) v += bias[gn];
                    if (act) v = v > 0.f ? v : (expf(v) - 1.f);
                    C[(long)rr * N + gn] = v;
                }
            }
        }
    }
}

// smem: 2 stages * 2 arrays * BMT rows * 4 uint4 * 16B = 256*BMT bytes
#define SMEM_L (256 * 128)   // 32768
#define SMEM_S (256 * 64)    // 16384

// ---------------------------------------------------------------------------
// LSTM pointwise step (gate order i,f,g,o)
// ---------------------------------------------------------------------------
__device__ __forceinline__ float sigf(float x) { return 1.f / (1.f + expf(-x)); }

__global__ void lstm_step_kernel(
    const float* __restrict__ xg, const float* __restrict__ hW,
    const float* __restrict__ bih, const float* __restrict__ bhh,
    float* __restrict__ h, float* __restrict__ c,
    int S, int t, int divA, int mulA, int mulB, int first)
{
    int idx = blockIdx.x * blockDim.x + threadIdx.x;
    if (idx >= S * E_DIM) return;
    int s = idx / E_DIM, e = idx % E_DIM;
    int xrow = (s / divA) * mulA + (s % divA) * mulB + t;
    const float* xr = xg + (long)xrow * G_DIM;

    float gi = xr[e]             + bih[e]             + bhh[e];
    float gf = xr[E_DIM + e]     + bih[E_DIM + e]     + bhh[E_DIM + e];
    float gg = xr[2 * E_DIM + e] + bih[2 * E_DIM + e] + bhh[2 * E_DIM + e];
    float go = xr[3 * E_DIM + e] + bih[3 * E_DIM + e] + bhh[3 * E_DIM + e];

    float cprev = 0.f;
    if (!first) {
        const float* hr = hW + (long)s * G_DIM;
        gi += hr[e]; gf += hr[E_DIM + e]; gg += hr[2 * E_DIM + e]; go += hr[3 * E_DIM + e];
        cprev = c[idx];
    }
    float cn = sigf(gf) * cprev + sigf(gi) * tanhf(gg);
    c[idx] = cn;
    h[idx] = sigf(go) * tanhf(cn);
}

// ---------------------------------------------------------------------------
__global__ void concat_kernel(
    const float* __restrict__ first, int firstB,
    const float* __restrict__ second, int secondB,
    float* __restrict__ cat, int rows)
{
    int idx = blockIdx.x * blockDim.x + threadIdx.x;
    if (idx >= rows * 2 * E_DIM) return;
    int r = idx / (2 * E_DIM), e = idx % (2 * E_DIM);
    float v;
    if (e < E_DIM) v = firstB  ? first[e]            : first[(long)r * E_DIM + e];
    else { int e2 = e - E_DIM; v = secondB ? second[e2] : second[(long)r * E_DIM + e2]; }
    cat[idx] = v;
}

// ---------------------------------------------------------------------------
__global__ void pred_kernel(const float* __restrict__ x, const float* __restrict__ w,
                            const float* __restrict__ b, float* __restrict__ out, int rows)
{
    int gwarp = (blockIdx.x * blockDim.x + threadIdx.x) >> 5;
    int lane = threadIdx.x & 31;
    if (gwarp >= rows) return;
    float s = 0.f;
    for (int e = lane; e < E_DIM; e += 32) s += x[(long)gwarp * E_DIM + e] * w[e];
#pragma unroll
    for (int o = 16; o; o >>= 1) s += __shfl_down_sync(0xffffffffu, s, o);
    if (lane == 0) out[gwarp] = s + b[0];
}

// ---------------------------------------------------------------------------
// host side
// ---------------------------------------------------------------------------
static inline void gemm(const float* A, const float* W, const float* bias, float* C,
                        int M, int N, int K, int act, int remap)
{
    int gL = ((N + 127) / 128) * ((M + 127) / 128);
    if (gL >= 96) {
        dim3 grid((N + 127) / 128, (M + 127) / 128);
        mma_gemm_bf<128, 2, 4, 2><<<grid, 256, SMEM_L>>>(A, W, bias, C, M, N, K, act, remap);
    } else {
        dim3 grid((N + 63) / 64, (M + 63) / 64);
        mma_gemm_bf<64, 2, 2, 4><<<grid, 128, SMEM_S>>>(A, W, bias, C, M, N, K, act, remap);
    }
}

extern "C" void kernel_launch(void* const* d_in, const int* in_sizes, int n_in,
                              void* d_out, int out_size)
{
    const float* ast    = (const float*)d_in[0];
    const float* ce_w0  = (const float*)d_in[1];  const float* ce_b0 = (const float*)d_in[2];
    const float* ce_w1  = (const float*)d_in[3];  const float* ce_b1 = (const float*)d_in[4];
    const float* ce_w2  = (const float*)d_in[5];  const float* ce_b2 = (const float*)d_in[6];
    const float* ce_w3  = (const float*)d_in[7];  const float* ce_b3 = (const float*)d_in[8];
    const float* cc_w0  = (const float*)d_in[9];  const float* cc_b0 = (const float*)d_in[10];
    const float* cc_w1  = (const float*)d_in[11]; const float* cc_b1 = (const float*)d_in[12];
    const float* rg_w0  = (const float*)d_in[13]; const float* rg_b0 = (const float*)d_in[14];
    const float* rg_w1  = (const float*)d_in[15]; const float* rg_b1 = (const float*)d_in[16];
    const float* pred_w = (const float*)d_in[17]; const float* pred_b = (const float*)d_in[18];
    const float* cl_Wih = (const float*)d_in[19]; const float* cl_Whh = (const float*)d_in[20];
    const float* cl_bih = (const float*)d_in[21]; const float* cl_bhh = (const float*)d_in[22];
    const float* nl_Wih = (const float*)d_in[23]; const float* nl_Whh = (const float*)d_in[24];
    const float* nl_bih = (const float*)d_in[25]; const float* nl_bhh = (const float*)d_in[26];
    const float* no_comps = (const float*)d_in[27];
    const float* no_nodes = (const float*)d_in[28];
    float* out = (float*)d_out;

    float* S0 = nullptr;
    cudaGetSymbolAddress((void**)&S0, g_scratch);

    float* emb0 = S0 + OFF_EMB0;  float* emb1 = S0 + OFF_EMB1;
    float* emb2 = S0 + OFF_EMB2;  float* embd = S0 + OFF_EMBD;
    float* xg   = S0 + OFF_XG;    float* xgm  = S0 + OFF_XGM;  float* xgr = S0 + OFF_XGR;
    float* hW   = S0 + OFF_HW;
    float* hA   = S0 + OFF_HA;    float* cA   = S0 + OFF_CA;
    float* cat  = S0 + OFF_CAT;   float* t200 = S0 + OFF_T200;
    float* leaf = S0 + OFF_LEAF;
    float* hM   = S0 + OFF_HM;    float* cM   = S0 + OFF_CM;   float* mido = S0 + OFF_MIDO;
    float* hR   = S0 + OFF_HR;    float* cR   = S0 + OFF_CR;
    float* prog = S0 + OFF_PROG;  float* r0   = S0 + OFF_R0;   float* r1  = S0 + OFF_R1;

    // ---- Phase A: comp-embedding MLP on the 48 used positions ----
    gemm(ast,  ce_w0, ce_b0, emb0, M_CE, 600, 1024, 1, 1);   // remap 48-of-64
    gemm(emb0, ce_w1, ce_b1, emb1, M_CE, 350, 600, 1, 0);
    gemm(emb1, ce_w2, ce_b2, emb2, M_CE, 200, 350, 1, 0);
    gemm(emb2, ce_w3, ce_b3, embd, M_CE, E_DIM, 200, 1, 0);

    // ---- Phase B: cl LSTM (S=1536, T=8) ----
    gemm(embd, cl_Wih, nullptr, xg, M_CE, G_DIM, E_DIM, 0, 0);
    {
        int thr = S_CL * E_DIM;
        lstm_step_kernel<<<(thr + 255) / 256, 256>>>(xg, hW, cl_bih, cl_bhh, hA, cA,
                                                     S_CL, 0, 6, 48, 8, 1);
        for (int t = 1; t < 8; t++) {
            gemm(hA, cl_Whh, nullptr, hW, S_CL, G_DIM, E_DIM, 0, 0);
            lstm_step_kernel<<<(thr + 255) / 256, 256>>>(xg, hW, cl_bih, cl_bhh, hA, cA,
                                                         S_CL, t, 6, 48, 8, 0);
        }
    }

    // ---- Phase C: leaf concat block ----
    {
        int thr = S_CL * 2 * E_DIM;
        concat_kernel<<<(thr + 255) / 256, 256>>>(no_nodes, 1, hA, 0, cat, S_CL);
        gemm(cat,  cc_w0, cc_b0, t200, S_CL, 200, 2 * E_DIM, 1, 0);
        gemm(t200, cc_w1, cc_b1, leaf, S_CL, E_DIM, 200, 1, 0);
    }

    // ---- Phase D: mid nl LSTM (S=768, T=2) ----
    gemm(leaf, nl_Wih, nullptr, xgm, S_CL, G_DIM, E_DIM, 0, 0);
    {
        int thr = S_MID * E_DIM;
        lstm_step_kernel<<<(thr + 255) / 256, 256>>>(xgm, hW, nl_bih, nl_bhh, hM, cM,
                                                     S_MID, 0, 3, 6, 2, 1);
        gemm(hM, nl_Whh, nullptr, hW, S_MID, G_DIM, E_DIM, 0, 0);
        lstm_step_kernel<<<(thr + 255) / 256, 256>>>(xgm, hW, nl_bih, nl_bhh, hM, cM,
                                                     S_MID, 1, 3, 6, 2, 0);
    }

    // ---- Phase E: mid concat block ----
    {
        int thr = S_MID * 2 * E_DIM;
        concat_kernel<<<(thr + 255) / 256, 256>>>(hM, 0, no_comps, 1, cat, S_MID);
        gemm(cat,  cc_w0, cc_b0, t200, S_MID, 200, 2 * E_DIM, 1, 0);
        gemm(t200, cc_w1, cc_b1, mido, S_MID, E_DIM, 200, 1, 0);
    }

    // ---- Phase F: root nl LSTM (S=256, T=3) ----
    gemm(mido, nl_Wih, nullptr, xgr, S_MID, G_DIM, E_DIM, 0, 0);
    {
        int thr = S_RT * E_DIM;
        lstm_step_kernel<<<(thr + 255) / 256, 256>>>(xgr, hW, nl_bih, nl_bhh, hR, cR,
                                                     S_RT, 0, 1, 3, 0, 1);
        for (int t = 1; t < 3; t++) {
            gemm(hR, nl_Whh, nullptr, hW, S_RT, G_DIM, E_DIM, 0, 0);
            lstm_step_kernel<<<(thr + 255) / 256, 256>>>(xgr, hW, nl_bih, nl_bhh, hR, cR,
                                                         S_RT, t, 1, 3, 0, 0);
        }
    }

    // ---- Phase G: root concat block ----
    {
        int thr = S_RT * 2 * E_DIM;
        concat_kernel<<<(thr + 255) / 256, 256>>>(hR, 0, no_comps, 1, cat, S_RT);
        gemm(cat,  cc_w0, cc_b0, t200, S_RT, 200, 2 * E_DIM, 1, 0);
        gemm(t200, cc_w1, cc_b1, prog, S_RT, E_DIM, 200, 1, 0);
    }

    // ---- Phase H: regression head ----
    gemm(prog, rg_w0, rg_b0, r0, S_RT, 200, E_DIM, 1, 0);
    gemm(r0,   rg_w1, rg_b1, r1, S_RT, E_DIM, 200, 1, 0);
    pred_kernel<<<(S_RT * 32 + 255) / 256, 256>>>(r1, pred_w, pred_b, out, S_RT);
}

// round 10
// speedup vs baseline: 4.2950x; 1.5139x over previous
#include <cuda_runtime.h>
#include <math.h>
#include <stdint.h>

// ---------------------------------------------------------------------------
// Model_Recursive_LSTM_v2 — 3xBF16 GEMM with pre-packed (hi,lo) operands and
// cp.async 4-stage pipeline. B=256, L=64 (only 0..47 used), IN=1024, E=180.
//
// Packed layout (word = uint32): per row of padded width Kp (mult of 16),
// pair index kp=k/2, slab=kp>>3, q=kp&7:
//   word_off = slab*16 + (q&3)*4 + (q>>2)*2 ; word[off]=hi bf16x2, [off+1]=lo
// This equals the GEMM smem slot layout, so the mainloop is pure cp.async.
// Packed row bytes == fp32 row bytes (no bandwidth penalty).
// ---------------------------------------------------------------------------

#define E_DIM 180
#define G_DIM 720
#define M_CE  12288
#define S_CL  1536
#define S_MID 768
#define S_RT  256

// ---- scratch offsets (float words, all multiples of 4) ----
#define OFF_ASTP  0UL
#define OFF_E0P   12582912UL
#define OFF_E1P   20054016UL
#define OFF_E2P   24379392UL
#define OFF_EDP   26935296UL
#define OFF_XG    29294592UL
#define OFF_HW    38141952UL
#define OFF_HAP   39247872UL
#define OFF_CA    39542784UL
#define OFF_CATP  39819264UL
#define OFF_T2P   40384512UL
#define OFF_LFP   40704000UL
#define OFF_XGM   40998912UL
#define OFF_HMP   42104832UL
#define OFF_CM    42252288UL
#define OFF_MDP   42390528UL
#define OFF_XGR   42537984UL
#define OFF_HRP   43090944UL
#define OFF_CR    43140096UL
#define OFF_PGP   43186176UL
#define OFF_R0P   43235328UL
#define OFF_R1    43288576UL
#define OFF_W0P   43334656UL
#define OFF_W1P   43949056UL
#define OFF_W2P   44161856UL
#define OFF_W3P   44232256UL
#define OFF_CW0P  44269696UL
#define OFF_CW1P  44343296UL
#define OFF_RW0P  44380736UL
#define OFF_RW1P  44419136UL
#define OFF_CLIP  44456576UL
#define OFF_CLHP  44594816UL
#define OFF_NLIP  44733056UL
#define OFF_NLHP  44871296UL
#define OFF_NCP   45009536UL
#define OFF_NNP   45009728UL
#define SCRATCH_F 45009920UL

__device__ float4 g_scratch4[SCRATCH_F / 4];

// hi/lo bf16 split of two consecutive values -> {hi_pair, lo_pair}
__device__ __forceinline__ uint2 bfsplit2(float v0, float v1) {
    uint32_t hp;
    asm("cvt.rn.bf16x2.f32 %0, %1, %2;" : "=r"(hp) : "f"(v1), "f"(v0));
    float h0 = __uint_as_float(hp << 16);
    float h1 = __uint_as_float(hp & 0xffff0000u);
    uint32_t lp;
    asm("cvt.rn.bf16x2.f32 %0, %1, %2;" : "=r"(lp) : "f"(v1 - h1), "f"(v0 - h0));
    return make_uint2(hp, lp);
}

// packed word index for even k within a row of padded width Kp
__device__ __forceinline__ long widx(long row, int k, int Kp) {
    int kp = k >> 1;
    int q = kp & 7;
    return row * Kp + (long)((kp >> 3) * 16 + (q & 3) * 4 + (q >> 2) * 2);
}

__device__ __forceinline__ void mma_bf16(float* d, const uint32_t* a, const uint32_t* b) {
    asm volatile(
        "mma.sync.aligned.m16n8k16.row.col.f32.bf16.bf16.f32 "
        "{%0,%1,%2,%3}, {%4,%5,%6,%7}, {%8,%9}, {%0,%1,%2,%3};"
        : "+f"(d[0]), "+f"(d[1]), "+f"(d[2]), "+f"(d[3])
        : "r"(a[0]), "r"(a[1]), "r"(a[2]), "r"(a[3]),
          "r"(b[0]), "r"(b[1]));
}

__device__ __forceinline__ uint32_t smem_u32(const void* p) {
    uint32_t a;
    asm("{ .reg .u64 t; cvta.to.shared.u64 t, %1; cvt.u32.u64 %0, t; }"
        : "=r"(a) : "l"(p));
    return a;
}

__device__ __forceinline__ void cpa16(uint32_t dst, const void* src, uint32_t bytes) {
    asm volatile("cp.async.cg.shared.global [%0], [%1], 16, %2;"
                 :: "r"(dst), "l"(src), "r"(bytes) : "memory");
}
#define CP_COMMIT() asm volatile("cp.async.commit_group;" ::: "memory")
#define CP_WAIT(n)  asm volatile("cp.async.wait_group %0;" :: "n"(n) : "memory")

extern __shared__ uint32_t dynsmem[];

// ---------------------------------------------------------------------------
// Packed 3xBF16 GEMM: C = act( A @ W^T + bias ). A,W packed. 4-stage cp.async.
// Npck>0: write packed C (width Npck, zero-padded); Npck==0: write fp32 C.
// M multiple of BMT at every call site.
// ---------------------------------------------------------------------------
template <int BMT, int WMT, int WNT, int MINB>
__global__ __launch_bounds__(2 * BMT, MINB) void mma_gemm_pk(
    const uint4* __restrict__ Ap, const uint4* __restrict__ Wp,
    const float* __restrict__ bias, void* __restrict__ Cout,
    int M, int N, int Kp, int act, int Npck)
{
    constexpr int MT = BMT / (WMT * 16);
    constexpr int NT = BMT / (WNT * 8);
    constexpr int RS = 4;                   // uint4 per row per slab
    constexpr int ARR_U4 = BMT * RS;
    constexpr int STAGE_U4 = 2 * ARR_U4;
    constexpr int STAGES = 4;

    uint4* smem4 = reinterpret_cast<uint4*>(dynsmem);
    const uint32_t sbase = smem_u32(dynsmem);

    const int tid  = threadIdx.x;
    const int warp = tid >> 5;
    const int lane = tid & 31;
    const int wm = warp % WMT;
    const int wn = warp / WMT;
    const int bm = blockIdx.y * BMT;
    const int bn = blockIdx.x * BMT;
    const int grp = lane >> 2;
    const int tig = lane & 3;

    float acc[MT][NT][4];
#pragma unroll
    for (int i = 0; i < MT; i++)
#pragma unroll
        for (int j = 0; j < NT; j++)
#pragma unroll
            for (int r = 0; r < 4; r++) acc[i][j][r] = 0.f;

    // copy assignment: thread -> (row, half); 2 uint4 of A + 2 of B per slab
    const int arow = tid >> 1;
    const int half = tid & 1;
    const long rowU4 = (long)(Kp >> 2);
    const long aBase = (long)(bm + arow) * rowU4 + half * 2;
    const int brow = bn + arow;
    const bool bval = brow < N;
    const long bBase = (long)(bval ? brow : 0) * rowU4 + half * 2;
    const uint32_t bbytes = bval ? 16u : 0u;
    const uint32_t aDst0 = sbase + (uint32_t)(arow * RS + half * 2) * 16u;
    const uint32_t bDst0 = aDst0 + (uint32_t)ARR_U4 * 16u;

    const int nSlab = Kp >> 4;

#define ISSUE(slabi) do {                                                    \
        int _s = (slabi) % STAGES;                                           \
        uint32_t _so = (uint32_t)(_s * STAGE_U4) * 16u;                      \
        const uint4* _as = Ap + aBase + (long)(slabi) * 4;                   \
        const uint4* _bs = Wp + bBase + (long)(slabi) * 4;                   \
        cpa16(aDst0 + _so,       _as,     16u);                              \
        cpa16(aDst0 + _so + 16u, _as + 1, 16u);                              \
        cpa16(bDst0 + _so,       _bs,     bbytes);                           \
        cpa16(bDst0 + _so + 16u, _bs + 1, bbytes);                           \
    } while (0)

#pragma unroll
    for (int s = 0; s < STAGES - 1; s++) {
        if (s < nSlab) ISSUE(s);
        CP_COMMIT();
    }

    for (int slab = 0; slab < nSlab; slab++) {
        CP_WAIT(STAGES - 2);
        __syncthreads();
        {
            int nx = slab + STAGES - 1;
            if (nx < nSlab) ISSUE(nx);
        }
        CP_COMMIT();

        // ---- compute slab ----
        const uint4* sA = smem4 + (slab % STAGES) * STAGE_U4;
        const uint4* sB = sA + ARR_U4;
        uint32_t ah[MT][4], al[MT][4];
        uint32_t bh[NT][2], bl[NT][2];
#pragma unroll
        for (int mt = 0; mt < MT; mt++) {
            int mr = wm * MT * 16 + mt * 16 + grp;
            uint4 p0 = sA[mr * RS + tig];
            uint4 p1 = sA[(mr + 8) * RS + tig];
            ah[mt][0] = p0.x; ah[mt][1] = p1.x; ah[mt][2] = p0.z; ah[mt][3] = p1.z;
            al[mt][0] = p0.y; al[mt][1] = p1.y; al[mt][2] = p0.w; al[mt][3] = p1.w;
        }
#pragma unroll
        for (int nt = 0; nt < NT; nt++) {
            int nc = wn * NT * 8 + nt * 8 + grp;
            uint4 q = sB[nc * RS + tig];
            bh[nt][0] = q.x; bh[nt][1] = q.z;
            bl[nt][0] = q.y; bl[nt][1] = q.w;
        }
#pragma unroll
        for (int mt = 0; mt < MT; mt++)
#pragma unroll
            for (int nt = 0; nt < NT; nt++) {
                mma_bf16(acc[mt][nt], ah[mt], bl[nt]);   // hi*lo
                mma_bf16(acc[mt][nt], al[mt], bh[nt]);   // lo*hi
                mma_bf16(acc[mt][nt], ah[mt], bh[nt]);   // hi*hi
            }
    }
#undef ISSUE

    // ---- epilogue ----
    if (Npck > 0) {
        uint32_t* Cw = (uint32_t*)Cout;
#pragma unroll
        for (int mt = 0; mt < MT; mt++) {
            int r0 = bm + wm * MT * 16 + mt * 16 + grp;
#pragma unroll
            for (int nt = 0; nt < NT; nt++) {
                int cc = bn + wn * NT * 8 + nt * 8 + tig * 2;
                if (cc >= Npck) continue;
#pragma unroll
                for (int hh = 0; hh < 2; hh++) {
                    int rr = r0 + hh * 8;
                    float v0 = 0.f, v1 = 0.f;
                    if (cc < N) {
                        v0 = acc[mt][nt][hh * 2];
                        if (bias) v0 += bias[cc];
                        if (act) v0 = v0 > 0.f ? v0 : (expf(v0) - 1.f);
                    }
                    if (cc + 1 < N) {
                        v1 = acc[mt][nt][hh * 2 + 1];
                        if (bias) v1 += bias[cc + 1];
                        if (act) v1 = v1 > 0.f ? v1 : (expf(v1) - 1.f);
                    }
                    uint2 p = bfsplit2(v0, v1);
                    *(uint2*)(Cw + widx((long)rr, cc, Npck)) = p;
                }
            }
        }
    } else {
        float* Cf = (float*)Cout;
#pragma unroll
        for (int mt = 0; mt < MT; mt++) {
            int r0 = bm + wm * MT * 16 + mt * 16 + grp;
#pragma unroll
            for (int nt = 0; nt < NT; nt++) {
                int cc = bn + wn * NT * 8 + nt * 8 + tig * 2;
#pragma unroll
                for (int hh = 0; hh < 2; hh++) {
                    int rr = r0 + hh * 8;
#pragma unroll
                    for (int q = 0; q < 2; q++) {
                        int gn = cc + q;
                        if (gn >= N) continue;
                        float v = acc[mt][nt][hh * 2 + q];
                        if (bias) v += bias[gn];
                        if (act) v = v > 0.f ? v : (expf(v) - 1.f);
                        Cf[(long)rr * N + gn] = v;
                    }
                }
            }
        }
    }
}

// smem: STAGES * 2 arrays * BMT rows * 4 uint4 * 16B
#define SMEM_L (4 * 2 * 128 * 4 * 16)   // 65536
#define SMEM_S (4 * 2 * 64 * 4 * 16)    // 32768

// ---------------------------------------------------------------------------
// Pack kernels: fp32 -> packed bf16 (hi,lo) layout
// ---------------------------------------------------------------------------
#define NPACK 14
struct PackTable {
    const float* src[NPACK];
    float* dst[NPACK];
    int rows[NPACK];
    int K[NPACK];
    int Kp[NPACK];
};

__global__ void pack_many_kernel(PackTable pt) {
    int which = blockIdx.y;
    int rows = pt.rows[which], K = pt.K[which], Kp = pt.Kp[which];
    int pairs = Kp >> 1;
    long n = (long)rows * pairs;
    long idx = (long)blockIdx.x * blockDim.x + threadIdx.x;
    if (idx >= n) return;
    int r = (int)(idx / pairs);
    int k = (int)(idx % pairs) * 2;
    const float* s = pt.src[which] + (long)r * K;
    float v0 = (k < K) ? s[k] : 0.f;
    float v1 = (k + 1 < K) ? s[k + 1] : 0.f;
    uint2 p = bfsplit2(v0, v1);
    *(uint2*)((uint32_t*)pt.dst[which] + widx((long)r, k, Kp)) = p;
}

// ast pack with 48-of-64 row gather; K=Kp=1024
__global__ void pack_ast_kernel(const float* __restrict__ src, uint32_t* __restrict__ dst) {
    long idx = (long)blockIdx.x * blockDim.x + threadIdx.x;
    if (idx >= (long)M_CE * 512) return;
    int m = (int)(idx / 512);
    int k = (int)(idx % 512) * 2;
    long phys = (long)(m / 48) * 64 + (m % 48);
    const float* s = src + phys * 1024 + k;
    uint2 p = bfsplit2(s[0], s[1]);
    *(uint2*)(dst + widx((long)m, k, 1024)) = p;
}

// ---------------------------------------------------------------------------
// LSTM pointwise step (gate order i,f,g,o); writes h packed (width 192)
// ---------------------------------------------------------------------------
__device__ __forceinline__ float sigf(float x) { return 1.f / (1.f + expf(-x)); }

__device__ __forceinline__ float lstm_gate(
    const float* xr, const float* hr, const float* bih, const float* bhh,
    float* cslot, int e, int hashW)
{
    float gi = xr[e]             + bih[e]             + bhh[e];
    float gf = xr[E_DIM + e]     + bih[E_DIM + e]     + bhh[E_DIM + e];
    float gg = xr[2 * E_DIM + e] + bih[2 * E_DIM + e] + bhh[2 * E_DIM + e];
    float go = xr[3 * E_DIM + e] + bih[3 * E_DIM + e] + bhh[3 * E_DIM + e];
    float cprev = 0.f;
    if (hashW) {
        gi += hr[e]; gf += hr[E_DIM + e]; gg += hr[2 * E_DIM + e]; go += hr[3 * E_DIM + e];
        cprev = *cslot;
    }
    float cn = sigf(gf) * cprev + sigf(gi) * tanhf(gg);
    *cslot = cn;
    return sigf(go) * tanhf(cn);
}

__global__ void lstm_step_kernel(
    const float* __restrict__ xg, const float* __restrict__ hW,
    const float* __restrict__ bih, const float* __restrict__ bhh,
    uint32_t* __restrict__ hP, float* __restrict__ c,
    int S, int t, int divA, int mulA, int mulB, int first)
{
    int idx = blockIdx.x * blockDim.x + threadIdx.x;
    if (idx >= S * 96) return;                   // 96 pairs per row (width 192)
    int s = idx / 96, pe = idx % 96;
    int e = pe * 2;
    uint2 p = make_uint2(0, 0);
    if (e < E_DIM) {
        int xrow = (s / divA) * mulA + (s % divA) * mulB + t;
        const float* xr = xg + (long)xrow * G_DIM;
        const float* hr = hW + (long)s * G_DIM;
        float v0 = lstm_gate(xr, hr, bih, bhh, c + (long)s * E_DIM + e, e, !first);
        float v1 = lstm_gate(xr, hr, bih, bhh, c + (long)s * E_DIM + e + 1, e + 1, !first);
        p = bfsplit2(v0, v1);
    }
    *(uint2*)(hP + widx((long)s, e, 192)) = p;
}

// ---------------------------------------------------------------------------
// Concat packed: width 368; regions [0,180) first, [180,360) second, rest 0.
// ---------------------------------------------------------------------------
__global__ void concat_kernel(
    const uint32_t* __restrict__ first, int firstB,
    const uint32_t* __restrict__ second, int secondB,
    uint32_t* __restrict__ cat, int rows)
{
    int idx = blockIdx.x * blockDim.x + threadIdx.x;
    if (idx >= rows * 184) return;               // 184 pairs per row
    int r = idx / 184, pj = idx % 184;
    int j = pj * 2;
    uint2 v = make_uint2(0, 0);
    if (j < E_DIM) {
        long sr = firstB ? 0 : (long)r;
        v = *(const uint2*)(first + widx(sr, j, 192));
    } else if (j < 2 * E_DIM) {
        long sr = secondB ? 0 : (long)r;
        v = *(const uint2*)(second + widx(sr, j - E_DIM, 192));
    }
    *(uint2*)(cat + widx((long)r, j, 368)) = v;
}

// ---------------------------------------------------------------------------
__global__ void pred_kernel(const float* __restrict__ x, const float* __restrict__ w,
                            const float* __restrict__ b, float* __restrict__ out, int rows)
{
    int gwarp = (blockIdx.x * blockDim.x + threadIdx.x) >> 5;
    int lane = threadIdx.x & 31;
    if (gwarp >= rows) return;
    float s = 0.f;
    for (int e = lane; e < E_DIM; e += 32) s += x[(long)gwarp * E_DIM + e] * w[e];
#pragma unroll
    for (int o = 16; o; o >>= 1) s += __shfl_down_sync(0xffffffffu, s, o);
    if (lane == 0) out[gwarp] = s + b[0];
}

// ---------------------------------------------------------------------------
// host side
// ---------------------------------------------------------------------------
static inline void gemm(const float* Ap, const float* Wp, const float* bias, void* C,
                        int M, int N, int Kp, int act, int Npck)
{
    int gL = ((N + 127) / 128) * (M / 128);
    if ((M % 128 == 0) && gL >= 96) {
        dim3 grid((N + 127) / 128, M / 128);
        mma_gemm_pk<128, 2, 4, 2><<<grid, 256, SMEM_L>>>(
            (const uint4*)Ap, (const uint4*)Wp, bias, C, M, N, Kp, act, Npck);
    } else {
        dim3 grid((N + 63) / 64, M / 64);
        mma_gemm_pk<64, 2, 2, 4><<<grid, 128, SMEM_S>>>(
            (const uint4*)Ap, (const uint4*)Wp, bias, C, M, N, Kp, act, Npck);
    }
}

extern "C" void kernel_launch(void* const* d_in, const int* in_sizes, int n_in,
                              void* d_out, int out_size)
{
    cudaFuncSetAttribute((const void*)mma_gemm_pk<128, 2, 4, 2>,
                         cudaFuncAttributeMaxDynamicSharedMemorySize, SMEM_L);
    cudaFuncSetAttribute((const void*)mma_gemm_pk<64, 2, 2, 4>,
                         cudaFuncAttributeMaxDynamicSharedMemorySize, SMEM_S);

    const float* ast    = (const float*)d_in[0];
    const float* ce_w0  = (const float*)d_in[1];  const float* ce_b0 = (const float*)d_in[2];
    const float* ce_w1  = (const float*)d_in[3];  const float* ce_b1 = (const float*)d_in[4];
    const float* ce_w2  = (const float*)d_in[5];  const float* ce_b2 = (const float*)d_in[6];
    const float* ce_w3  = (const float*)d_in[7];  const float* ce_b3 = (const float*)d_in[8];
    const float* cc_w0  = (const float*)d_in[9];  const float* cc_b0 = (const float*)d_in[10];
    const float* cc_w1  = (const float*)d_in[11]; const float* cc_b1 = (const float*)d_in[12];
    const float* rg_w0  = (const float*)d_in[13]; const float* rg_b0 = (const float*)d_in[14];
    const float* rg_w1  = (const float*)d_in[15]; const float* rg_b1 = (const float*)d_in[16];
    const float* pred_w = (const float*)d_in[17]; const float* pred_b = (const float*)d_in[18];
    const float* cl_Wih = (const float*)d_in[19]; const float* cl_Whh = (const float*)d_in[20];
    const float* cl_bih = (const float*)d_in[21]; const float* cl_bhh = (const float*)d_in[22];
    const float* nl_Wih = (const float*)d_in[23]; const float* nl_Whh = (const float*)d_in[24];
    const float* nl_bih = (const float*)d_in[25]; const float* nl_bhh = (const float*)d_in[26];
    const float* no_comps = (const float*)d_in[27];
    const float* no_nodes = (const float*)d_in[28];
    float* out = (float*)d_out;

    float* S0 = nullptr;
    cudaGetSymbolAddress((void**)&S0, g_scratch4);

    float* astP = S0 + OFF_ASTP;
    float* e0P = S0 + OFF_E0P;   float* e1P = S0 + OFF_E1P;
    float* e2P = S0 + OFF_E2P;   float* edP = S0 + OFF_EDP;
    float* xg  = S0 + OFF_XG;    float* hW  = S0 + OFF_HW;
    float* hAP = S0 + OFF_HAP;   float* cA  = S0 + OFF_CA;
    float* catP = S0 + OFF_CATP; float* t2P = S0 + OFF_T2P;
    float* lfP = S0 + OFF_LFP;   float* xgm = S0 + OFF_XGM;
    float* hMP = S0 + OFF_HMP;   float* cM  = S0 + OFF_CM;
    float* mdP = S0 + OFF_MDP;   float* xgr = S0 + OFF_XGR;
    float* hRP = S0 + OFF_HRP;   float* cR  = S0 + OFF_CR;
    float* pgP = S0 + OFF_PGP;   float* r0P = S0 + OFF_R0P;
    float* r1  = S0 + OFF_R1;
    float* w0P = S0 + OFF_W0P;   float* w1P = S0 + OFF_W1P;
    float* w2P = S0 + OFF_W2P;   float* w3P = S0 + OFF_W3P;
    float* cw0P = S0 + OFF_CW0P; float* cw1P = S0 + OFF_CW1P;
    float* rw0P = S0 + OFF_RW0P; float* rw1P = S0 + OFF_RW1P;
    float* clIP = S0 + OFF_CLIP; float* clHP = S0 + OFF_CLHP;
    float* nlIP = S0 + OFF_NLIP; float* nlHP = S0 + OFF_NLHP;
    float* ncP = S0 + OFF_NCP;   float* nnP = S0 + OFF_NNP;

    // ---- pack weights + constants ----
    PackTable pt;
    const float* srcs[NPACK] = { ce_w0, ce_w1, ce_w2, ce_w3, cc_w0, cc_w1, rg_w0, rg_w1,
                                 cl_Wih, cl_Whh, nl_Wih, nl_Whh, no_comps, no_nodes };
    float* dsts[NPACK] = { w0P, w1P, w2P, w3P, cw0P, cw1P, rw0P, rw1P,
                           clIP, clHP, nlIP, nlHP, ncP, nnP };
    int rws[NPACK] = { 600, 350, 200, 180, 200, 180, 200, 180, 720, 720, 720, 720, 1, 1 };
    int ks[NPACK]  = { 1024, 600, 350, 200, 360, 200, 180, 200, 180, 180, 180, 180, 180, 180 };
    int kps[NPACK] = { 1024, 608, 352, 208, 368, 208, 192, 208, 192, 192, 192, 192, 192, 192 };
    for (int i = 0; i < NPACK; i++) {
        pt.src[i] = srcs[i]; pt.dst[i] = dsts[i];
        pt.rows[i] = rws[i]; pt.K[i] = ks[i]; pt.Kp[i] = kps[i];
    }
    {
        long maxn = 600L * 512;
        dim3 g((unsigned)((maxn + 255) / 256), NPACK);
        pack_many_kernel<<<g, 256>>>(pt);
    }
    pack_ast_kernel<<<(int)(((long)M_CE * 512 + 255) / 256), 256>>>(ast, (uint32_t*)astP);

    // ---- Phase A: comp-embedding MLP ----
    gemm(astP, w0P, ce_b0, e0P, M_CE, 600, 1024, 1, 608);
    gemm(e0P,  w1P, ce_b1, e1P, M_CE, 350, 608, 1, 352);
    gemm(e1P,  w2P, ce_b2, e2P, M_CE, 200, 352, 1, 208);
    gemm(e2P,  w3P, ce_b3, edP, M_CE, 180, 208, 1, 192);

    // ---- Phase B: cl LSTM (S=1536, T=8) ----
    gemm(edP, clIP, nullptr, xg, M_CE, G_DIM, 192, 0, 0);
    {
        int thr = S_CL * 96;
        lstm_step_kernel<<<(thr + 255) / 256, 256>>>(xg, hW, cl_bih, cl_bhh,
                                                     (uint32_t*)hAP, cA, S_CL, 0, 6, 48, 8, 1);
        for (int t = 1; t < 8; t++) {
            gemm(hAP, clHP, nullptr, hW, S_CL, G_DIM, 192, 0, 0);
            lstm_step_kernel<<<(thr + 255) / 256, 256>>>(xg, hW, cl_bih, cl_bhh,
                                                         (uint32_t*)hAP, cA, S_CL, t, 6, 48, 8, 0);
        }
    }

    // ---- Phase C: leaf concat block ----
    {
        int thr = S_CL * 184;
        concat_kernel<<<(thr + 255) / 256, 256>>>((uint32_t*)nnP, 1, (uint32_t*)hAP, 0,
                                                  (uint32_t*)catP, S_CL);
        gemm(catP, cw0P, cc_b0, t2P, S_CL, 200, 368, 1, 208);
        gemm(t2P,  cw1P, cc_b1, lfP, S_CL, 180, 208, 1, 192);
    }

    // ---- Phase D: mid nl LSTM (S=768, T=2) ----
    gemm(lfP, nlIP, nullptr, xgm, S_CL, G_DIM, 192, 0, 0);
    {
        int thr = S_MID * 96;
        lstm_step_kernel<<<(thr + 255) / 256, 256>>>(xgm, hW, nl_bih, nl_bhh,
                                                     (uint32_t*)hMP, cM, S_MID, 0, 3, 6, 2, 1);
        gemm(hMP, nlHP, nullptr, hW, S_MID, G_DIM, 192, 0, 0);
        lstm_step_kernel<<<(thr + 255) / 256, 256>>>(xgm, hW, nl_bih, nl_bhh,
                                                     (uint32_t*)hMP, cM, S_MID, 1, 3, 6, 2, 0);
    }

    // ---- Phase E: mid concat block ----
    {
        int thr = S_MID * 184;
        concat_kernel<<<(thr + 255) / 256, 256>>>((uint32_t*)hMP, 0, (uint32_t*)ncP, 1,
                                                  (uint32_t*)catP, S_MID);
        gemm(catP, cw0P, cc_b0, t2P, S_MID, 200, 368, 1, 208);
        gemm(t2P,  cw1P, cc_b1, mdP, S_MID, 180, 208, 1, 192);
    }

    // ---- Phase F: root nl LSTM (S=256, T=3) ----
    gemm(mdP, nlIP, nullptr, xgr, S_MID, G_DIM, 192, 0, 0);
    {
        int thr = S_RT * 96;
        lstm_step_kernel<<<(thr + 255) / 256, 256>>>(xgr, hW, nl_bih, nl_bhh,
                                                     (uint32_t*)hRP, cR, S_RT, 0, 1, 3, 0, 1);
        for (int t = 1; t < 3; t++) {
            gemm(hRP, nlHP, nullptr, hW, S_RT, G_DIM, 192, 0, 0);
            lstm_step_kernel<<<(thr + 255) / 256, 256>>>(xgr, hW, nl_bih, nl_bhh,
                                                         (uint32_t*)hRP, cR, S_RT, t, 1, 3, 0, 0);
        }
    }

    // ---- Phase G: root concat block ----
    {
        int thr = S_RT * 184;
        concat_kernel<<<(thr + 255) / 256, 256>>>((uint32_t*)hRP, 0, (uint32_t*)ncP, 1,
                                                  (uint32_t*)catP, S_RT);
        gemm(catP, cw0P, cc_b0, t2P, S_RT, 200, 368, 1, 208);
        gemm(t2P,  cw1P, cc_b1, pgP, S_RT, 180, 208, 1, 192);
    }

    // ---- Phase H: regression head ----
    gemm(pgP, rw0P, rg_b0, r0P, S_RT, 200, 192, 1, 208);
    gemm(r0P, rw1P, rg_b1, r1, S_RT, 180, 208, 1, 0);
    pred_kernel<<<(S_RT * 32 + 255) / 256, 256>>>(r1, pred_w, pred_b, out, S_RT);
}

// round 11
// speedup vs baseline: 4.5079x; 1.0496x over previous
#include <cuda_runtime.h>
#include <math.h>
#include <stdint.h>

// ---------------------------------------------------------------------------
// Model_Recursive_LSTM_v2 — 3xBF16 GEMM, pre-packed (hi,lo) operands,
// cp.async 4-stage pipeline with constant-folded unrolled mainloop.
// B=256, L=64 (only 0..47 used), IN=1024, E=180.
//
// Packed layout (word = uint32): per row of padded width Kp (mult of 16),
// pair index kp=k/2, slab=kp>>3, q=kp&7:
//   word_off = slab*16 + (q&3)*4 + (q>>2)*2 ; word[off]=hi bf16x2, [off+1]=lo
// ---------------------------------------------------------------------------

#define E_DIM 180
#define G_DIM 720
#define M_CE  12288
#define S_CL  1536
#define S_MID 768
#define S_RT  256

// ---- scratch offsets (float words, all multiples of 4) ----
#define OFF_ASTP  0UL
#define OFF_E0P   12582912UL
#define OFF_E1P   20054016UL
#define OFF_E2P   24379392UL
#define OFF_EDP   26935296UL
#define OFF_XG    29294592UL
#define OFF_HW    38141952UL
#define OFF_HAP   39247872UL
#define OFF_CA    39542784UL
#define OFF_CATP  39819264UL
#define OFF_T2P   40384512UL
#define OFF_LFP   40704000UL
#define OFF_XGM   40998912UL
#define OFF_HMP   42104832UL
#define OFF_CM    42252288UL
#define OFF_MDP   42390528UL
#define OFF_XGR   42537984UL
#define OFF_HRP   43090944UL
#define OFF_CR    43140096UL
#define OFF_PGP   43186176UL
#define OFF_R0P   43235328UL
#define OFF_R1    43288576UL
#define OFF_W0P   43334656UL
#define OFF_W1P   43949056UL
#define OFF_W2P   44161856UL
#define OFF_W3P   44232256UL
#define OFF_CW0P  44269696UL
#define OFF_CW1P  44343296UL
#define OFF_RW0P  44380736UL
#define OFF_RW1P  44419136UL
#define OFF_CLIP  44456576UL
#define OFF_CLHP  44594816UL
#define OFF_NLIP  44733056UL
#define OFF_NLHP  44871296UL
#define OFF_NCP   45009536UL
#define OFF_NNP   45009728UL
#define SCRATCH_F 45009920UL

__device__ float4 g_scratch4[SCRATCH_F / 4];

// hi/lo bf16 split of two consecutive values -> {hi_pair, lo_pair}
__device__ __forceinline__ uint2 bfsplit2(float v0, float v1) {
    uint32_t hp;
    asm("cvt.rn.bf16x2.f32 %0, %1, %2;" : "=r"(hp) : "f"(v1), "f"(v0));
    float h0 = __uint_as_float(hp << 16);
    float h1 = __uint_as_float(hp & 0xffff0000u);
    uint32_t lp;
    asm("cvt.rn.bf16x2.f32 %0, %1, %2;" : "=r"(lp) : "f"(v1 - h1), "f"(v0 - h0));
    return make_uint2(hp, lp);
}

// packed word index for even k within a row of padded width Kp
__device__ __forceinline__ long widx(long row, int k, int Kp) {
    int kp = k >> 1;
    int q = kp & 7;
    return row * Kp + (long)((kp >> 3) * 16 + (q & 3) * 4 + (q >> 2) * 2);
}

__device__ __forceinline__ void mma_bf16(float* d, const uint32_t* a, const uint32_t* b) {
    asm volatile(
        "mma.sync.aligned.m16n8k16.row.col.f32.bf16.bf16.f32 "
        "{%0,%1,%2,%3}, {%4,%5,%6,%7}, {%8,%9}, {%0,%1,%2,%3};"
        : "+f"(d[0]), "+f"(d[1]), "+f"(d[2]), "+f"(d[3])
        : "r"(a[0]), "r"(a[1]), "r"(a[2]), "r"(a[3]),
          "r"(b[0]), "r"(b[1]));
}

__device__ __forceinline__ uint32_t smem_u32(const void* p) {
    uint32_t a;
    asm("{ .reg .u64 t; cvta.to.shared.u64 t, %1; cvt.u32.u64 %0, t; }"
        : "=r"(a) : "l"(p));
    return a;
}

__device__ __forceinline__ void cpa16(uint32_t dst, const void* src, uint32_t bytes) {
    asm volatile("cp.async.cg.shared.global [%0], [%1], 16, %2;"
                 :: "r"(dst), "l"(src), "r"(bytes) : "memory");
}
#define CP_COMMIT() asm volatile("cp.async.commit_group;" ::: "memory")
#define CP_WAIT(n)  asm volatile("cp.async.wait_group %0;" :: "n"(n) : "memory")

extern __shared__ uint32_t dynsmem[];

// ---------------------------------------------------------------------------
// Packed 3xBF16 GEMM: C = act( A @ W^T + bias ). A,W packed. 4-stage cp.async,
// mainloop unrolled x4 with compile-time stage offsets + incremental pointers.
// Npck>0: write packed C (width Npck, zero-padded); Npck==0: write fp32 C.
// M multiple of BMT at every call site.
// ---------------------------------------------------------------------------
template <int BMT, int WMT, int WNT, int MINB>
__global__ __launch_bounds__(2 * BMT, MINB) void mma_gemm_pk(
    const uint4* __restrict__ Ap, const uint4* __restrict__ Wp,
    const float* __restrict__ bias, void* __restrict__ Cout,
    int M, int N, int Kp, int act, int Npck)
{
    constexpr int MT = BMT / (WMT * 16);
    constexpr int NT = BMT / (WNT * 8);
    constexpr int RS = 4;                   // uint4 per row per slab
    constexpr int ARR_U4 = BMT * RS;
    constexpr int STAGE_U4 = 2 * ARR_U4;
    constexpr int STAGE_B = STAGE_U4 * 16;
    constexpr int STAGES = 4;

    uint4* smem4 = reinterpret_cast<uint4*>(dynsmem);
    const uint32_t sbase = smem_u32(dynsmem);

    const int tid  = threadIdx.x;
    const int warp = tid >> 5;
    const int lane = tid & 31;
    const int wm = warp % WMT;
    const int wn = warp / WMT;
    const int bm = blockIdx.y * BMT;
    const int bn = blockIdx.x * BMT;
    const int grp = lane >> 2;
    const int tig = lane & 3;

    float acc[MT][NT][4];
#pragma unroll
    for (int i = 0; i < MT; i++)
#pragma unroll
        for (int j = 0; j < NT; j++)
#pragma unroll
            for (int r = 0; r < 4; r++) acc[i][j][r] = 0.f;

    // copy assignment: thread -> (row, half); 2 uint4 of A + 2 of B per slab
    const int arow = tid >> 1;
    const int half = tid & 1;
    const long rowU4 = (long)(Kp >> 2);
    const long aBase = (long)(bm + arow) * rowU4 + half * 2;
    const int brow = bn + arow;
    const bool bval = brow < N;
    const long bBase = (long)(bval ? brow : 0) * rowU4 + half * 2;
    const uint32_t bbytes = bval ? 16u : 0u;
    const uint32_t aDst0 = sbase + (uint32_t)(arow * RS + half * 2) * 16u;
    const uint32_t bDst0 = aDst0 + (uint32_t)ARR_U4 * 16u;

    const int nSlab = Kp >> 4;

    // ---- prologue: issue slabs 0..2 ----
    {
        const uint4* as = Ap + aBase;
        const uint4* bs = Wp + bBase;
#pragma unroll
        for (int s = 0; s < STAGES - 1; s++) {
            if (s < nSlab) {
                uint32_t so = (uint32_t)(s * STAGE_B);
                cpa16(aDst0 + so,       as,     16u);
                cpa16(aDst0 + so + 16u, as + 1, 16u);
                cpa16(bDst0 + so,       bs,     bbytes);
                cpa16(bDst0 + so + 16u, bs + 1, bbytes);
            }
            CP_COMMIT();
            as += 4; bs += 4;
        }
    }

    // ---- hoisted fragment smem byte offsets (relative to stage base) ----
    uint32_t offA[MT][2], offB[NT];
#pragma unroll
    for (int mt = 0; mt < MT; mt++) {
        int mr = wm * MT * 16 + mt * 16 + grp;
        offA[mt][0] = (uint32_t)((mr * RS + tig) * 16);
        offA[mt][1] = (uint32_t)(((mr + 8) * RS + tig) * 16);
    }
#pragma unroll
    for (int nt = 0; nt < NT; nt++) {
        int nc = wn * NT * 8 + nt * 8 + grp;
        offB[nt] = (uint32_t)((ARR_U4 + nc * RS + tig) * 16);
    }
    const char* sbytes = (const char*)smem4;

    // incremental global pointers for slab s+3
    const uint4* aNxt = Ap + aBase + 3 * 4;
    const uint4* bNxt = Wp + bBase + 3 * 4;

    auto gstep = [&](int slabi, int stage) {
        CP_WAIT(2);
        __syncthreads();
        if (slabi + 3 < nSlab) {
            uint32_t so = (uint32_t)(((slabi + 3) & 3) * STAGE_B);
            cpa16(aDst0 + so,       aNxt,     16u);
            cpa16(aDst0 + so + 16u, aNxt + 1, 16u);
            cpa16(bDst0 + so,       bNxt,     bbytes);
            cpa16(bDst0 + so + 16u, bNxt + 1, bbytes);
        }
        CP_COMMIT();
        aNxt += 4; bNxt += 4;

        const char* sb = sbytes + stage * STAGE_B;
        uint32_t ah[MT][4], al[MT][4];
        uint32_t bh[NT][2], bl[NT][2];
#pragma unroll
        for (int mt = 0; mt < MT; mt++) {
            uint4 p0 = *(const uint4*)(sb + offA[mt][0]);
            uint4 p1 = *(const uint4*)(sb + offA[mt][1]);
            ah[mt][0] = p0.x; ah[mt][1] = p1.x; ah[mt][2] = p0.z; ah[mt][3] = p1.z;
            al[mt][0] = p0.y; al[mt][1] = p1.y; al[mt][2] = p0.w; al[mt][3] = p1.w;
        }
#pragma unroll
        for (int nt = 0; nt < NT; nt++) {
            uint4 q = *(const uint4*)(sb + offB[nt]);
            bh[nt][0] = q.x; bh[nt][1] = q.z;
            bl[nt][0] = q.y; bl[nt][1] = q.w;
        }
#pragma unroll
        for (int mt = 0; mt < MT; mt++)
#pragma unroll
            for (int nt = 0; nt < NT; nt++) {
                mma_bf16(acc[mt][nt], ah[mt], bl[nt]);   // hi*lo
                mma_bf16(acc[mt][nt], al[mt], bh[nt]);   // lo*hi
                mma_bf16(acc[mt][nt], ah[mt], bh[nt]);   // hi*hi
            }
    };

    int slab = 0;
    const int fullN = nSlab & ~(STAGES - 1);
    for (; slab < fullN; slab += STAGES) {
        gstep(slab + 0, 0);
        gstep(slab + 1, 1);
        gstep(slab + 2, 2);
        gstep(slab + 3, 3);
    }
    for (; slab < nSlab; slab++) gstep(slab, slab & 3);

    // ---- epilogue ----
    if (Npck > 0) {
        uint32_t* Cw = (uint32_t*)Cout;
#pragma unroll
        for (int mt = 0; mt < MT; mt++) {
            int r0 = bm + wm * MT * 16 + mt * 16 + grp;
#pragma unroll
            for (int nt = 0; nt < NT; nt++) {
                int cc = bn + wn * NT * 8 + nt * 8 + tig * 2;
                if (cc >= Npck) continue;
#pragma unroll
                for (int hh = 0; hh < 2; hh++) {
                    int rr = r0 + hh * 8;
                    float v0 = 0.f, v1 = 0.f;
                    if (cc < N) {
                        v0 = acc[mt][nt][hh * 2];
                        if (bias) v0 += bias[cc];
                        if (act) v0 = v0 > 0.f ? v0 : (expf(v0) - 1.f);
                    }
                    if (cc + 1 < N) {
                        v1 = acc[mt][nt][hh * 2 + 1];
                        if (bias) v1 += bias[cc + 1];
                        if (act) v1 = v1 > 0.f ? v1 : (expf(v1) - 1.f);
                    }
                    uint2 p = bfsplit2(v0, v1);
                    *(uint2*)(Cw + widx((long)rr, cc, Npck)) = p;
                }
            }
        }
    } else {
        float* Cf = (float*)Cout;
#pragma unroll
        for (int mt = 0; mt < MT; mt++) {
            int r0 = bm + wm * MT * 16 + mt * 16 + grp;
#pragma unroll
            for (int nt = 0; nt < NT; nt++) {
                int cc = bn + wn * NT * 8 + nt * 8 + tig * 2;
#pragma unroll
                for (int hh = 0; hh < 2; hh++) {
                    int rr = r0 + hh * 8;
#pragma unroll
                    for (int q = 0; q < 2; q++) {
                        int gn = cc + q;
                        if (gn >= N) continue;
                        float v = acc[mt][nt][hh * 2 + q];
                        if (bias) v += bias[gn];
                        if (act) v = v > 0.f ? v : (expf(v) - 1.f);
                        Cf[(long)rr * N + gn] = v;
                    }
                }
            }
        }
    }
}

// smem: STAGES * 2 arrays * BMT rows * 4 uint4 * 16B
#define SMEM_L (4 * 2 * 128 * 4 * 16)   // 65536
#define SMEM_S (4 * 2 * 64 * 4 * 16)    // 32768

// ---------------------------------------------------------------------------
// Pack kernels: fp32 -> packed bf16 (hi,lo) layout
// ---------------------------------------------------------------------------
#define NPACK 14
struct PackTable {
    const float* src[NPACK];
    float* dst[NPACK];
    int rows[NPACK];
    int K[NPACK];
    int Kp[NPACK];
};

__global__ void pack_many_kernel(PackTable pt) {
    int which = blockIdx.y;
    int rows = pt.rows[which], K = pt.K[which], Kp = pt.Kp[which];
    int pairs = Kp >> 1;
    long n = (long)rows * pairs;
    long idx = (long)blockIdx.x * blockDim.x + threadIdx.x;
    if (idx >= n) return;
    int r = (int)(idx / pairs);
    int k = (int)(idx % pairs) * 2;
    const float* s = pt.src[which] + (long)r * K;
    float v0 = (k < K) ? s[k] : 0.f;
    float v1 = (k + 1 < K) ? s[k + 1] : 0.f;
    uint2 p = bfsplit2(v0, v1);
    *(uint2*)((uint32_t*)pt.dst[which] + widx((long)r, k, Kp)) = p;
}

// ast pack with 48-of-64 row gather; K=Kp=1024
__global__ void pack_ast_kernel(const float* __restrict__ src, uint32_t* __restrict__ dst) {
    long idx = (long)blockIdx.x * blockDim.x + threadIdx.x;
    if (idx >= (long)M_CE * 512) return;
    int m = (int)(idx / 512);
    int k = (int)(idx % 512) * 2;
    long phys = (long)(m / 48) * 64 + (m % 48);
    const float* s = src + phys * 1024 + k;
    uint2 p = bfsplit2(s[0], s[1]);
    *(uint2*)(dst + widx((long)m, k, 1024)) = p;
}

// ---------------------------------------------------------------------------
// LSTM pointwise step (gate order i,f,g,o); writes h packed (width 192)
// ---------------------------------------------------------------------------
__device__ __forceinline__ float sigf(float x) { return 1.f / (1.f + expf(-x)); }

__device__ __forceinline__ float lstm_gate(
    const float* xr, const float* hr, const float* bih, const float* bhh,
    float* cslot, int e, int hashW)
{
    float gi = xr[e]             + bih[e]             + bhh[e];
    float gf = xr[E_DIM + e]     + bih[E_DIM + e]     + bhh[E_DIM + e];
    float gg = xr[2 * E_DIM + e] + bih[2 * E_DIM + e] + bhh[2 * E_DIM + e];
    float go = xr[3 * E_DIM + e] + bih[3 * E_DIM + e] + bhh[3 * E_DIM + e];
    float cprev = 0.f;
    if (hashW) {
        gi += hr[e]; gf += hr[E_DIM + e]; gg += hr[2 * E_DIM + e]; go += hr[3 * E_DIM + e];
        cprev = *cslot;
    }
    float cn = sigf(gf) * cprev + sigf(gi) * tanhf(gg);
    *cslot = cn;
    return sigf(go) * tanhf(cn);
}

__global__ void lstm_step_kernel(
    const float* __restrict__ xg, const float* __restrict__ hW,
    const float* __restrict__ bih, const float* __restrict__ bhh,
    uint32_t* __restrict__ hP, float* __restrict__ c,
    int S, int t, int divA, int mulA, int mulB, int first)
{
    int idx = blockIdx.x * blockDim.x + threadIdx.x;
    if (idx >= S * 96) return;                   // 96 pairs per row (width 192)
    int s = idx / 96, pe = idx % 96;
    int e = pe * 2;
    uint2 p = make_uint2(0, 0);
    if (e < E_DIM) {
        int xrow = (s / divA) * mulA + (s % divA) * mulB + t;
        const float* xr = xg + (long)xrow * G_DIM;
        const float* hr = hW + (long)s * G_DIM;
        float v0 = lstm_gate(xr, hr, bih, bhh, c + (long)s * E_DIM + e, e, !first);
        float v1 = lstm_gate(xr, hr, bih, bhh, c + (long)s * E_DIM + e + 1, e + 1, !first);
        p = bfsplit2(v0, v1);
    }
    *(uint2*)(hP + widx((long)s, e, 192)) = p;
}

// ---------------------------------------------------------------------------
// Concat packed: width 368; regions [0,180) first, [180,360) second, rest 0.
// ---------------------------------------------------------------------------
__global__ void concat_kernel(
    const uint32_t* __restrict__ first, int firstB,
    const uint32_t* __restrict__ second, int secondB,
    uint32_t* __restrict__ cat, int rows)
{
    int idx = blockIdx.x * blockDim.x + threadIdx.x;
    if (idx >= rows * 184) return;               // 184 pairs per row
    int r = idx / 184, pj = idx % 184;
    int j = pj * 2;
    uint2 v = make_uint2(0, 0);
    if (j < E_DIM) {
        long sr = firstB ? 0 : (long)r;
        v = *(const uint2*)(first + widx(sr, j, 192));
    } else if (j < 2 * E_DIM) {
        long sr = secondB ? 0 : (long)r;
        v = *(const uint2*)(second + widx(sr, j - E_DIM, 192));
    }
    *(uint2*)(cat + widx((long)r, j, 368)) = v;
}

// ---------------------------------------------------------------------------
__global__ void pred_kernel(const float* __restrict__ x, const float* __restrict__ w,
                            const float* __restrict__ b, float* __restrict__ out, int rows)
{
    int gwarp = (blockIdx.x * blockDim.x + threadIdx.x) >> 5;
    int lane = threadIdx.x & 31;
    if (gwarp >= rows) return;
    float s = 0.f;
    for (int e = lane; e < E_DIM; e += 32) s += x[(long)gwarp * E_DIM + e] * w[e];
#pragma unroll
    for (int o = 16; o; o >>= 1) s += __shfl_down_sync(0xffffffffu, s, o);
    if (lane == 0) out[gwarp] = s + b[0];
}

// ---------------------------------------------------------------------------
// host side
// ---------------------------------------------------------------------------
static inline void gemm(const float* Ap, const float* Wp, const float* bias, void* C,
                        int M, int N, int Kp, int act, int Npck)
{
    int gL = ((N + 127) / 128) * (M / 128);
    if ((M % 128 == 0) && gL >= 96) {
        dim3 grid((N + 127) / 128, M / 128);
        mma_gemm_pk<128, 2, 4, 2><<<grid, 256, SMEM_L>>>(
            (const uint4*)Ap, (const uint4*)Wp, bias, C, M, N, Kp, act, Npck);
    } else {
        dim3 grid((N + 63) / 64, M / 64);
        mma_gemm_pk<64, 2, 2, 4><<<grid, 128, SMEM_S>>>(
            (const uint4*)Ap, (const uint4*)Wp, bias, C, M, N, Kp, act, Npck);
    }
}

extern "C" void kernel_launch(void* const* d_in, const int* in_sizes, int n_in,
                              void* d_out, int out_size)
{
    cudaFuncSetAttribute((const void*)mma_gemm_pk<128, 2, 4, 2>,
                         cudaFuncAttributeMaxDynamicSharedMemorySize, SMEM_L);
    cudaFuncSetAttribute((const void*)mma_gemm_pk<64, 2, 2, 4>,
                         cudaFuncAttributeMaxDynamicSharedMemorySize, SMEM_S);

    const float* ast    = (const float*)d_in[0];
    const float* ce_w0  = (const float*)d_in[1];  const float* ce_b0 = (const float*)d_in[2];
    const float* ce_w1  = (const float*)d_in[3];  const float* ce_b1 = (const float*)d_in[4];
    const float* ce_w2  = (const float*)d_in[5];  const float* ce_b2 = (const float*)d_in[6];
    const float* ce_w3  = (const float*)d_in[7];  const float* ce_b3 = (const float*)d_in[8];
    const float* cc_w0  = (const float*)d_in[9];  const float* cc_b0 = (const float*)d_in[10];
    const float* cc_w1  = (const float*)d_in[11]; const float* cc_b1 = (const float*)d_in[12];
    const float* rg_w0  = (const float*)d_in[13]; const float* rg_b0 = (const float*)d_in[14];
    const float* rg_w1  = (const float*)d_in[15]; const float* rg_b1 = (const float*)d_in[16];
    const float* pred_w = (const float*)d_in[17]; const float* pred_b = (const float*)d_in[18];
    const float* cl_Wih = (const float*)d_in[19]; const float* cl_Whh = (const float*)d_in[20];
    const float* cl_bih = (const float*)d_in[21]; const float* cl_bhh = (const float*)d_in[22];
    const float* nl_Wih = (const float*)d_in[23]; const float* nl_Whh = (const float*)d_in[24];
    const float* nl_bih = (const float*)d_in[25]; const float* nl_bhh = (const float*)d_in[26];
    const float* no_comps = (const float*)d_in[27];
    const float* no_nodes = (const float*)d_in[28];
    float* out = (float*)d_out;

    float* S0 = nullptr;
    cudaGetSymbolAddress((void**)&S0, g_scratch4);

    float* astP = S0 + OFF_ASTP;
    float* e0P = S0 + OFF_E0P;   float* e1P = S0 + OFF_E1P;
    float* e2P = S0 + OFF_E2P;   float* edP = S0 + OFF_EDP;
    float* xg  = S0 + OFF_XG;    float* hW  = S0 + OFF_HW;
    float* hAP = S0 + OFF_HAP;   float* cA  = S0 + OFF_CA;
    float* catP = S0 + OFF_CATP; float* t2P = S0 + OFF_T2P;
    float* lfP = S0 + OFF_LFP;   float* xgm = S0 + OFF_XGM;
    float* hMP = S0 + OFF_HMP;   float* cM  = S0 + OFF_CM;
    float* mdP = S0 + OFF_MDP;   float* xgr = S0 + OFF_XGR;
    float* hRP = S0 + OFF_HRP;   float* cR  = S0 + OFF_CR;
    float* pgP = S0 + OFF_PGP;   float* r0P = S0 + OFF_R0P;
    float* r1  = S0 + OFF_R1;
    float* w0P = S0 + OFF_W0P;   float* w1P = S0 + OFF_W1P;
    float* w2P = S0 + OFF_W2P;   float* w3P = S0 + OFF_W3P;
    float* cw0P = S0 + OFF_CW0P; float* cw1P = S0 + OFF_CW1P;
    float* rw0P = S0 + OFF_RW0P; float* rw1P = S0 + OFF_RW1P;
    float* clIP = S0 + OFF_CLIP; float* clHP = S0 + OFF_CLHP;
    float* nlIP = S0 + OFF_NLIP; float* nlHP = S0 + OFF_NLHP;
    float* ncP = S0 + OFF_NCP;   float* nnP = S0 + OFF_NNP;

    // ---- pack weights + constants ----
    PackTable pt;
    const float* srcs[NPACK] = { ce_w0, ce_w1, ce_w2, ce_w3, cc_w0, cc_w1, rg_w0, rg_w1,
                                 cl_Wih, cl_Whh, nl_Wih, nl_Whh, no_comps, no_nodes };
    float* dsts[NPACK] = { w0P, w1P, w2P, w3P, cw0P, cw1P, rw0P, rw1P,
                           clIP, clHP, nlIP, nlHP, ncP, nnP };
    int rws[NPACK] = { 600, 350, 200, 180, 200, 180, 200, 180, 720, 720, 720, 720, 1, 1 };
    int ks[NPACK]  = { 1024, 600, 350, 200, 360, 200, 180, 200, 180, 180, 180, 180, 180, 180 };
    int kps[NPACK] = { 1024, 608, 352, 208, 368, 208, 192, 208, 192, 192, 192, 192, 192, 192 };
    for (int i = 0; i < NPACK; i++) {
        pt.src[i] = srcs[i]; pt.dst[i] = dsts[i];
        pt.rows[i] = rws[i]; pt.K[i] = ks[i]; pt.Kp[i] = kps[i];
    }
    {
        long maxn = 600L * 512;
        dim3 g((unsigned)((maxn + 255) / 256), NPACK);
        pack_many_kernel<<<g, 256>>>(pt);
    }
    pack_ast_kernel<<<(int)(((long)M_CE * 512 + 255) / 256), 256>>>(ast, (uint32_t*)astP);

    // ---- Phase A: comp-embedding MLP ----
    gemm(astP, w0P, ce_b0, e0P, M_CE, 600, 1024, 1, 608);
    gemm(e0P,  w1P, ce_b1, e1P, M_CE, 350, 608, 1, 352);
    gemm(e1P,  w2P, ce_b2, e2P, M_CE, 200, 352, 1, 208);
    gemm(e2P,  w3P, ce_b3, edP, M_CE, 180, 208, 1, 192);

    // ---- Phase B: cl LSTM (S=1536, T=8) ----
    gemm(edP, clIP, nullptr, xg, M_CE, G_DIM, 192, 0, 0);
    {
        int thr = S_CL * 96;
        lstm_step_kernel<<<(thr + 255) / 256, 256>>>(xg, hW, cl_bih, cl_bhh,
                                                     (uint32_t*)hAP, cA, S_CL, 0, 6, 48, 8, 1);
        for (int t = 1; t < 8; t++) {
            gemm(hAP, clHP, nullptr, hW, S_CL, G_DIM, 192, 0, 0);
            lstm_step_kernel<<<(thr + 255) / 256, 256>>>(xg, hW, cl_bih, cl_bhh,
                                                         (uint32_t*)hAP, cA, S_CL, t, 6, 48, 8, 0);
        }
    }

    // ---- Phase C: leaf concat block ----
    {
        int thr = S_CL * 184;
        concat_kernel<<<(thr + 255) / 256, 256>>>((uint32_t*)nnP, 1, (uint32_t*)hAP, 0,
                                                  (uint32_t*)catP, S_CL);
        gemm(catP, cw0P, cc_b0, t2P, S_CL, 200, 368, 1, 208);
        gemm(t2P,  cw1P, cc_b1, lfP, S_CL, 180, 208, 1, 192);
    }

    // ---- Phase D: mid nl LSTM (S=768, T=2) ----
    gemm(lfP, nlIP, nullptr, xgm, S_CL, G_DIM, 192, 0, 0);
    {
        int thr = S_MID * 96;
        lstm_step_kernel<<<(thr + 255) / 256, 256>>>(xgm, hW, nl_bih, nl_bhh,
                                                     (uint32_t*)hMP, cM, S_MID, 0, 3, 6, 2, 1);
        gemm(hMP, nlHP, nullptr, hW, S_MID, G_DIM, 192, 0, 0);
        lstm_step_kernel<<<(thr + 255) / 256, 256>>>(xgm, hW, nl_bih, nl_bhh,
                                                     (uint32_t*)hMP, cM, S_MID, 1, 3, 6, 2, 0);
    }

    // ---- Phase E: mid concat block ----
    {
        int thr = S_MID * 184;
        concat_kernel<<<(thr + 255) / 256, 256>>>((uint32_t*)hMP, 0, (uint32_t*)ncP, 1,
                                                  (uint32_t*)catP, S_MID);
        gemm(catP, cw0P, cc_b0, t2P, S_MID, 200, 368, 1, 208);
        gemm(t2P,  cw1P, cc_b1, mdP, S_MID, 180, 208, 1, 192);
    }

    // ---- Phase F: root nl LSTM (S=256, T=3) ----
    gemm(mdP, nlIP, nullptr, xgr, S_MID, G_DIM, 192, 0, 0);
    {
        int thr = S_RT * 96;
        lstm_step_kernel<<<(thr + 255) / 256, 256>>>(xgr, hW, nl_bih, nl_bhh,
                                                     (uint32_t*)hRP, cR, S_RT, 0, 1, 3, 0, 1);
        for (int t = 1; t < 3; t++) {
            gemm(hRP, nlHP, nullptr, hW, S_RT, G_DIM, 192, 0, 0);
            lstm_step_kernel<<<(thr + 255) / 256, 256>>>(xgr, hW, nl_bih, nl_bhh,
                                                         (uint32_t*)hRP, cR, S_RT, t, 1, 3, 0, 0);
        }
    }

    // ---- Phase G: root concat block ----
    {
        int thr = S_RT * 184;
        concat_kernel<<<(thr + 255) / 256, 256>>>((uint32_t*)hRP, 0, (uint32_t*)ncP, 1,
                                                  (uint32_t*)catP, S_RT);
        gemm(catP, cw0P, cc_b0, t2P, S_RT, 200, 368, 1, 208);
        gemm(t2P,  cw1P, cc_b1, pgP, S_RT, 180, 208, 1, 192);
    }

    // ---- Phase H: regression head ----
    gemm(pgP, rw0P, rg_b0, r0P, S_RT, 200, 192, 1, 208);
    gemm(r0P, rw1P, rg_b1, r1, S_RT, 180, 208, 1, 0);
    pred_kernel<<<(S_RT * 32 + 255) / 256, 256>>>(r1, pred_w, pred_b, out, S_RT);
}